// round 3
// baseline (speedup 1.0000x reference)
#include <cuda_runtime.h>
#include <cstdint>

#define N_NODES  1000000
#define N_EDGES  4000000
#define N_GRAPHS 32768
#define HID      128
#define BN_EPS   1e-5f

// ---------------- scratch (device globals: no allocations allowed) ----------------
__device__ float g_dinv[N_NODES];          // degree, then rsqrt(deg)
__device__ float g_xpad[N_NODES * 8];      // x padded to 8 cols
__device__ float g_agg0[N_NODES * 8];      // A @ x   (7 used cols)
__device__ float g_h1 [N_NODES * HID];     // h1 (activated), later reused as out3
__device__ float g_hw [N_NODES * HID];     // hW scratch (gather source)
__device__ float g_out[N_NODES * HID];     // aggregation buffer layer 2
__device__ float g_pool[N_GRAPHS * HID];   // pooled sums
__device__ float g_cnt [N_GRAPHS];         // nodes per graph
__device__ float g_s[3 * HID];             // folded BN scale  per layer
__device__ float g_t[3 * HID];             // folded BN shift (includes bias) per layer

// ---------------- helpers ----------------
__device__ __forceinline__ void red_add_v4(float* addr, float x, float y, float z, float w) {
    asm volatile("red.global.add.v4.f32 [%0], {%1,%2,%3,%4};"
                 :: "l"(addr), "f"(x), "f"(y), "f"(z), "f"(w) : "memory");
}

// ---------------- kernels ----------------
__global__ void k_zero() {
    int i = blockIdx.x * blockDim.x + threadIdx.x;         // grid covers N_GRAPHS*HID
    g_pool[i] = 0.0f;
    if (i < N_NODES)  g_dinv[i] = 0.0f;
    if (i < N_GRAPHS) g_cnt[i]  = 0.0f;
}

__global__ void k_bnprep(const float* __restrict__ b1, const float* __restrict__ ga1,
                         const float* __restrict__ be1, const float* __restrict__ rm1,
                         const float* __restrict__ rv1,
                         const float* __restrict__ b2, const float* __restrict__ ga2,
                         const float* __restrict__ be2, const float* __restrict__ rm2,
                         const float* __restrict__ rv2,
                         const float* __restrict__ b3, const float* __restrict__ ga3,
                         const float* __restrict__ be3, const float* __restrict__ rm3,
                         const float* __restrict__ rv3) {
    int j = threadIdx.x;
    if (j >= HID) return;
    const float* B[3]  = {b1, b2, b3};
    const float* G[3]  = {ga1, ga2, ga3};
    const float* BE[3] = {be1, be2, be3};
    const float* RM[3] = {rm1, rm2, rm3};
    const float* RV[3] = {rv1, rv2, rv3};
    for (int l = 0; l < 3; l++) {
        float s = G[l][j] * rsqrtf(RV[l][j] + BN_EPS);
        g_s[l * HID + j] = s;
        g_t[l * HID + j] = (B[l][j] - RM[l][j]) * s + BE[l][j];
    }
}

// degree count (edges by dst; self-loop added in node_prep)
__global__ void k_deg(const int* __restrict__ ei) {
    int e = blockIdx.x * blockDim.x + threadIdx.x;
    if (e >= N_EDGES) return;
    atomicAdd(&g_dinv[ei[N_EDGES + e]], 1.0f);
}

// dinv = rsqrt(deg+1); pad x; init agg0 with self-loop term; per-graph counts
__global__ void k_node_prep(const float* __restrict__ x, const int* __restrict__ batch) {
    int i = blockIdx.x * blockDim.x + threadIdx.x;
    if (i >= N_NODES) return;
    float d  = g_dinv[i] + 1.0f;           // + self-loop
    float di = rsqrtf(d);
    g_dinv[i] = di;
    float di2 = di * di;
    const float* xr = x + (long long)i * 7;
    float xv[8];
#pragma unroll
    for (int j = 0; j < 7; j++) xv[j] = xr[j];
    xv[7] = 0.0f;
    float4* xp = (float4*)(g_xpad + i * 8);
    float4* ag = (float4*)(g_agg0 + i * 8);
    xp[0] = make_float4(xv[0], xv[1], xv[2], xv[3]);
    xp[1] = make_float4(xv[4], xv[5], xv[6], xv[7]);
    ag[0] = make_float4(di2 * xv[0], di2 * xv[1], di2 * xv[2], di2 * xv[3]);
    ag[1] = make_float4(di2 * xv[4], di2 * xv[5], di2 * xv[6], di2 * xv[7]);
    atomicAdd(&g_cnt[batch[i]], 1.0f);
}

// layer-1 edge scatter on 8-wide x: agg0[dst] += norm * xpad[src]
__global__ void k_scatter8(const int* __restrict__ ei) {
    int e = blockIdx.x * blockDim.x + threadIdx.x;
    if (e >= N_EDGES) return;
    int s = ei[e], d = ei[N_EDGES + e];
    float nrm = g_dinv[s] * g_dinv[d];
    const float4* sp = (const float4*)(g_xpad + s * 8);
    float4 a = sp[0], b = sp[1];
    red_add_v4(g_agg0 + d * 8,     nrm * a.x, nrm * a.y, nrm * a.z, nrm * a.w);
    red_add_v4(g_agg0 + d * 8 + 4, nrm * b.x, nrm * b.y, nrm * b.z, nrm * b.w);
}

// h1 = relu( (agg0 @ W1) * s1 + t1 )   (agg0 is [N,8], 7 real cols)
__global__ void k_gemm1(const float* __restrict__ W1) {
    __shared__ float Wsm[7 * 128];
    __shared__ float rsm[32 * 8];
    int j = threadIdx.x;                       // 128 threads: output column
#pragma unroll
    for (int k = 0; k < 7; k++) Wsm[k * 128 + j] = W1[k * 128 + j];
    float sj = g_s[j], tj = g_t[j];
    int base = blockIdx.x * 32;
    rsm[j]       = g_agg0[base * 8 + j];
    rsm[j + 128] = g_agg0[base * 8 + j + 128];
    __syncthreads();
#pragma unroll 4
    for (int n = 0; n < 32; n++) {
        float acc = 0.0f;
#pragma unroll
        for (int k = 0; k < 7; k++) acc += rsm[n * 8 + k] * Wsm[k * 128 + j];
        g_h1[(long long)(base + n) * HID + j] = fmaxf(acc * sj + tj, 0.0f);
    }
}

// hW = act(In) @ W ; out1 = hW ; out2 = dinv^2 * hW  (self-loop init for aggregation)
// ACT: apply y = relu(y*s+t) to input columns while loading (layer-3 reads raw agg of layer 2)
template <bool ACT>
__global__ void __launch_bounds__(256, 2)
k_gemm128(const float* __restrict__ In, const float* __restrict__ Wg,
          const float* __restrict__ sv, const float* __restrict__ tv,
          float* __restrict__ out1, float* __restrict__ out2) {
    __shared__ float Wsm[128 * 128];           // 64 KB, loaded once per block
    __shared__ float Asm[2][64 * 16];          // double-buffered A tile [node][k]
    const int tid = threadIdx.x;

    for (int i = tid * 4; i < 128 * 128; i += 1024)
        *(float4*)(Wsm + i) = *(const float4*)(Wg + i);

    const int an = tid >> 2;                   // A-load: node in tile (0..63)
    const int aq = (tid & 3) * 4;              // A-load: k offset (0,4,8,12)
    const int tr = tid >> 5, tc = tid & 31;
    const int r0 = tr * 8, c0 = tc * 4;
    __syncthreads();

    for (int tile = blockIdx.x; tile < N_NODES / 64; tile += gridDim.x) {
        const long long base = (long long)tile * 64;
        float acc[8][4];
#pragma unroll
        for (int i = 0; i < 8; i++)
#pragma unroll
            for (int j = 0; j < 4; j++) acc[i][j] = 0.0f;

        // prologue: chunk 0
        {
            float4 v = *(const float4*)(In + (base + an) * HID + aq);
            if (ACT) {
                float4 s4 = *(const float4*)(sv + aq);
                float4 t4 = *(const float4*)(tv + aq);
                v.x = fmaxf(v.x * s4.x + t4.x, 0.0f);
                v.y = fmaxf(v.y * s4.y + t4.y, 0.0f);
                v.z = fmaxf(v.z * s4.z + t4.z, 0.0f);
                v.w = fmaxf(v.w * s4.w + t4.w, 0.0f);
            }
            *(float4*)(&Asm[0][an * 16 + aq]) = v;
        }
        __syncthreads();

#pragma unroll
        for (int kc = 0; kc < 8; kc++) {
            const int cur = kc & 1;
            if (kc < 7) {                      // prefetch next chunk
                float4 v = *(const float4*)(In + (base + an) * HID + (kc + 1) * 16 + aq);
                if (ACT) {
                    float4 s4 = *(const float4*)(sv + (kc + 1) * 16 + aq);
                    float4 t4 = *(const float4*)(tv + (kc + 1) * 16 + aq);
                    v.x = fmaxf(v.x * s4.x + t4.x, 0.0f);
                    v.y = fmaxf(v.y * s4.y + t4.y, 0.0f);
                    v.z = fmaxf(v.z * s4.z + t4.z, 0.0f);
                    v.w = fmaxf(v.w * s4.w + t4.w, 0.0f);
                }
                *(float4*)(&Asm[cur ^ 1][an * 16 + aq]) = v;
            }
#pragma unroll
            for (int k4 = 0; k4 < 4; k4++) {
                float a[8][4], b[4][4];
#pragma unroll
                for (int i = 0; i < 8; i++) {
                    float4 av = *(const float4*)(&Asm[cur][(r0 + i) * 16 + k4 * 4]);
                    a[i][0] = av.x; a[i][1] = av.y; a[i][2] = av.z; a[i][3] = av.w;
                }
#pragma unroll
                for (int q = 0; q < 4; q++) {
                    float4 bv = *(const float4*)(&Wsm[(kc * 16 + k4 * 4 + q) * 128 + c0]);
                    b[q][0] = bv.x; b[q][1] = bv.y; b[q][2] = bv.z; b[q][3] = bv.w;
                }
#pragma unroll
                for (int q = 0; q < 4; q++)
#pragma unroll
                    for (int i = 0; i < 8; i++)
#pragma unroll
                        for (int j = 0; j < 4; j++)
                            acc[i][j] += a[i][q] * b[q][j];
            }
            __syncthreads();
        }
        // epilogue
#pragma unroll
        for (int i = 0; i < 8; i++) {
            long long node = base + r0 + i;
            float di = g_dinv[node];
            float di2 = di * di;
            float4 v = make_float4(acc[i][0], acc[i][1], acc[i][2], acc[i][3]);
            *(float4*)(out1 + node * HID + c0) = v;
            *(float4*)(out2 + node * HID + c0) =
                make_float4(di2 * v.x, di2 * v.y, di2 * v.z, di2 * v.w);
        }
    }
}

// edge scatter 128-wide: dstbuf[dst] += norm * srcbuf[src]; one warp per edge
__global__ void k_scatter128(const float* __restrict__ srcbuf, float* __restrict__ dstbuf,
                             const int* __restrict__ ei) {
    long long t = (long long)blockIdx.x * blockDim.x + threadIdx.x;
    int e = (int)(t >> 5);
    if (e >= N_EDGES) return;
    int lane = threadIdx.x & 31;
    int s = ei[e], d = ei[N_EDGES + e];
    float nrm = g_dinv[s] * g_dinv[d];
    float4 v = *(const float4*)(srcbuf + (long long)s * HID + lane * 4);
    red_add_v4(dstbuf + (long long)d * HID + lane * 4,
               nrm * v.x, nrm * v.y, nrm * v.z, nrm * v.w);
}

// pool: relu(bn3(out3)) summed per graph; one warp per node
__global__ void k_pool(const float* __restrict__ h, const int* __restrict__ batch) {
    long long t = (long long)blockIdx.x * blockDim.x + threadIdx.x;
    int node = (int)(t >> 5);
    if (node >= N_NODES) return;
    int lane = threadIdx.x & 31;
    int g = batch[node];
    float4 v  = *(const float4*)(h + (long long)node * HID + lane * 4);
    float4 s4 = *(const float4*)(g_s + 2 * HID + lane * 4);
    float4 t4 = *(const float4*)(g_t + 2 * HID + lane * 4);
    float a = fmaxf(v.x * s4.x + t4.x, 0.0f);
    float b = fmaxf(v.y * s4.y + t4.y, 0.0f);
    float c = fmaxf(v.z * s4.z + t4.z, 0.0f);
    float dd = fmaxf(v.w * s4.w + t4.w, 0.0f);
    red_add_v4(g_pool + (long long)g * HID + lane * 4, a, b, c, dd);
}

// final MLP head: 8 graphs per block (1 warp per graph)
__global__ void k_mlp(const float* __restrict__ Wc1, const float* __restrict__ bc1,
                      const float* __restrict__ Wc2, const float* __restrict__ bc2,
                      float* __restrict__ out) {
    __shared__ float W1s[128 * 64];
    __shared__ float w2s[64];
    __shared__ float b1s[64];
    __shared__ float msm[8][128];
    int tid = threadIdx.x;
    for (int i = tid; i < 128 * 64; i += 256) W1s[i] = Wc1[i];
    if (tid < 64) { w2s[tid] = Wc2[tid]; b1s[tid] = bc1[tid]; }
    __syncthreads();
    int w = tid >> 5, lane = tid & 31;
    int g = blockIdx.x * 8 + w;
    float inv = 1.0f / fmaxf(g_cnt[g], 1.0f);
    float4 v = *(const float4*)(g_pool + (long long)g * HID + lane * 4);
    *(float4*)(&msm[w][lane * 4]) = make_float4(v.x * inv, v.y * inv, v.z * inv, v.w * inv);
    __syncwarp();
    float h0 = b1s[lane], h1 = b1s[lane + 32];
#pragma unroll 8
    for (int i = 0; i < 128; i++) {
        float m = msm[w][i];
        h0 += m * W1s[i * 64 + lane];
        h1 += m * W1s[i * 64 + lane + 32];
    }
    h0 = fmaxf(h0, 0.0f);
    h1 = fmaxf(h1, 0.0f);
    float p = h0 * w2s[lane] + h1 * w2s[lane + 32];
#pragma unroll
    for (int off = 16; off > 0; off >>= 1) p += __shfl_down_sync(0xffffffffu, p, off);
    if (lane == 0) out[g] = p + bc2[0];
}

// ---------------- launch ----------------
extern "C" void kernel_launch(void* const* d_in, const int* in_sizes, int n_in,
                              void* d_out, int out_size) {
    const float* x     = (const float*)d_in[0];
    const int*   ei    = (const int*)d_in[1];
    const int*   batch = (const int*)d_in[2];
    const float* W1 = (const float*)d_in[3];
    const float* b1 = (const float*)d_in[4];
    const float* ga1 = (const float*)d_in[5];
    const float* be1 = (const float*)d_in[6];
    const float* rm1 = (const float*)d_in[7];
    const float* rv1 = (const float*)d_in[8];
    const float* W2 = (const float*)d_in[9];
    const float* b2 = (const float*)d_in[10];
    const float* ga2 = (const float*)d_in[11];
    const float* be2 = (const float*)d_in[12];
    const float* rm2 = (const float*)d_in[13];
    const float* rv2 = (const float*)d_in[14];
    const float* W3 = (const float*)d_in[15];
    const float* b3 = (const float*)d_in[16];
    const float* ga3 = (const float*)d_in[17];
    const float* be3 = (const float*)d_in[18];
    const float* rm3 = (const float*)d_in[19];
    const float* rv3 = (const float*)d_in[20];
    const float* Wc1 = (const float*)d_in[21];
    const float* bc1 = (const float*)d_in[22];
    const float* Wc2 = (const float*)d_in[23];
    const float* bc2 = (const float*)d_in[24];
    float* out = (float*)d_out;

    float *p_s = nullptr, *p_t = nullptr;   // device addresses of g_s / g_t
    cudaGetSymbolAddress((void**)&p_s, g_s);
    cudaGetSymbolAddress((void**)&p_t, g_t);
    float *p_h1 = nullptr, *p_hw = nullptr, *p_out = nullptr;
    cudaGetSymbolAddress((void**)&p_h1, g_h1);
    cudaGetSymbolAddress((void**)&p_hw, g_hw);
    cudaGetSymbolAddress((void**)&p_out, g_out);

    k_zero<<<(N_GRAPHS * HID) / 256, 256>>>();
    k_bnprep<<<1, 128>>>(b1, ga1, be1, rm1, rv1, b2, ga2, be2, rm2, rv2,
                         b3, ga3, be3, rm3, rv3);
    k_deg<<<(N_EDGES + 255) / 256, 256>>>(ei);
    k_node_prep<<<(N_NODES + 255) / 256, 256>>>(x, batch);
    k_scatter8<<<(N_EDGES + 255) / 256, 256>>>(ei);
    k_gemm1<<<N_NODES / 32, 128>>>(W1);

    const int gemm_grid = 148 * 2;
    // layer 2: hW2 = h1 @ W2 -> g_hw ; g_out = dinv^2 * hW2
    k_gemm128<false><<<gemm_grid, 256>>>(p_h1, W2, nullptr, nullptr, p_hw, p_out);
    k_scatter128<<<(int)(((long long)N_EDGES * 32 + 255) / 256), 256>>>(p_hw, p_out, ei);
    // layer 3: input = act2(g_out); hW3 -> g_hw ; g_h1 = dinv^2 * hW3
    k_gemm128<true><<<gemm_grid, 256>>>(p_out, W3, p_s + HID, p_t + HID, p_hw, p_h1);
    k_scatter128<<<(int)(((long long)N_EDGES * 32 + 255) / 256), 256>>>(p_hw, p_h1, ei);

    k_pool<<<(int)(((long long)N_NODES * 32 + 255) / 256), 256>>>(p_h1, batch);
    k_mlp<<<N_GRAPHS / 8, 256>>>(Wc1, bc1, Wc2, bc2, out);
}

// round 4
// speedup vs baseline: 1.0225x; 1.0225x over previous
#include <cuda_runtime.h>
#include <cstdint>

#define N_NODES  1000000
#define N_EDGES  4000000
#define N_GRAPHS 32768
#define HID      128
#define BN_EPS   1e-5f

// ---------------- scratch (device globals: no allocations allowed) ----------------
__device__ float g_dinv[N_NODES];          // degree, then rsqrt(deg)
__device__ float g_xpad[N_NODES * 8];      // x padded to 8 cols
__device__ float g_agg0[N_NODES * 8];      // A @ x   (7 used cols)
__device__ float g_h1 [N_NODES * HID];     // h1 (activated), later reused as out3
__device__ float g_hw [N_NODES * HID];     // hW scratch (gather source)
__device__ float g_out[N_NODES * HID];     // aggregation buffer layer 2
__device__ float g_pool[N_GRAPHS * HID];   // pooled sums
__device__ float g_cnt [N_GRAPHS];         // nodes per graph
__device__ float g_s[3 * HID];             // folded BN scale  per layer
__device__ float g_t[3 * HID];             // folded BN shift (includes bias) per layer

// ---------------- helpers ----------------
__device__ __forceinline__ void red_add_v4(float* addr, float x, float y, float z, float w) {
    asm volatile("red.global.add.v4.f32 [%0], {%1,%2,%3,%4};"
                 :: "l"(addr), "f"(x), "f"(y), "f"(z), "f"(w) : "memory");
}

// pack one float into both halves of an f32x2 register pair
__device__ __forceinline__ unsigned long long dupf(float a) {
    unsigned long long r;
    asm("mov.b64 %0, {%1, %1};" : "=l"(r) : "f"(a));
    return r;
}
// packed dual-FMA: acc.{lo,hi} += a.{lo,hi} * b.{lo,hi}
__device__ __forceinline__ void ffma2(unsigned long long& acc, unsigned long long a,
                                      unsigned long long b) {
    asm("fma.rn.f32x2 %0, %1, %2, %0;" : "+l"(acc) : "l"(a), "l"(b));
}
__device__ __forceinline__ float2 unpack2(unsigned long long v) {
    float2 r;
    asm("mov.b64 {%0, %1}, %2;" : "=f"(r.x), "=f"(r.y) : "l"(v));
    return r;
}
__device__ __forceinline__ unsigned long long zero2() {
    unsigned long long r;
    asm("mov.b64 %0, {%1, %1};" : "=l"(r) : "f"(0.0f));
    return r;
}

// ---------------- kernels ----------------
__global__ void k_zero() {
    int i = blockIdx.x * blockDim.x + threadIdx.x;         // grid covers N_GRAPHS*HID
    g_pool[i] = 0.0f;
    if (i < N_NODES)  g_dinv[i] = 0.0f;
    if (i < N_GRAPHS) g_cnt[i]  = 0.0f;
}

__global__ void k_bnprep(const float* __restrict__ b1, const float* __restrict__ ga1,
                         const float* __restrict__ be1, const float* __restrict__ rm1,
                         const float* __restrict__ rv1,
                         const float* __restrict__ b2, const float* __restrict__ ga2,
                         const float* __restrict__ be2, const float* __restrict__ rm2,
                         const float* __restrict__ rv2,
                         const float* __restrict__ b3, const float* __restrict__ ga3,
                         const float* __restrict__ be3, const float* __restrict__ rm3,
                         const float* __restrict__ rv3) {
    int j = threadIdx.x;
    if (j >= HID) return;
    const float* B[3]  = {b1, b2, b3};
    const float* G[3]  = {ga1, ga2, ga3};
    const float* BE[3] = {be1, be2, be3};
    const float* RM[3] = {rm1, rm2, rm3};
    const float* RV[3] = {rv1, rv2, rv3};
    for (int l = 0; l < 3; l++) {
        float s = G[l][j] * rsqrtf(RV[l][j] + BN_EPS);
        g_s[l * HID + j] = s;
        g_t[l * HID + j] = (B[l][j] - RM[l][j]) * s + BE[l][j];
    }
}

// degree count (edges by dst; self-loop added in node_prep)
__global__ void k_deg(const int* __restrict__ ei) {
    int e = blockIdx.x * blockDim.x + threadIdx.x;
    if (e >= N_EDGES) return;
    atomicAdd(&g_dinv[ei[N_EDGES + e]], 1.0f);
}

// dinv = rsqrt(deg+1); pad x; init agg0 with self-loop term; per-graph counts
__global__ void k_node_prep(const float* __restrict__ x, const int* __restrict__ batch) {
    int i = blockIdx.x * blockDim.x + threadIdx.x;
    if (i >= N_NODES) return;
    float d  = g_dinv[i] + 1.0f;           // + self-loop
    float di = rsqrtf(d);
    g_dinv[i] = di;
    float di2 = di * di;
    const float* xr = x + (long long)i * 7;
    float xv[8];
#pragma unroll
    for (int j = 0; j < 7; j++) xv[j] = xr[j];
    xv[7] = 0.0f;
    float4* xp = (float4*)(g_xpad + i * 8);
    float4* ag = (float4*)(g_agg0 + i * 8);
    xp[0] = make_float4(xv[0], xv[1], xv[2], xv[3]);
    xp[1] = make_float4(xv[4], xv[5], xv[6], xv[7]);
    ag[0] = make_float4(di2 * xv[0], di2 * xv[1], di2 * xv[2], di2 * xv[3]);
    ag[1] = make_float4(di2 * xv[4], di2 * xv[5], di2 * xv[6], di2 * xv[7]);
    atomicAdd(&g_cnt[batch[i]], 1.0f);
}

// layer-1 edge scatter on 8-wide x: agg0[dst] += norm * xpad[src]
__global__ void k_scatter8(const int* __restrict__ ei) {
    int e = blockIdx.x * blockDim.x + threadIdx.x;
    if (e >= N_EDGES) return;
    int s = ei[e], d = ei[N_EDGES + e];
    float nrm = g_dinv[s] * g_dinv[d];
    const float4* sp = (const float4*)(g_xpad + s * 8);
    float4 a = sp[0], b = sp[1];
    red_add_v4(g_agg0 + d * 8,     nrm * a.x, nrm * a.y, nrm * a.z, nrm * a.w);
    red_add_v4(g_agg0 + d * 8 + 4, nrm * b.x, nrm * b.y, nrm * b.z, nrm * b.w);
}

// h1 = relu( (agg0 @ W1) * s1 + t1 )   (agg0 is [N,8], 7 real cols)
__global__ void k_gemm1(const float* __restrict__ W1) {
    __shared__ float Wsm[7 * 128];
    __shared__ float rsm[32 * 8];
    int j = threadIdx.x;                       // 128 threads: output column
#pragma unroll
    for (int k = 0; k < 7; k++) Wsm[k * 128 + j] = W1[k * 128 + j];
    float sj = g_s[j], tj = g_t[j];
    int base = blockIdx.x * 32;
    rsm[j]       = g_agg0[base * 8 + j];
    rsm[j + 128] = g_agg0[base * 8 + j + 128];
    __syncthreads();
#pragma unroll 4
    for (int n = 0; n < 32; n++) {
        float acc = 0.0f;
#pragma unroll
        for (int k = 0; k < 7; k++) acc += rsm[n * 8 + k] * Wsm[k * 128 + j];
        g_h1[(long long)(base + n) * HID + j] = fmaxf(acc * sj + tj, 0.0f);
    }
}

// hW = act(In) @ W ; out1 = hW ; out2 = dinv^2 * hW  (self-loop init for aggregation)
// Packed f32x2 FFMA mainloop. Tile: 128 nodes x 128 cols per block.
// Thread = 16 rows x 4 cols (2 packed col-pairs).
template <bool ACT>
__global__ void __launch_bounds__(256, 2)
k_gemm128(const float* __restrict__ In, const float* __restrict__ Wg,
          const float* __restrict__ sv, const float* __restrict__ tv,
          float* __restrict__ out1, float* __restrict__ out2) {
    __shared__ __align__(16) float Wsm[128 * 128];     // 64 KB, loaded once per block
    __shared__ __align__(16) float Asm[2][128 * 16];   // double-buffered A tile [node][k]
    const int tid = threadIdx.x;

    for (int i = tid * 4; i < 128 * 128; i += 1024)
        *(float4*)(Wsm + i) = *(const float4*)(Wg + i);

    const int an   = tid >> 1;             // A-load: row in tile (0..127)
    const int aq   = (tid & 1) * 8;        // A-load: k offset (0 or 8)
    const int lane = tid & 31;
    const int row0 = (tid >> 5) * 16;      // compute: 16 rows per thread
    const int c0   = lane * 4;             // compute: 4 cols per thread
    __syncthreads();

    const int NT = (N_NODES + 127) / 128;  // 7813 (last tile is half)
    for (int tile = blockIdx.x; tile < NT; tile += gridDim.x) {
        const long long base = (long long)tile * 128;
        unsigned long long acc[16][2];
#pragma unroll
        for (int i = 0; i < 16; i++) { acc[i][0] = zero2(); acc[i][1] = zero2(); }

        const long long arow = base + an;
        const bool avalid = (arow < N_NODES);
        const float* aptr = In + arow * HID;

        // ---- chunk loader: 16 k-values of 128 rows ----
        auto load_chunk = [&](int kc, float* dst) {
            float4 v0, v1;
            if (avalid) {
                v0 = *(const float4*)(aptr + kc * 16 + aq);
                v1 = *(const float4*)(aptr + kc * 16 + aq + 4);
                if (ACT) {
                    float4 s0 = *(const float4*)(sv + kc * 16 + aq);
                    float4 t0 = *(const float4*)(tv + kc * 16 + aq);
                    float4 s1 = *(const float4*)(sv + kc * 16 + aq + 4);
                    float4 t1 = *(const float4*)(tv + kc * 16 + aq + 4);
                    v0.x = fmaxf(v0.x * s0.x + t0.x, 0.0f);
                    v0.y = fmaxf(v0.y * s0.y + t0.y, 0.0f);
                    v0.z = fmaxf(v0.z * s0.z + t0.z, 0.0f);
                    v0.w = fmaxf(v0.w * s0.w + t0.w, 0.0f);
                    v1.x = fmaxf(v1.x * s1.x + t1.x, 0.0f);
                    v1.y = fmaxf(v1.y * s1.y + t1.y, 0.0f);
                    v1.z = fmaxf(v1.z * s1.z + t1.z, 0.0f);
                    v1.w = fmaxf(v1.w * s1.w + t1.w, 0.0f);
                }
            } else {
                v0 = make_float4(0.f, 0.f, 0.f, 0.f);
                v1 = v0;
            }
            *(float4*)(dst + an * 16 + aq)     = v0;
            *(float4*)(dst + an * 16 + aq + 4) = v1;
        };

        load_chunk(0, Asm[0]);
        __syncthreads();

#pragma unroll
        for (int kc = 0; kc < 8; kc++) {
            const int cur = kc & 1;
            if (kc < 7) load_chunk(kc + 1, Asm[cur ^ 1]);

#pragma unroll
            for (int k4 = 0; k4 < 4; k4++) {
                // B pairs: lanes 0..31 read one contiguous 512B W row -> conflict-free
                unsigned long long b0[4], b1[4];
#pragma unroll
                for (int q = 0; q < 4; q++) {
                    ulonglong2 bv = *(const ulonglong2*)(&Wsm[(kc * 16 + k4 * 4 + q) * 128 + c0]);
                    b0[q] = bv.x;          // cols (c0, c0+1)
                    b1[q] = bv.y;          // cols (c0+2, c0+3)
                }
#pragma unroll
                for (int i = 0; i < 16; i++) {
                    // a is warp-uniform (all lanes same row) -> LDS broadcast
                    float4 av = *(const float4*)(&Asm[cur][(row0 + i) * 16 + k4 * 4]);
                    unsigned long long ad;
                    ad = dupf(av.x); ffma2(acc[i][0], ad, b0[0]); ffma2(acc[i][1], ad, b1[0]);
                    ad = dupf(av.y); ffma2(acc[i][0], ad, b0[1]); ffma2(acc[i][1], ad, b1[1]);
                    ad = dupf(av.z); ffma2(acc[i][0], ad, b0[2]); ffma2(acc[i][1], ad, b1[2]);
                    ad = dupf(av.w); ffma2(acc[i][0], ad, b0[3]); ffma2(acc[i][1], ad, b1[3]);
                }
            }
            __syncthreads();
        }

        // epilogue
#pragma unroll
        for (int i = 0; i < 16; i++) {
            long long node = base + row0 + i;
            if (node < N_NODES) {
                float di = g_dinv[node];
                float di2 = di * di;
                float2 p0 = unpack2(acc[i][0]);
                float2 p1 = unpack2(acc[i][1]);
                float4 v = make_float4(p0.x, p0.y, p1.x, p1.y);
                *(float4*)(out1 + node * HID + c0) = v;
                *(float4*)(out2 + node * HID + c0) =
                    make_float4(di2 * v.x, di2 * v.y, di2 * v.z, di2 * v.w);
            }
        }
    }
}

// edge scatter 128-wide: dstbuf[dst] += norm * srcbuf[src]; one warp per edge
__global__ void k_scatter128(const float* __restrict__ srcbuf, float* __restrict__ dstbuf,
                             const int* __restrict__ ei) {
    long long t = (long long)blockIdx.x * blockDim.x + threadIdx.x;
    int e = (int)(t >> 5);
    if (e >= N_EDGES) return;
    int lane = threadIdx.x & 31;
    int s = ei[e], d = ei[N_EDGES + e];
    float nrm = g_dinv[s] * g_dinv[d];
    float4 v = *(const float4*)(srcbuf + (long long)s * HID + lane * 4);
    red_add_v4(dstbuf + (long long)d * HID + lane * 4,
               nrm * v.x, nrm * v.y, nrm * v.z, nrm * v.w);
}

// pool: relu(bn3(out3)) summed per graph; one warp per node
__global__ void k_pool(const float* __restrict__ h, const int* __restrict__ batch) {
    long long t = (long long)blockIdx.x * blockDim.x + threadIdx.x;
    int node = (int)(t >> 5);
    if (node >= N_NODES) return;
    int lane = threadIdx.x & 31;
    int g = batch[node];
    float4 v  = *(const float4*)(h + (long long)node * HID + lane * 4);
    float4 s4 = *(const float4*)(g_s + 2 * HID + lane * 4);
    float4 t4 = *(const float4*)(g_t + 2 * HID + lane * 4);
    float a = fmaxf(v.x * s4.x + t4.x, 0.0f);
    float b = fmaxf(v.y * s4.y + t4.y, 0.0f);
    float c = fmaxf(v.z * s4.z + t4.z, 0.0f);
    float dd = fmaxf(v.w * s4.w + t4.w, 0.0f);
    red_add_v4(g_pool + (long long)g * HID + lane * 4, a, b, c, dd);
}

// final MLP head: 8 graphs per block (1 warp per graph)
__global__ void k_mlp(const float* __restrict__ Wc1, const float* __restrict__ bc1,
                      const float* __restrict__ Wc2, const float* __restrict__ bc2,
                      float* __restrict__ out) {
    __shared__ float W1s[128 * 64];
    __shared__ float w2s[64];
    __shared__ float b1s[64];
    __shared__ float msm[8][128];
    int tid = threadIdx.x;
    for (int i = tid; i < 128 * 64; i += 256) W1s[i] = Wc1[i];
    if (tid < 64) { w2s[tid] = Wc2[tid]; b1s[tid] = bc1[tid]; }
    __syncthreads();
    int w = tid >> 5, lane = tid & 31;
    int g = blockIdx.x * 8 + w;
    float inv = 1.0f / fmaxf(g_cnt[g], 1.0f);
    float4 v = *(const float4*)(g_pool + (long long)g * HID + lane * 4);
    *(float4*)(&msm[w][lane * 4]) = make_float4(v.x * inv, v.y * inv, v.z * inv, v.w * inv);
    __syncwarp();
    float h0 = b1s[lane], h1 = b1s[lane + 32];
#pragma unroll 8
    for (int i = 0; i < 128; i++) {
        float m = msm[w][i];
        h0 += m * W1s[i * 64 + lane];
        h1 += m * W1s[i * 64 + lane + 32];
    }
    h0 = fmaxf(h0, 0.0f);
    h1 = fmaxf(h1, 0.0f);
    float p = h0 * w2s[lane] + h1 * w2s[lane + 32];
#pragma unroll
    for (int off = 16; off > 0; off >>= 1) p += __shfl_down_sync(0xffffffffu, p, off);
    if (lane == 0) out[g] = p + bc2[0];
}

// ---------------- launch ----------------
extern "C" void kernel_launch(void* const* d_in, const int* in_sizes, int n_in,
                              void* d_out, int out_size) {
    const float* x     = (const float*)d_in[0];
    const int*   ei    = (const int*)d_in[1];
    const int*   batch = (const int*)d_in[2];
    const float* W1 = (const float*)d_in[3];
    const float* b1 = (const float*)d_in[4];
    const float* ga1 = (const float*)d_in[5];
    const float* be1 = (const float*)d_in[6];
    const float* rm1 = (const float*)d_in[7];
    const float* rv1 = (const float*)d_in[8];
    const float* W2 = (const float*)d_in[9];
    const float* b2 = (const float*)d_in[10];
    const float* ga2 = (const float*)d_in[11];
    const float* be2 = (const float*)d_in[12];
    const float* rm2 = (const float*)d_in[13];
    const float* rv2 = (const float*)d_in[14];
    const float* W3 = (const float*)d_in[15];
    const float* b3 = (const float*)d_in[16];
    const float* ga3 = (const float*)d_in[17];
    const float* be3 = (const float*)d_in[18];
    const float* rm3 = (const float*)d_in[19];
    const float* rv3 = (const float*)d_in[20];
    const float* Wc1 = (const float*)d_in[21];
    const float* bc1 = (const float*)d_in[22];
    const float* Wc2 = (const float*)d_in[23];
    const float* bc2 = (const float*)d_in[24];
    float* out = (float*)d_out;

    float *p_s = nullptr, *p_t = nullptr;   // device addresses of g_s / g_t
    cudaGetSymbolAddress((void**)&p_s, g_s);
    cudaGetSymbolAddress((void**)&p_t, g_t);
    float *p_h1 = nullptr, *p_hw = nullptr, *p_out = nullptr;
    cudaGetSymbolAddress((void**)&p_h1, g_h1);
    cudaGetSymbolAddress((void**)&p_hw, g_hw);
    cudaGetSymbolAddress((void**)&p_out, g_out);

    k_zero<<<(N_GRAPHS * HID) / 256, 256>>>();
    k_bnprep<<<1, 128>>>(b1, ga1, be1, rm1, rv1, b2, ga2, be2, rm2, rv2,
                         b3, ga3, be3, rm3, rv3);
    k_deg<<<(N_EDGES + 255) / 256, 256>>>(ei);
    k_node_prep<<<(N_NODES + 255) / 256, 256>>>(x, batch);
    k_scatter8<<<(N_EDGES + 255) / 256, 256>>>(ei);
    k_gemm1<<<N_NODES / 32, 128>>>(W1);

    const int gemm_grid = 148 * 2;
    // layer 2: hW2 = h1 @ W2 -> g_hw ; g_out = dinv^2 * hW2
    k_gemm128<false><<<gemm_grid, 256>>>(p_h1, W2, nullptr, nullptr, p_hw, p_out);
    k_scatter128<<<(int)(((long long)N_EDGES * 32 + 255) / 256), 256>>>(p_hw, p_out, ei);
    // layer 3: input = act2(g_out); hW3 -> g_hw ; g_h1 = dinv^2 * hW3
    k_gemm128<true><<<gemm_grid, 256>>>(p_out, W3, p_s + HID, p_t + HID, p_hw, p_h1);
    k_scatter128<<<(int)(((long long)N_EDGES * 32 + 255) / 256), 256>>>(p_hw, p_h1, ei);

    k_pool<<<(int)(((long long)N_NODES * 32 + 255) / 256), 256>>>(p_h1, batch);
    k_mlp<<<N_GRAPHS / 8, 256>>>(Wc1, bc1, Wc2, bc2, out);
}

// round 9
// speedup vs baseline: 1.1638x; 1.1382x over previous
#include <cuda_runtime.h>
#include <cuda_bf16.h>
#include <cstdint>

#define N_NODES  1000000
#define N_EDGES  4000000
#define N_GRAPHS 32768
#define HID      128
#define BN_EPS   1e-5f

#define NTILES   7813                       // ceil(1e6/128)
#define N_PAD    (NTILES * 128)             // 1000064

// ---------------- scratch (device globals: no allocations allowed) ----------------
__device__ float g_dinv[N_PAD];            // degree, then rsqrt(deg); pad rows = 0
__device__ float g_xpad[N_NODES * 8];      // x padded to 8 cols
__device__ float g_agg0[N_NODES * 8];      // A @ x   (7 used cols)
__device__ float g_h1 [N_PAD * HID];       // h1 (activated), later reused as out3
__device__ float g_hw [N_PAD * HID];       // hW scratch (gather source)
__device__ float g_out[N_PAD * HID];       // aggregation buffer layer 2
__device__ float g_pool[N_GRAPHS * HID];   // pooled sums
__device__ float g_cnt [N_GRAPHS];         // nodes per graph
__device__ float g_s[3 * HID];             // folded BN scale  per layer
__device__ float g_t[3 * HID];             // folded BN shift (includes bias) per layer

// ---------------- helpers ----------------
__device__ __forceinline__ void red_add_v4(float* addr, float x, float y, float z, float w) {
    asm volatile("red.global.add.v4.f32 [%0], {%1,%2,%3,%4};"
                 :: "l"(addr), "f"(x), "f"(y), "f"(z), "f"(w) : "memory");
}
__device__ __forceinline__ uint32_t smem_u32(const void* p) {
    uint32_t a;
    asm("{ .reg .u64 t; cvta.to.shared.u64 t, %1; cvt.u32.u64 %0, t; }" : "=r"(a) : "l"(p));
    return a;
}
// split fp32 pair -> bf16x2 hi (returned), bf16x2 lo (out-param); elem a in low half
__device__ __forceinline__ uint32_t pack_hilo(float a, float b, uint32_t& lo) {
    __nv_bfloat16 ah = __float2bfloat16(a);
    __nv_bfloat16 bh = __float2bfloat16(b);
    __nv_bfloat16 al = __float2bfloat16(a - __bfloat162float(ah));
    __nv_bfloat16 bl = __float2bfloat16(b - __bfloat162float(bh));
    lo = ((uint32_t)__bfloat16_as_ushort(bl) << 16) | __bfloat16_as_ushort(al);
    return ((uint32_t)__bfloat16_as_ushort(bh) << 16) | __bfloat16_as_ushort(ah);
}
__device__ __forceinline__ void ldsm4(uint32_t* r, uint32_t addr) {
    asm volatile("ldmatrix.sync.aligned.m8n8.x4.shared.b16 {%0,%1,%2,%3}, [%4];"
                 : "=r"(r[0]), "=r"(r[1]), "=r"(r[2]), "=r"(r[3]) : "r"(addr));
}
__device__ __forceinline__ void mma_bf16(float* d, const uint32_t* a, uint32_t b0, uint32_t b1) {
    asm volatile(
        "mma.sync.aligned.m16n8k16.row.col.f32.bf16.bf16.f32 "
        "{%0,%1,%2,%3}, {%4,%5,%6,%7}, {%8,%9}, {%0,%1,%2,%3};"
        : "+f"(d[0]), "+f"(d[1]), "+f"(d[2]), "+f"(d[3])
        : "r"(a[0]), "r"(a[1]), "r"(a[2]), "r"(a[3]), "r"(b0), "r"(b1));
}

// padded bf16 tile layout: 128 rows x 136 bf16 (272 B/row; rows shift 4 banks -> LDSM conflict-free)
#define ROWB   136
#define TILE_B (128 * ROWB * 2)             // 34816 bytes
#define SM_WHI 0
#define SM_WLO (TILE_B)
#define SM_AHI (2 * TILE_B)
#define SM_ALO (3 * TILE_B)
#define SM_TOT (4 * TILE_B)

// ---------------- kernels ----------------
__global__ void k_zero() {
    int i = blockIdx.x * blockDim.x + threadIdx.x;         // grid covers N_GRAPHS*HID
    g_pool[i] = 0.0f;
    if (i < N_PAD)    g_dinv[i] = 0.0f;
    if (i < N_GRAPHS) g_cnt[i]  = 0.0f;
}

__global__ void k_bnprep(const float* __restrict__ b1, const float* __restrict__ ga1,
                         const float* __restrict__ be1, const float* __restrict__ rm1,
                         const float* __restrict__ rv1,
                         const float* __restrict__ b2, const float* __restrict__ ga2,
                         const float* __restrict__ be2, const float* __restrict__ rm2,
                         const float* __restrict__ rv2,
                         const float* __restrict__ b3, const float* __restrict__ ga3,
                         const float* __restrict__ be3, const float* __restrict__ rm3,
                         const float* __restrict__ rv3) {
    int j = threadIdx.x;
    if (j >= HID) return;
    const float* B[3]  = {b1, b2, b3};
    const float* G[3]  = {ga1, ga2, ga3};
    const float* BE[3] = {be1, be2, be3};
    const float* RM[3] = {rm1, rm2, rm3};
    const float* RV[3] = {rv1, rv2, rv3};
    for (int l = 0; l < 3; l++) {
        float s = G[l][j] * rsqrtf(RV[l][j] + BN_EPS);
        g_s[l * HID + j] = s;
        g_t[l * HID + j] = (B[l][j] - RM[l][j]) * s + BE[l][j];
    }
}

__global__ void k_deg(const int* __restrict__ ei) {
    int e = blockIdx.x * blockDim.x + threadIdx.x;
    if (e >= N_EDGES) return;
    atomicAdd(&g_dinv[ei[N_EDGES + e]], 1.0f);
}

__global__ void k_node_prep(const float* __restrict__ x, const int* __restrict__ batch) {
    int i = blockIdx.x * blockDim.x + threadIdx.x;
    if (i >= N_NODES) return;
    float d  = g_dinv[i] + 1.0f;           // + self-loop
    float di = rsqrtf(d);
    g_dinv[i] = di;
    float di2 = di * di;
    const float* xr = x + (long long)i * 7;
    float xv[8];
#pragma unroll
    for (int j = 0; j < 7; j++) xv[j] = xr[j];
    xv[7] = 0.0f;
    float4* xp = (float4*)(g_xpad + i * 8);
    float4* ag = (float4*)(g_agg0 + i * 8);
    xp[0] = make_float4(xv[0], xv[1], xv[2], xv[3]);
    xp[1] = make_float4(xv[4], xv[5], xv[6], xv[7]);
    ag[0] = make_float4(di2 * xv[0], di2 * xv[1], di2 * xv[2], di2 * xv[3]);
    ag[1] = make_float4(di2 * xv[4], di2 * xv[5], di2 * xv[6], di2 * xv[7]);
    atomicAdd(&g_cnt[batch[i]], 1.0f);
}

__global__ void k_scatter8(const int* __restrict__ ei) {
    int e = blockIdx.x * blockDim.x + threadIdx.x;
    if (e >= N_EDGES) return;
    int s = ei[e], d = ei[N_EDGES + e];
    float nrm = g_dinv[s] * g_dinv[d];
    const float4* sp = (const float4*)(g_xpad + s * 8);
    float4 a = sp[0], b = sp[1];
    red_add_v4(g_agg0 + d * 8,     nrm * a.x, nrm * a.y, nrm * a.z, nrm * a.w);
    red_add_v4(g_agg0 + d * 8 + 4, nrm * b.x, nrm * b.y, nrm * b.z, nrm * b.w);
}

// h1 = relu( (agg0 @ W1) * s1 + t1 )   (agg0 is [N,8], 7 real cols)
__global__ void k_gemm1(const float* __restrict__ W1) {
    __shared__ float Wsm[7 * 128];
    __shared__ float rsm[32 * 8];
    int j = threadIdx.x;
#pragma unroll
    for (int k = 0; k < 7; k++) Wsm[k * 128 + j] = W1[k * 128 + j];
    float sj = g_s[j], tj = g_t[j];
    int base = blockIdx.x * 32;
    rsm[j]       = g_agg0[base * 8 + j];
    rsm[j + 128] = g_agg0[base * 8 + j + 128];
    __syncthreads();
#pragma unroll 4
    for (int n = 0; n < 32; n++) {
        float acc = 0.0f;
#pragma unroll
        for (int k = 0; k < 7; k++) acc += rsm[n * 8 + k] * Wsm[k * 128 + j];
        g_h1[(long long)(base + n) * HID + j] = fmaxf(acc * sj + tj, 0.0f);
    }
}

// ---------- HMMA GEMM: out1 = act(In) @ W ; out2 = dinv^2 * out1 ----------
// bf16 hi/lo 3-term split via mma.sync.m16n8k16 (baseline PTX; works on plain sm_103 target).
// 128x128 tile per CTA; 8 warps in 4x2: warp = 32 rows x 64 cols.
template <bool ACT>
__global__ void __launch_bounds__(256, 1)
k_gemm_mma(const float* __restrict__ In, const float* __restrict__ Wg,
           const float* __restrict__ sv, const float* __restrict__ tv,
           float* __restrict__ out1, float* __restrict__ out2) {
    extern __shared__ char smem[];
    const uint32_t sb = smem_u32(smem);
    const int tid  = threadIdx.x;
    const int wid  = tid >> 5, lane = tid & 31;
    const int mw   = wid >> 1;            // 0..3 -> rows mw*32
    const int nw   = wid & 1;             // 0..1 -> cols nw*64

    // ---- W transpose + hi/lo split into padded SMEM (once per CTA) ----
    {
        const int n  = tid >> 1;          // output column -> B row (K-major)
        const int kh = (tid & 1) * 64;
#pragma unroll
        for (int j = 0; j < 8; j++) {
            uint32_t hi[4], lo[4];
#pragma unroll
            for (int q = 0; q < 4; q++) {
                float a = Wg[(kh + j * 8 + q * 2    ) * 128 + n];
                float b = Wg[(kh + j * 8 + q * 2 + 1) * 128 + n];
                hi[q] = pack_hilo(a, b, lo[q]);
            }
            const int off = (n * ROWB + kh + j * 8) * 2;
            *(uint4*)(smem + SM_WHI + off) = make_uint4(hi[0], hi[1], hi[2], hi[3]);
            *(uint4*)(smem + SM_WLO + off) = make_uint4(lo[0], lo[1], lo[2], lo[3]);
        }
    }
    __syncthreads();

    // ldmatrix lane addressing (constant per thread)
    const int a_row  = (lane & 15);            // + mf*16 + mw*32
    const int a_koff = (lane >> 4) * 8;        // + k*16
    const int b_noff = (lane & 7) + ((lane >> 4) & 1) * 8;   // + nf2*16 + nw*64
    const int b_koff = ((lane >> 3) & 1) * 8;                // + k*16

    for (int tile = blockIdx.x; tile < NTILES; tile += gridDim.x) {
        const long long base = (long long)tile * 128;

        // ---- stage A: fp32 -> (ACT) -> bf16 hi/lo into padded SMEM ----
        {
            const int r  = tid >> 1;
            const int kh = (tid & 1) * 64;
            const long long row = base + r;
            const bool valid = (row < N_NODES);
            const float* ap = In + row * HID + kh;
#pragma unroll
            for (int j = 0; j < 8; j++) {
                float4 v0, v1;
                if (valid) {
                    v0 = *(const float4*)(ap + j * 8);
                    v1 = *(const float4*)(ap + j * 8 + 4);
                    if (ACT) {
                        float4 s0 = *(const float4*)(sv + kh + j * 8);
                        float4 t0 = *(const float4*)(tv + kh + j * 8);
                        float4 s1 = *(const float4*)(sv + kh + j * 8 + 4);
                        float4 t1 = *(const float4*)(tv + kh + j * 8 + 4);
                        v0.x = fmaxf(v0.x * s0.x + t0.x, 0.0f);
                        v0.y = fmaxf(v0.y * s0.y + t0.y, 0.0f);
                        v0.z = fmaxf(v0.z * s0.z + t0.z, 0.0f);
                        v0.w = fmaxf(v0.w * s0.w + t0.w, 0.0f);
                        v1.x = fmaxf(v1.x * s1.x + t1.x, 0.0f);
                        v1.y = fmaxf(v1.y * s1.y + t1.y, 0.0f);
                        v1.z = fmaxf(v1.z * s1.z + t1.z, 0.0f);
                        v1.w = fmaxf(v1.w * s1.w + t1.w, 0.0f);
                    }
                } else {
                    v0 = make_float4(0.f, 0.f, 0.f, 0.f);
                    v1 = v0;
                }
                uint4 H, L;
                H.x = pack_hilo(v0.x, v0.y, L.x);
                H.y = pack_hilo(v0.z, v0.w, L.y);
                H.z = pack_hilo(v1.x, v1.y, L.z);
                H.w = pack_hilo(v1.z, v1.w, L.w);
                const int off = (r * ROWB + kh + j * 8) * 2;
                *(uint4*)(smem + SM_AHI + off) = H;
                *(uint4*)(smem + SM_ALO + off) = L;
            }
        }
        __syncthreads();

        // ---- mainloop: 8 k16 steps, 48 HMMA each ----
        float acc[2][8][4];
#pragma unroll
        for (int mf = 0; mf < 2; mf++)
#pragma unroll
            for (int nf = 0; nf < 8; nf++)
#pragma unroll
                for (int q = 0; q < 4; q++) acc[mf][nf][q] = 0.0f;

#pragma unroll
        for (int k = 0; k < 8; k++) {
            uint32_t Bh[4][4], Bl[4][4];
#pragma unroll
            for (int nf2 = 0; nf2 < 4; nf2++) {
                const int n    = nw * 64 + nf2 * 16 + b_noff;
                const uint32_t ad = sb + SM_WHI + (uint32_t)((n * ROWB + k * 16 + b_koff) * 2);
                ldsm4(Bh[nf2], ad);
                ldsm4(Bl[nf2], ad + (SM_WLO - SM_WHI));
            }
            uint32_t Ah[2][4], Al[2][4];
#pragma unroll
            for (int mf = 0; mf < 2; mf++) {
                const int rr = mw * 32 + mf * 16 + a_row;
                const uint32_t ad = sb + SM_AHI + (uint32_t)((rr * ROWB + k * 16 + a_koff) * 2);
                ldsm4(Ah[mf], ad);
                ldsm4(Al[mf], ad + (SM_ALO - SM_AHI));
            }
#pragma unroll
            for (int mf = 0; mf < 2; mf++)
#pragma unroll
                for (int nf2 = 0; nf2 < 4; nf2++) {
                    // nfrag 2*nf2  (B regs 0,1)  and 2*nf2+1 (B regs 2,3)
                    mma_bf16(acc[mf][2 * nf2],     Ah[mf], Bh[nf2][0], Bh[nf2][1]);
                    mma_bf16(acc[mf][2 * nf2],     Al[mf], Bh[nf2][0], Bh[nf2][1]);
                    mma_bf16(acc[mf][2 * nf2],     Ah[mf], Bl[nf2][0], Bl[nf2][1]);
                    mma_bf16(acc[mf][2 * nf2 + 1], Ah[mf], Bh[nf2][2], Bh[nf2][3]);
                    mma_bf16(acc[mf][2 * nf2 + 1], Al[mf], Bh[nf2][2], Bh[nf2][3]);
                    mma_bf16(acc[mf][2 * nf2 + 1], Ah[mf], Bl[nf2][2], Bl[nf2][3]);
                }
        }
        __syncthreads();    // A smem free for next tile's staging

        // ---- epilogue: D frag thread t -> rows t/4, t/4+8; cols (t%4)*2 ----
#pragma unroll
        for (int mf = 0; mf < 2; mf++) {
            const long long r0 = base + mw * 32 + mf * 16 + (lane >> 2);
            const long long r1 = r0 + 8;
            const float d0 = g_dinv[r0], d1 = g_dinv[r1];
            const float e0 = d0 * d0, e1 = d1 * d1;
            float* o1a = out1 + r0 * HID;
            float* o1b = out1 + r1 * HID;
            float* o2a = out2 + r0 * HID;
            float* o2b = out2 + r1 * HID;
            const int cb = nw * 64 + (lane & 3) * 2;
#pragma unroll
            for (int nf = 0; nf < 8; nf++) {
                const int c = cb + nf * 8;
                float2 va = make_float2(acc[mf][nf][0], acc[mf][nf][1]);
                float2 vb = make_float2(acc[mf][nf][2], acc[mf][nf][3]);
                *(float2*)(o1a + c) = va;
                *(float2*)(o1b + c) = vb;
                *(float2*)(o2a + c) = make_float2(e0 * va.x, e0 * va.y);
                *(float2*)(o2b + c) = make_float2(e1 * vb.x, e1 * vb.y);
            }
        }
    }
}

// edge scatter 128-wide: dstbuf[dst] += norm * srcbuf[src]; one warp per edge
__global__ void k_scatter128(const float* __restrict__ srcbuf, float* __restrict__ dstbuf,
                             const int* __restrict__ ei) {
    long long t = (long long)blockIdx.x * blockDim.x + threadIdx.x;
    int e = (int)(t >> 5);
    if (e >= N_EDGES) return;
    int lane = threadIdx.x & 31;
    int s = ei[e], d = ei[N_EDGES + e];
    float nrm = g_dinv[s] * g_dinv[d];
    float4 v = *(const float4*)(srcbuf + (long long)s * HID + lane * 4);
    red_add_v4(dstbuf + (long long)d * HID + lane * 4,
               nrm * v.x, nrm * v.y, nrm * v.z, nrm * v.w);
}

// pool: relu(bn3(out3)) summed per graph; one warp per node
__global__ void k_pool(const float* __restrict__ h, const int* __restrict__ batch) {
    long long t = (long long)blockIdx.x * blockDim.x + threadIdx.x;
    int node = (int)(t >> 5);
    if (node >= N_NODES) return;
    int lane = threadIdx.x & 31;
    int g = batch[node];
    float4 v  = *(const float4*)(h + (long long)node * HID + lane * 4);
    float4 s4 = *(const float4*)(g_s + 2 * HID + lane * 4);
    float4 t4 = *(const float4*)(g_t + 2 * HID + lane * 4);
    float a = fmaxf(v.x * s4.x + t4.x, 0.0f);
    float b = fmaxf(v.y * s4.y + t4.y, 0.0f);
    float c = fmaxf(v.z * s4.z + t4.z, 0.0f);
    float dd = fmaxf(v.w * s4.w + t4.w, 0.0f);
    red_add_v4(g_pool + (long long)g * HID + lane * 4, a, b, c, dd);
}

// final MLP head: 8 graphs per block (1 warp per graph)
__global__ void k_mlp(const float* __restrict__ Wc1, const float* __restrict__ bc1,
                      const float* __restrict__ Wc2, const float* __restrict__ bc2,
                      float* __restrict__ out) {
    __shared__ float W1s[128 * 64];
    __shared__ float w2s[64];
    __shared__ float b1s[64];
    __shared__ float msm[8][128];
    int tid = threadIdx.x;
    for (int i = tid; i < 128 * 64; i += 256) W1s[i] = Wc1[i];
    if (tid < 64) { w2s[tid] = Wc2[tid]; b1s[tid] = bc1[tid]; }
    __syncthreads();
    int w = tid >> 5, lane = tid & 31;
    int g = blockIdx.x * 8 + w;
    float inv = 1.0f / fmaxf(g_cnt[g], 1.0f);
    float4 v = *(const float4*)(g_pool + (long long)g * HID + lane * 4);
    *(float4*)(&msm[w][lane * 4]) = make_float4(v.x * inv, v.y * inv, v.z * inv, v.w * inv);
    __syncwarp();
    float h0 = b1s[lane], h1 = b1s[lane + 32];
#pragma unroll 8
    for (int i = 0; i < 128; i++) {
        float m = msm[w][i];
        h0 += m * W1s[i * 64 + lane];
        h1 += m * W1s[i * 64 + lane + 32];
    }
    h0 = fmaxf(h0, 0.0f);
    h1 = fmaxf(h1, 0.0f);
    float p = h0 * w2s[lane] + h1 * w2s[lane + 32];
#pragma unroll
    for (int off = 16; off > 0; off >>= 1) p += __shfl_down_sync(0xffffffffu, p, off);
    if (lane == 0) out[g] = p + bc2[0];
}

// ---------------- launch ----------------
extern "C" void kernel_launch(void* const* d_in, const int* in_sizes, int n_in,
                              void* d_out, int out_size) {
    const float* x     = (const float*)d_in[0];
    const int*   ei    = (const int*)d_in[1];
    const int*   batch = (const int*)d_in[2];
    const float* W1 = (const float*)d_in[3];
    const float* b1 = (const float*)d_in[4];
    const float* ga1 = (const float*)d_in[5];
    const float* be1 = (const float*)d_in[6];
    const float* rm1 = (const float*)d_in[7];
    const float* rv1 = (const float*)d_in[8];
    const float* W2 = (const float*)d_in[9];
    const float* b2 = (const float*)d_in[10];
    const float* ga2 = (const float*)d_in[11];
    const float* be2 = (const float*)d_in[12];
    const float* rm2 = (const float*)d_in[13];
    const float* rv2 = (const float*)d_in[14];
    const float* W3 = (const float*)d_in[15];
    const float* b3 = (const float*)d_in[16];
    const float* ga3 = (const float*)d_in[17];
    const float* be3 = (const float*)d_in[18];
    const float* rm3 = (const float*)d_in[19];
    const float* rv3 = (const float*)d_in[20];
    const float* Wc1 = (const float*)d_in[21];
    const float* bc1 = (const float*)d_in[22];
    const float* Wc2 = (const float*)d_in[23];
    const float* bc2 = (const float*)d_in[24];
    float* out = (float*)d_out;

    float *p_s = nullptr, *p_t = nullptr;
    cudaGetSymbolAddress((void**)&p_s, g_s);
    cudaGetSymbolAddress((void**)&p_t, g_t);
    float *p_h1 = nullptr, *p_hw = nullptr, *p_out = nullptr;
    cudaGetSymbolAddress((void**)&p_h1, g_h1);
    cudaGetSymbolAddress((void**)&p_hw, g_hw);
    cudaGetSymbolAddress((void**)&p_out, g_out);

    cudaFuncSetAttribute(k_gemm_mma<false>, cudaFuncAttributeMaxDynamicSharedMemorySize, SM_TOT);
    cudaFuncSetAttribute(k_gemm_mma<true>,  cudaFuncAttributeMaxDynamicSharedMemorySize, SM_TOT);

    k_zero<<<(N_GRAPHS * HID) / 256, 256>>>();
    k_bnprep<<<1, 128>>>(b1, ga1, be1, rm1, rv1, b2, ga2, be2, rm2, rv2,
                         b3, ga3, be3, rm3, rv3);
    k_deg<<<(N_EDGES + 255) / 256, 256>>>(ei);
    k_node_prep<<<(N_NODES + 255) / 256, 256>>>(x, batch);
    k_scatter8<<<(N_EDGES + 255) / 256, 256>>>(ei);
    k_gemm1<<<N_NODES / 32, 128>>>(W1);

    // layer 2: hW2 = h1 @ W2 -> g_hw ; g_out = dinv^2 * hW2
    k_gemm_mma<false><<<148, 256, SM_TOT>>>(p_h1, W2, nullptr, nullptr, p_hw, p_out);
    k_scatter128<<<(int)(((long long)N_EDGES * 32 + 255) / 256), 256>>>(p_hw, p_out, ei);
    // layer 3: input = act2(g_out); hW3 -> g_hw ; g_h1 = dinv^2 * hW3
    k_gemm_mma<true><<<148, 256, SM_TOT>>>(p_out, W3, p_s + HID, p_t + HID, p_hw, p_h1);
    k_scatter128<<<(int)(((long long)N_EDGES * 32 + 255) / 256), 256>>>(p_hw, p_h1, ei);

    k_pool<<<(int)(((long long)N_NODES * 32 + 255) / 256), 256>>>(p_h1, batch);
    k_mlp<<<N_GRAPHS / 8, 256>>>(Wc1, bc1, Wc2, bc2, out);
}

// round 10
// speedup vs baseline: 1.7119x; 1.4710x over previous
#include <cuda_runtime.h>
#include <cuda_bf16.h>
#include <cstdint>

#define N_NODES  1000000
#define N_EDGES  4000000
#define N_GRAPHS 32768
#define HID      128
#define BN_EPS   1e-5f

#define NTILES   7813                       // ceil(1e6/128)
#define N_PAD    (NTILES * 128)             // 1000064
#define NSCAN_B  977                        // ceil(1e6/1024)

// ---------------- scratch (device globals: no allocations allowed) ----------------
__device__ float g_dinv[N_NODES];          // rsqrt(deg+1)
__device__ int   g_degi[N_NODES];          // int in-degree (by dst, no self loop)
__device__ int   g_off [N_NODES];          // CSR offsets (exclusive scan of degi)
__device__ int   g_cur [N_NODES];          // binning cursors
__device__ int   g_csr [N_EDGES];          // src ids grouped by dst
__device__ int   g_bsum[1024];             // scan block sums
__device__ float g_xpad[N_NODES * 8];      // x padded to 8 cols
__device__ float g_agg0[N_NODES * 8];      // A @ x   (7 used cols)
__device__ float g_h1 [N_PAD * HID];       // h1 (activated)
__device__ float g_hw [N_PAD * HID];       // hW scratch (gather source)
__device__ float g_out[N_PAD * HID];       // aggregated layer-2 (raw)
__device__ float g_pool[N_GRAPHS * HID];   // pooled sums
__device__ float g_cnt [N_GRAPHS];         // nodes per graph
__device__ float g_s[3 * HID];             // folded BN scale  per layer
__device__ float g_t[3 * HID];             // folded BN shift (includes bias) per layer

// ---------------- helpers ----------------
__device__ __forceinline__ void red_add_v4(float* addr, float x, float y, float z, float w) {
    asm volatile("red.global.add.v4.f32 [%0], {%1,%2,%3,%4};"
                 :: "l"(addr), "f"(x), "f"(y), "f"(z), "f"(w) : "memory");
}
__device__ __forceinline__ uint32_t smem_u32(const void* p) {
    uint32_t a;
    asm("{ .reg .u64 t; cvta.to.shared.u64 t, %1; cvt.u32.u64 %0, t; }" : "=r"(a) : "l"(p));
    return a;
}
// split fp32 pair -> bf16x2 hi (returned), bf16x2 lo (out-param); elem a in low half
__device__ __forceinline__ uint32_t pack_hilo(float a, float b, uint32_t& lo) {
    __nv_bfloat16 ah = __float2bfloat16(a);
    __nv_bfloat16 bh = __float2bfloat16(b);
    __nv_bfloat16 al = __float2bfloat16(a - __bfloat162float(ah));
    __nv_bfloat16 bl = __float2bfloat16(b - __bfloat162float(bh));
    lo = ((uint32_t)__bfloat16_as_ushort(bl) << 16) | __bfloat16_as_ushort(al);
    return ((uint32_t)__bfloat16_as_ushort(bh) << 16) | __bfloat16_as_ushort(ah);
}
__device__ __forceinline__ void ldsm4(uint32_t* r, uint32_t addr) {
    asm volatile("ldmatrix.sync.aligned.m8n8.x4.shared.b16 {%0,%1,%2,%3}, [%4];"
                 : "=r"(r[0]), "=r"(r[1]), "=r"(r[2]), "=r"(r[3]) : "r"(addr));
}
__device__ __forceinline__ void mma_bf16(float* d, const uint32_t* a, uint32_t b0, uint32_t b1) {
    asm volatile(
        "mma.sync.aligned.m16n8k16.row.col.f32.bf16.bf16.f32 "
        "{%0,%1,%2,%3}, {%4,%5,%6,%7}, {%8,%9}, {%0,%1,%2,%3};"
        : "+f"(d[0]), "+f"(d[1]), "+f"(d[2]), "+f"(d[3])
        : "r"(a[0]), "r"(a[1]), "r"(a[2]), "r"(a[3]), "r"(b0), "r"(b1));
}

// padded bf16 tile layout: 128 rows x 136 bf16 (272 B/row; rows shift 4 banks -> LDSM conflict-free)
#define ROWB   136
#define TILE_B (128 * ROWB * 2)             // 34816 bytes
#define SM_WHI 0
#define SM_WLO (TILE_B)
#define SM_AHI (2 * TILE_B)
#define SM_ALO (3 * TILE_B)
#define SM_TOT (4 * TILE_B)

// ---------------- init / prep ----------------
__global__ void k_zero() {
    int i = blockIdx.x * blockDim.x + threadIdx.x;         // grid covers N_GRAPHS*HID
    g_pool[i] = 0.0f;
    if (i < N_NODES)  { g_degi[i] = 0; g_cur[i] = 0; }
    if (i < N_GRAPHS) g_cnt[i]  = 0.0f;
}

__global__ void k_bnprep(const float* __restrict__ b1, const float* __restrict__ ga1,
                         const float* __restrict__ be1, const float* __restrict__ rm1,
                         const float* __restrict__ rv1,
                         const float* __restrict__ b2, const float* __restrict__ ga2,
                         const float* __restrict__ be2, const float* __restrict__ rm2,
                         const float* __restrict__ rv2,
                         const float* __restrict__ b3, const float* __restrict__ ga3,
                         const float* __restrict__ be3, const float* __restrict__ rm3,
                         const float* __restrict__ rv3) {
    int j = threadIdx.x;
    if (j >= HID) return;
    const float* B[3]  = {b1, b2, b3};
    const float* G[3]  = {ga1, ga2, ga3};
    const float* BE[3] = {be1, be2, be3};
    const float* RM[3] = {rm1, rm2, rm3};
    const float* RV[3] = {rv1, rv2, rv3};
    for (int l = 0; l < 3; l++) {
        float s = G[l][j] * rsqrtf(RV[l][j] + BN_EPS);
        g_s[l * HID + j] = s;
        g_t[l * HID + j] = (B[l][j] - RM[l][j]) * s + BE[l][j];
    }
}

__global__ void k_deg(const int* __restrict__ ei) {
    int e = blockIdx.x * blockDim.x + threadIdx.x;
    if (e >= N_EDGES) return;
    atomicAdd(&g_degi[ei[N_EDGES + e]], 1);
}

// ---- 3-kernel exclusive scan of g_degi -> g_off ----
__global__ void k_scan1() {
    __shared__ int sd[256];
    const int b = blockIdx.x, t = threadIdx.x;
    const int base = b * 1024 + t * 4;
    int v[4];
#pragma unroll
    for (int j = 0; j < 4; j++) v[j] = (base + j < N_NODES) ? g_degi[base + j] : 0;
    const int s = v[0] + v[1] + v[2] + v[3];
    sd[t] = s;
    __syncthreads();
    for (int off = 1; off < 256; off <<= 1) {
        int x = (t >= off) ? sd[t - off] : 0;
        __syncthreads();
        sd[t] += x;
        __syncthreads();
    }
    int run = sd[t] - s;                   // exclusive within block
#pragma unroll
    for (int j = 0; j < 4; j++) {
        if (base + j < N_NODES) g_off[base + j] = run;
        run += v[j];
    }
    if (t == 255) g_bsum[b] = sd[255];
}
__global__ void k_scan2() {
    __shared__ int sd[1024];
    const int t = threadIdx.x;
    const int v = (t < NSCAN_B) ? g_bsum[t] : 0;
    sd[t] = v;
    __syncthreads();
    for (int off = 1; off < 1024; off <<= 1) {
        int x = (t >= off) ? sd[t - off] : 0;
        __syncthreads();
        sd[t] += x;
        __syncthreads();
    }
    if (t < NSCAN_B) g_bsum[t] = sd[t] - v;   // exclusive
}
__global__ void k_scan3() {
    const int b = blockIdx.x, t = threadIdx.x;
    const int add = g_bsum[b];
    const int base = b * 1024 + t * 4;
#pragma unroll
    for (int j = 0; j < 4; j++)
        if (base + j < N_NODES) g_off[base + j] += add;
}

// bin edges by dst
__global__ void k_bin(const int* __restrict__ ei) {
    int e = blockIdx.x * blockDim.x + threadIdx.x;
    if (e >= N_EDGES) return;
    const int d = ei[N_EDGES + e];
    const int pos = g_off[d] + atomicAdd(&g_cur[d], 1);
    g_csr[pos] = ei[e];
}

__global__ void k_node_prep(const float* __restrict__ x, const int* __restrict__ batch) {
    int i = blockIdx.x * blockDim.x + threadIdx.x;
    if (i >= N_NODES) return;
    float di = rsqrtf((float)g_degi[i] + 1.0f);   // + self-loop
    g_dinv[i] = di;
    float di2 = di * di;
    const float* xr = x + (long long)i * 7;
    float xv[8];
#pragma unroll
    for (int j = 0; j < 7; j++) xv[j] = xr[j];
    xv[7] = 0.0f;
    float4* xp = (float4*)(g_xpad + i * 8);
    float4* ag = (float4*)(g_agg0 + i * 8);
    xp[0] = make_float4(xv[0], xv[1], xv[2], xv[3]);
    xp[1] = make_float4(xv[4], xv[5], xv[6], xv[7]);
    ag[0] = make_float4(di2 * xv[0], di2 * xv[1], di2 * xv[2], di2 * xv[3]);
    ag[1] = make_float4(di2 * xv[4], di2 * xv[5], di2 * xv[6], di2 * xv[7]);
    atomicAdd(&g_cnt[batch[i]], 1.0f);
}

// layer-1 edge scatter on 8-wide x (atomics fine at this width)
__global__ void k_scatter8(const int* __restrict__ ei) {
    int e = blockIdx.x * blockDim.x + threadIdx.x;
    if (e >= N_EDGES) return;
    int s = ei[e], d = ei[N_EDGES + e];
    float nrm = g_dinv[s] * g_dinv[d];
    const float4* sp = (const float4*)(g_xpad + s * 8);
    float4 a = sp[0], b = sp[1];
    red_add_v4(g_agg0 + d * 8,     nrm * a.x, nrm * a.y, nrm * a.z, nrm * a.w);
    red_add_v4(g_agg0 + d * 8 + 4, nrm * b.x, nrm * b.y, nrm * b.z, nrm * b.w);
}

// h1 = relu( (agg0 @ W1) * s1 + t1 )
__global__ void k_gemm1(const float* __restrict__ W1) {
    __shared__ float Wsm[7 * 128];
    __shared__ float rsm[32 * 8];
    int j = threadIdx.x;
#pragma unroll
    for (int k = 0; k < 7; k++) Wsm[k * 128 + j] = W1[k * 128 + j];
    float sj = g_s[j], tj = g_t[j];
    int base = blockIdx.x * 32;
    rsm[j]       = g_agg0[base * 8 + j];
    rsm[j + 128] = g_agg0[base * 8 + j + 128];
    __syncthreads();
#pragma unroll 4
    for (int n = 0; n < 32; n++) {
        float acc = 0.0f;
#pragma unroll
        for (int k = 0; k < 7; k++) acc += rsm[n * 8 + k] * Wsm[k * 128 + j];
        g_h1[(long long)(base + n) * HID + j] = fmaxf(acc * sj + tj, 0.0f);
    }
}

// ---------- HMMA GEMM: out = act(In) @ W  (single output now) ----------
template <bool ACT>
__global__ void __launch_bounds__(256, 1)
k_gemm_mma(const float* __restrict__ In, const float* __restrict__ Wg,
           const float* __restrict__ sv, const float* __restrict__ tv,
           float* __restrict__ out1) {
    extern __shared__ char smem[];
    const uint32_t sb = smem_u32(smem);
    const int tid  = threadIdx.x;
    const int wid  = tid >> 5, lane = tid & 31;
    const int mw   = wid >> 1;
    const int nw   = wid & 1;

    // ---- W transpose + hi/lo split into padded SMEM (once per CTA) ----
    {
        const int n  = tid >> 1;
        const int kh = (tid & 1) * 64;
#pragma unroll
        for (int j = 0; j < 8; j++) {
            uint32_t hi[4], lo[4];
#pragma unroll
            for (int q = 0; q < 4; q++) {
                float a = Wg[(kh + j * 8 + q * 2    ) * 128 + n];
                float b = Wg[(kh + j * 8 + q * 2 + 1) * 128 + n];
                hi[q] = pack_hilo(a, b, lo[q]);
            }
            const int off = (n * ROWB + kh + j * 8) * 2;
            *(uint4*)(smem + SM_WHI + off) = make_uint4(hi[0], hi[1], hi[2], hi[3]);
            *(uint4*)(smem + SM_WLO + off) = make_uint4(lo[0], lo[1], lo[2], lo[3]);
        }
    }
    __syncthreads();

    const int a_row  = (lane & 15);
    const int a_koff = (lane >> 4) * 8;
    const int b_noff = (lane & 7) + ((lane >> 4) & 1) * 8;
    const int b_koff = ((lane >> 3) & 1) * 8;

    for (int tile = blockIdx.x; tile < NTILES; tile += gridDim.x) {
        const long long base = (long long)tile * 128;

        // ---- stage A: fp32 -> (ACT) -> bf16 hi/lo into padded SMEM ----
        {
            const int r  = tid >> 1;
            const int kh = (tid & 1) * 64;
            const long long row = base + r;
            const bool valid = (row < N_NODES);
            const float* ap = In + row * HID + kh;
#pragma unroll
            for (int j = 0; j < 8; j++) {
                float4 v0, v1;
                if (valid) {
                    v0 = *(const float4*)(ap + j * 8);
                    v1 = *(const float4*)(ap + j * 8 + 4);
                    if (ACT) {
                        float4 s0 = *(const float4*)(sv + kh + j * 8);
                        float4 t0 = *(const float4*)(tv + kh + j * 8);
                        float4 s1 = *(const float4*)(sv + kh + j * 8 + 4);
                        float4 t1 = *(const float4*)(tv + kh + j * 8 + 4);
                        v0.x = fmaxf(v0.x * s0.x + t0.x, 0.0f);
                        v0.y = fmaxf(v0.y * s0.y + t0.y, 0.0f);
                        v0.z = fmaxf(v0.z * s0.z + t0.z, 0.0f);
                        v0.w = fmaxf(v0.w * s0.w + t0.w, 0.0f);
                        v1.x = fmaxf(v1.x * s1.x + t1.x, 0.0f);
                        v1.y = fmaxf(v1.y * s1.y + t1.y, 0.0f);
                        v1.z = fmaxf(v1.z * s1.z + t1.z, 0.0f);
                        v1.w = fmaxf(v1.w * s1.w + t1.w, 0.0f);
                    }
                } else {
                    v0 = make_float4(0.f, 0.f, 0.f, 0.f);
                    v1 = v0;
                }
                uint4 H, L;
                H.x = pack_hilo(v0.x, v0.y, L.x);
                H.y = pack_hilo(v0.z, v0.w, L.y);
                H.z = pack_hilo(v1.x, v1.y, L.z);
                H.w = pack_hilo(v1.z, v1.w, L.w);
                const int off = (r * ROWB + kh + j * 8) * 2;
                *(uint4*)(smem + SM_AHI + off) = H;
                *(uint4*)(smem + SM_ALO + off) = L;
            }
        }
        __syncthreads();

        // ---- mainloop ----
        float acc[2][8][4];
#pragma unroll
        for (int mf = 0; mf < 2; mf++)
#pragma unroll
            for (int nf = 0; nf < 8; nf++)
#pragma unroll
                for (int q = 0; q < 4; q++) acc[mf][nf][q] = 0.0f;

#pragma unroll
        for (int k = 0; k < 8; k++) {
            uint32_t Bh[4][4], Bl[4][4];
#pragma unroll
            for (int nf2 = 0; nf2 < 4; nf2++) {
                const int n    = nw * 64 + nf2 * 16 + b_noff;
                const uint32_t ad = sb + SM_WHI + (uint32_t)((n * ROWB + k * 16 + b_koff) * 2);
                ldsm4(Bh[nf2], ad);
                ldsm4(Bl[nf2], ad + (SM_WLO - SM_WHI));
            }
            uint32_t Ah[2][4], Al[2][4];
#pragma unroll
            for (int mf = 0; mf < 2; mf++) {
                const int rr = mw * 32 + mf * 16 + a_row;
                const uint32_t ad = sb + SM_AHI + (uint32_t)((rr * ROWB + k * 16 + a_koff) * 2);
                ldsm4(Ah[mf], ad);
                ldsm4(Al[mf], ad + (SM_ALO - SM_AHI));
            }
#pragma unroll
            for (int mf = 0; mf < 2; mf++)
#pragma unroll
                for (int nf2 = 0; nf2 < 4; nf2++) {
                    mma_bf16(acc[mf][2 * nf2],     Ah[mf], Bh[nf2][0], Bh[nf2][1]);
                    mma_bf16(acc[mf][2 * nf2],     Al[mf], Bh[nf2][0], Bh[nf2][1]);
                    mma_bf16(acc[mf][2 * nf2],     Ah[mf], Bl[nf2][0], Bl[nf2][1]);
                    mma_bf16(acc[mf][2 * nf2 + 1], Ah[mf], Bh[nf2][2], Bh[nf2][3]);
                    mma_bf16(acc[mf][2 * nf2 + 1], Al[mf], Bh[nf2][2], Bh[nf2][3]);
                    mma_bf16(acc[mf][2 * nf2 + 1], Ah[mf], Bl[nf2][2], Bl[nf2][3]);
                }
        }
        __syncthreads();

        // ---- epilogue: write hW only ----
#pragma unroll
        for (int mf = 0; mf < 2; mf++) {
            const long long r0 = base + mw * 32 + mf * 16 + (lane >> 2);
            const long long r1 = r0 + 8;
            float* o1a = out1 + r0 * HID;
            float* o1b = out1 + r1 * HID;
            const int cb = nw * 64 + (lane & 3) * 2;
#pragma unroll
            for (int nf = 0; nf < 8; nf++) {
                const int c = cb + nf * 8;
                *(float2*)(o1a + c) = make_float2(acc[mf][nf][0], acc[mf][nf][1]);
                *(float2*)(o1b + c) = make_float2(acc[mf][nf][2], acc[mf][nf][3]);
            }
        }
    }
}

// ---------- CSR pull-aggregation: out[d] = dinv_d^2*hw[d] + sum norm*hw[s] ----------
// One warp per dst node; no fp atomics (except POOL's per-graph red_add).
// POOL: apply bn3+relu and accumulate into g_pool instead of writing out.
template <bool POOL>
__global__ void k_agg(const float* __restrict__ hw, float* __restrict__ outbuf,
                      const int* __restrict__ batch) {
    long long t = (long long)blockIdx.x * blockDim.x + threadIdx.x;
    const int node = (int)(t >> 5);
    if (node >= N_NODES) return;
    const int lane = threadIdx.x & 31;

    const float dd  = g_dinv[node];
    const float di2 = dd * dd;
    float4 acc = *(const float4*)(hw + (long long)node * HID + lane * 4);
    acc.x *= di2; acc.y *= di2; acc.z *= di2; acc.w *= di2;

    const int start = g_off[node];
    const int deg   = g_degi[node];
    int i = 0;
    for (; i + 1 < deg; i += 2) {
        const int s0 = g_csr[start + i];
        const int s1 = g_csr[start + i + 1];
        const float n0 = dd * g_dinv[s0];
        const float n1 = dd * g_dinv[s1];
        float4 v0 = *(const float4*)(hw + (long long)s0 * HID + lane * 4);
        float4 v1 = *(const float4*)(hw + (long long)s1 * HID + lane * 4);
        acc.x += n0 * v0.x + n1 * v1.x;
        acc.y += n0 * v0.y + n1 * v1.y;
        acc.z += n0 * v0.z + n1 * v1.z;
        acc.w += n0 * v0.w + n1 * v1.w;
    }
    if (i < deg) {
        const int s0 = g_csr[start + i];
        const float n0 = dd * g_dinv[s0];
        float4 v0 = *(const float4*)(hw + (long long)s0 * HID + lane * 4);
        acc.x += n0 * v0.x;
        acc.y += n0 * v0.y;
        acc.z += n0 * v0.z;
        acc.w += n0 * v0.w;
    }

    if (POOL) {
        float4 s4 = *(const float4*)(g_s + 2 * HID + lane * 4);
        float4 t4 = *(const float4*)(g_t + 2 * HID + lane * 4);
        float a = fmaxf(acc.x * s4.x + t4.x, 0.0f);
        float b = fmaxf(acc.y * s4.y + t4.y, 0.0f);
        float c = fmaxf(acc.z * s4.z + t4.z, 0.0f);
        float d = fmaxf(acc.w * s4.w + t4.w, 0.0f);
        red_add_v4(g_pool + (long long)batch[node] * HID + lane * 4, a, b, c, d);
    } else {
        *(float4*)(outbuf + (long long)node * HID + lane * 4) = acc;
    }
}

// final MLP head: 8 graphs per block (1 warp per graph)
__global__ void k_mlp(const float* __restrict__ Wc1, const float* __restrict__ bc1,
                      const float* __restrict__ Wc2, const float* __restrict__ bc2,
                      float* __restrict__ out) {
    __shared__ float W1s[128 * 64];
    __shared__ float w2s[64];
    __shared__ float b1s[64];
    __shared__ float msm[8][128];
    int tid = threadIdx.x;
    for (int i = tid; i < 128 * 64; i += 256) W1s[i] = Wc1[i];
    if (tid < 64) { w2s[tid] = Wc2[tid]; b1s[tid] = bc1[tid]; }
    __syncthreads();
    int w = tid >> 5, lane = tid & 31;
    int g = blockIdx.x * 8 + w;
    float inv = 1.0f / fmaxf(g_cnt[g], 1.0f);
    float4 v = *(const float4*)(g_pool + (long long)g * HID + lane * 4);
    *(float4*)(&msm[w][lane * 4]) = make_float4(v.x * inv, v.y * inv, v.z * inv, v.w * inv);
    __syncwarp();
    float h0 = b1s[lane], h1 = b1s[lane + 32];
#pragma unroll 8
    for (int i = 0; i < 128; i++) {
        float m = msm[w][i];
        h0 += m * W1s[i * 64 + lane];
        h1 += m * W1s[i * 64 + lane + 32];
    }
    h0 = fmaxf(h0, 0.0f);
    h1 = fmaxf(h1, 0.0f);
    float p = h0 * w2s[lane] + h1 * w2s[lane + 32];
#pragma unroll
    for (int off = 16; off > 0; off >>= 1) p += __shfl_down_sync(0xffffffffu, p, off);
    if (lane == 0) out[g] = p + bc2[0];
}

// ---------------- launch ----------------
extern "C" void kernel_launch(void* const* d_in, const int* in_sizes, int n_in,
                              void* d_out, int out_size) {
    const float* x     = (const float*)d_in[0];
    const int*   ei    = (const int*)d_in[1];
    const int*   batch = (const int*)d_in[2];
    const float* W1 = (const float*)d_in[3];
    const float* b1 = (const float*)d_in[4];
    const float* ga1 = (const float*)d_in[5];
    const float* be1 = (const float*)d_in[6];
    const float* rm1 = (const float*)d_in[7];
    const float* rv1 = (const float*)d_in[8];
    const float* W2 = (const float*)d_in[9];
    const float* b2 = (const float*)d_in[10];
    const float* ga2 = (const float*)d_in[11];
    const float* be2 = (const float*)d_in[12];
    const float* rm2 = (const float*)d_in[13];
    const float* rv2 = (const float*)d_in[14];
    const float* W3 = (const float*)d_in[15];
    const float* b3 = (const float*)d_in[16];
    const float* ga3 = (const float*)d_in[17];
    const float* be3 = (const float*)d_in[18];
    const float* rm3 = (const float*)d_in[19];
    const float* rv3 = (const float*)d_in[20];
    const float* Wc1 = (const float*)d_in[21];
    const float* bc1 = (const float*)d_in[22];
    const float* Wc2 = (const float*)d_in[23];
    const float* bc2 = (const float*)d_in[24];
    float* out = (float*)d_out;

    float *p_s = nullptr, *p_t = nullptr;
    cudaGetSymbolAddress((void**)&p_s, g_s);
    cudaGetSymbolAddress((void**)&p_t, g_t);
    float *p_h1 = nullptr, *p_hw = nullptr, *p_out = nullptr;
    cudaGetSymbolAddress((void**)&p_h1, g_h1);
    cudaGetSymbolAddress((void**)&p_hw, g_hw);
    cudaGetSymbolAddress((void**)&p_out, g_out);

    cudaFuncSetAttribute(k_gemm_mma<false>, cudaFuncAttributeMaxDynamicSharedMemorySize, SM_TOT);
    cudaFuncSetAttribute(k_gemm_mma<true>,  cudaFuncAttributeMaxDynamicSharedMemorySize, SM_TOT);

    k_zero<<<(N_GRAPHS * HID) / 256, 256>>>();
    k_bnprep<<<1, 128>>>(b1, ga1, be1, rm1, rv1, b2, ga2, be2, rm2, rv2,
                         b3, ga3, be3, rm3, rv3);
    k_deg<<<(N_EDGES + 255) / 256, 256>>>(ei);
    // CSR build
    k_scan1<<<NSCAN_B, 256>>>();
    k_scan2<<<1, 1024>>>();
    k_scan3<<<NSCAN_B, 256>>>();
    k_bin<<<(N_EDGES + 255) / 256, 256>>>(ei);

    k_node_prep<<<(N_NODES + 255) / 256, 256>>>(x, batch);
    k_scatter8<<<(N_EDGES + 255) / 256, 256>>>(ei);
    k_gemm1<<<N_NODES / 32, 128>>>(W1);

    const int agg_grid = (int)(((long long)N_NODES * 32 + 255) / 256);
    // layer 2: hw = h1 @ W2 ; g_out = A_norm * hw (pull)
    k_gemm_mma<false><<<148, 256, SM_TOT>>>(p_h1, W2, nullptr, nullptr, p_hw);
    k_agg<false><<<agg_grid, 256>>>(p_hw, p_out, batch);
    // layer 3: hw = act2(g_out) @ W3 ; pool += relu(bn3(A_norm * hw)) (pull, fused)
    k_gemm_mma<true><<<148, 256, SM_TOT>>>(p_out, W3, p_s + HID, p_t + HID, p_hw);
    k_agg<true><<<agg_grid, 256>>>(p_hw, nullptr, batch);

    k_mlp<<<N_GRAPHS / 8, 256>>>(Wc1, bc1, Wc2, bc2, out);
}

// round 11
// speedup vs baseline: 1.7851x; 1.0427x over previous
#include <cuda_runtime.h>
#include <cuda_bf16.h>
#include <cstdint>

#define N_NODES  1000000
#define N_EDGES  4000000
#define N_GRAPHS 32768
#define HID      128
#define BN_EPS   1e-5f

#define NTILES   7813                       // ceil(1e6/128)
#define N_PAD    (NTILES * 128)             // 1000064
#define NSCAN_B  977                        // ceil(1e6/1024)

// ---------------- scratch (device globals: no allocations allowed) ----------------
__device__ float g_dinv[N_NODES];          // rsqrt(deg+1)
__device__ int   g_degi[N_NODES];          // int in-degree (by dst, no self loop)
__device__ int   g_off [N_NODES];          // CSR offsets (exclusive scan of degi)
__device__ int   g_cur [N_NODES];          // binning cursors
__device__ int   g_csr [N_EDGES];          // src ids grouped by dst
__device__ int   g_bsum[1024];             // scan block sums
__device__ float g_xpad[N_NODES * 8];      // x padded to 8 cols
__device__ float g_agg0[N_NODES * 8];      // A @ x   (7 used cols)
__device__ float g_h1 [N_PAD * HID];       // h1 (activated)
__device__ float g_hw [N_PAD * HID];       // hW scratch (gather source)
__device__ float g_out[N_PAD * HID];       // aggregated layer-2 (raw)
__device__ float g_pool[N_GRAPHS * HID];   // pooled sums
__device__ float g_cnt [N_GRAPHS];         // nodes per graph
__device__ float g_s[3 * HID];             // folded BN scale  per layer
__device__ float g_t[3 * HID];             // folded BN shift (includes bias) per layer

// ---------------- helpers ----------------
__device__ __forceinline__ void red_add_v4(float* addr, float x, float y, float z, float w) {
    asm volatile("red.global.add.v4.f32 [%0], {%1,%2,%3,%4};"
                 :: "l"(addr), "f"(x), "f"(y), "f"(z), "f"(w) : "memory");
}
__device__ __forceinline__ uint32_t smem_u32(const void* p) {
    uint32_t a;
    asm("{ .reg .u64 t; cvta.to.shared.u64 t, %1; cvt.u32.u64 %0, t; }" : "=r"(a) : "l"(p));
    return a;
}
// split fp32 pair -> bf16x2 hi (returned), bf16x2 lo (out-param); elem a in low half
__device__ __forceinline__ uint32_t pack_hilo(float a, float b, uint32_t& lo) {
    __nv_bfloat16 ah = __float2bfloat16(a);
    __nv_bfloat16 bh = __float2bfloat16(b);
    __nv_bfloat16 al = __float2bfloat16(a - __bfloat162float(ah));
    __nv_bfloat16 bl = __float2bfloat16(b - __bfloat162float(bh));
    lo = ((uint32_t)__bfloat16_as_ushort(bl) << 16) | __bfloat16_as_ushort(al);
    return ((uint32_t)__bfloat16_as_ushort(bh) << 16) | __bfloat16_as_ushort(ah);
}
__device__ __forceinline__ void ldsm4(uint32_t* r, uint32_t addr) {
    asm volatile("ldmatrix.sync.aligned.m8n8.x4.shared.b16 {%0,%1,%2,%3}, [%4];"
                 : "=r"(r[0]), "=r"(r[1]), "=r"(r[2]), "=r"(r[3]) : "r"(addr));
}
__device__ __forceinline__ void mma_bf16(float* d, const uint32_t* a, uint32_t b0, uint32_t b1) {
    asm volatile(
        "mma.sync.aligned.m16n8k16.row.col.f32.bf16.bf16.f32 "
        "{%0,%1,%2,%3}, {%4,%5,%6,%7}, {%8,%9}, {%0,%1,%2,%3};"
        : "+f"(d[0]), "+f"(d[1]), "+f"(d[2]), "+f"(d[3])
        : "r"(a[0]), "r"(a[1]), "r"(a[2]), "r"(a[3]), "r"(b0), "r"(b1));
}
__device__ __forceinline__ void cp16(uint32_t smem_dst, const void* gmem_src) {
    asm volatile("cp.async.cg.shared.global [%0], [%1], 16;"
                 :: "r"(smem_dst), "l"(gmem_src) : "memory");
}
#define CP_COMMIT() asm volatile("cp.async.commit_group;" ::: "memory")
#define CP_WAIT0()  asm volatile("cp.async.wait_group 0;" ::: "memory")

// padded bf16 tile layout: 128 rows x 136 bf16 (272 B/row; rows shift 4 banks -> LDSM conflict-free)
#define ROWB   136
#define TILE_B (128 * ROWB * 2)             // 34816 bytes
// fp32 staging tile: 128 rows x 132 floats (528 B/row -> <=2-way LDS conflicts)
#define SROWF  132
#define STG_B  (128 * SROWF * 4)            // 67584 bytes
#define SM_WHI  0
#define SM_WLO  (TILE_B)
#define SM_AHI  (2 * TILE_B)
#define SM_ALO  (3 * TILE_B)
#define SM_ASTG (4 * TILE_B)
#define SM_TOT  (4 * TILE_B + STG_B)        // 206848 bytes

// ---------------- init / prep ----------------
__global__ void k_zero() {
    int i = blockIdx.x * blockDim.x + threadIdx.x;         // grid covers N_GRAPHS*HID
    g_pool[i] = 0.0f;
    if (i < N_NODES)  { g_degi[i] = 0; g_cur[i] = 0; }
    if (i < N_GRAPHS) g_cnt[i]  = 0.0f;
}

__global__ void k_bnprep(const float* __restrict__ b1, const float* __restrict__ ga1,
                         const float* __restrict__ be1, const float* __restrict__ rm1,
                         const float* __restrict__ rv1,
                         const float* __restrict__ b2, const float* __restrict__ ga2,
                         const float* __restrict__ be2, const float* __restrict__ rm2,
                         const float* __restrict__ rv2,
                         const float* __restrict__ b3, const float* __restrict__ ga3,
                         const float* __restrict__ be3, const float* __restrict__ rm3,
                         const float* __restrict__ rv3) {
    int j = threadIdx.x;
    if (j >= HID) return;
    const float* B[3]  = {b1, b2, b3};
    const float* G[3]  = {ga1, ga2, ga3};
    const float* BE[3] = {be1, be2, be3};
    const float* RM[3] = {rm1, rm2, rm3};
    const float* RV[3] = {rv1, rv2, rv3};
    for (int l = 0; l < 3; l++) {
        float s = G[l][j] * rsqrtf(RV[l][j] + BN_EPS);
        g_s[l * HID + j] = s;
        g_t[l * HID + j] = (B[l][j] - RM[l][j]) * s + BE[l][j];
    }
}

__global__ void k_deg(const int* __restrict__ ei) {
    int e = blockIdx.x * blockDim.x + threadIdx.x;
    if (e >= N_EDGES) return;
    atomicAdd(&g_degi[ei[N_EDGES + e]], 1);
}

// ---- 3-kernel exclusive scan of g_degi -> g_off ----
__global__ void k_scan1() {
    __shared__ int sd[256];
    const int b = blockIdx.x, t = threadIdx.x;
    const int base = b * 1024 + t * 4;
    int v[4];
#pragma unroll
    for (int j = 0; j < 4; j++) v[j] = (base + j < N_NODES) ? g_degi[base + j] : 0;
    const int s = v[0] + v[1] + v[2] + v[3];
    sd[t] = s;
    __syncthreads();
    for (int off = 1; off < 256; off <<= 1) {
        int x = (t >= off) ? sd[t - off] : 0;
        __syncthreads();
        sd[t] += x;
        __syncthreads();
    }
    int run = sd[t] - s;                   // exclusive within block
#pragma unroll
    for (int j = 0; j < 4; j++) {
        if (base + j < N_NODES) g_off[base + j] = run;
        run += v[j];
    }
    if (t == 255) g_bsum[b] = sd[255];
}
__global__ void k_scan2() {
    __shared__ int sd[1024];
    const int t = threadIdx.x;
    const int v = (t < NSCAN_B) ? g_bsum[t] : 0;
    sd[t] = v;
    __syncthreads();
    for (int off = 1; off < 1024; off <<= 1) {
        int x = (t >= off) ? sd[t - off] : 0;
        __syncthreads();
        sd[t] += x;
        __syncthreads();
    }
    if (t < NSCAN_B) g_bsum[t] = sd[t] - v;   // exclusive
}
__global__ void k_scan3() {
    const int b = blockIdx.x, t = threadIdx.x;
    const int add = g_bsum[b];
    const int base = b * 1024 + t * 4;
#pragma unroll
    for (int j = 0; j < 4; j++)
        if (base + j < N_NODES) g_off[base + j] += add;
}

// bin edges by dst
__global__ void k_bin(const int* __restrict__ ei) {
    int e = blockIdx.x * blockDim.x + threadIdx.x;
    if (e >= N_EDGES) return;
    const int d = ei[N_EDGES + e];
    const int pos = g_off[d] + atomicAdd(&g_cur[d], 1);
    g_csr[pos] = ei[e];
}

__global__ void k_node_prep(const float* __restrict__ x, const int* __restrict__ batch) {
    int i = blockIdx.x * blockDim.x + threadIdx.x;
    if (i >= N_NODES) return;
    float di = rsqrtf((float)g_degi[i] + 1.0f);   // + self-loop
    g_dinv[i] = di;
    float di2 = di * di;
    const float* xr = x + (long long)i * 7;
    float xv[8];
#pragma unroll
    for (int j = 0; j < 7; j++) xv[j] = xr[j];
    xv[7] = 0.0f;
    float4* xp = (float4*)(g_xpad + i * 8);
    float4* ag = (float4*)(g_agg0 + i * 8);
    xp[0] = make_float4(xv[0], xv[1], xv[2], xv[3]);
    xp[1] = make_float4(xv[4], xv[5], xv[6], xv[7]);
    ag[0] = make_float4(di2 * xv[0], di2 * xv[1], di2 * xv[2], di2 * xv[3]);
    ag[1] = make_float4(di2 * xv[4], di2 * xv[5], di2 * xv[6], di2 * xv[7]);
    atomicAdd(&g_cnt[batch[i]], 1.0f);
}

// layer-1 edge scatter on 8-wide x (atomics fine at this width)
__global__ void k_scatter8(const int* __restrict__ ei) {
    int e = blockIdx.x * blockDim.x + threadIdx.x;
    if (e >= N_EDGES) return;
    int s = ei[e], d = ei[N_EDGES + e];
    float nrm = g_dinv[s] * g_dinv[d];
    const float4* sp = (const float4*)(g_xpad + s * 8);
    float4 a = sp[0], b = sp[1];
    red_add_v4(g_agg0 + d * 8,     nrm * a.x, nrm * a.y, nrm * a.z, nrm * a.w);
    red_add_v4(g_agg0 + d * 8 + 4, nrm * b.x, nrm * b.y, nrm * b.z, nrm * b.w);
}

// h1 = relu( (agg0 @ W1) * s1 + t1 )
__global__ void k_gemm1(const float* __restrict__ W1) {
    __shared__ float Wsm[7 * 128];
    __shared__ float rsm[32 * 8];
    int j = threadIdx.x;
#pragma unroll
    for (int k = 0; k < 7; k++) Wsm[k * 128 + j] = W1[k * 128 + j];
    float sj = g_s[j], tj = g_t[j];
    int base = blockIdx.x * 32;
    rsm[j]       = g_agg0[base * 8 + j];
    rsm[j + 128] = g_agg0[base * 8 + j + 128];
    __syncthreads();
#pragma unroll 4
    for (int n = 0; n < 32; n++) {
        float acc = 0.0f;
#pragma unroll
        for (int k = 0; k < 7; k++) acc += rsm[n * 8 + k] * Wsm[k * 128 + j];
        g_h1[(long long)(base + n) * HID + j] = fmaxf(acc * sj + tj, 0.0f);
    }
}

// ---------- HMMA GEMM: out = act(In) @ W  (cp.async-pipelined A staging) ----------
// Pad rows (>= N_NODES) carry garbage; their outputs are never consumed downstream.
template <bool ACT>
__global__ void __launch_bounds__(256, 1)
k_gemm_mma(const float* __restrict__ In, const float* __restrict__ Wg,
           const float* __restrict__ sv, const float* __restrict__ tv,
           float* __restrict__ out1) {
    extern __shared__ char smem[];
    const uint32_t sb = smem_u32(smem);
    const int tid  = threadIdx.x;
    const int wid  = tid >> 5, lane = tid & 31;
    const int mw   = wid >> 1;
    const int nw   = wid & 1;

    // ---- W transpose + hi/lo split into padded SMEM (once per CTA) ----
    {
        const int n  = tid >> 1;
        const int kh = (tid & 1) * 64;
#pragma unroll
        for (int j = 0; j < 8; j++) {
            uint32_t hi[4], lo[4];
#pragma unroll
            for (int q = 0; q < 4; q++) {
                float a = Wg[(kh + j * 8 + q * 2    ) * 128 + n];
                float b = Wg[(kh + j * 8 + q * 2 + 1) * 128 + n];
                hi[q] = pack_hilo(a, b, lo[q]);
            }
            const int off = (n * ROWB + kh + j * 8) * 2;
            *(uint4*)(smem + SM_WHI + off) = make_uint4(hi[0], hi[1], hi[2], hi[3]);
            *(uint4*)(smem + SM_WLO + off) = make_uint4(lo[0], lo[1], lo[2], lo[3]);
        }
    }

    // staging assignment: thread -> row rr, half hh (64 floats = 256B)
    const int rr = tid >> 1;
    const int hh = (tid & 1) * 64;
    const uint32_t stg_dst = sb + SM_ASTG + (uint32_t)((rr * SROWF + hh) * 4);

    // prologue: cp.async tile(blockIdx.x)
    {
        const float* src = In + ((long long)blockIdx.x * 128 + rr) * HID + hh;
#pragma unroll
        for (int i = 0; i < 16; i++) cp16(stg_dst + i * 16, src + i * 4);
        CP_COMMIT();
    }
    CP_WAIT0();
    __syncthreads();

    const int a_row  = (lane & 15);
    const int a_koff = (lane >> 4) * 8;
    const int b_noff = (lane & 7) + ((lane >> 4) & 1) * 8;
    const int b_koff = ((lane >> 3) & 1) * 8;

    for (int tile = blockIdx.x; tile < NTILES; tile += gridDim.x) {
        // ---- convert staged fp32 -> (ACT) -> bf16 hi/lo (SMEM -> SMEM) ----
        {
            const float* ap = (const float*)(smem + SM_ASTG) + rr * SROWF + hh;
#pragma unroll
            for (int j = 0; j < 8; j++) {
                float4 v0 = *(const float4*)(ap + j * 8);
                float4 v1 = *(const float4*)(ap + j * 8 + 4);
                if (ACT) {
                    float4 s0 = *(const float4*)(sv + hh + j * 8);
                    float4 t0 = *(const float4*)(tv + hh + j * 8);
                    float4 s1 = *(const float4*)(sv + hh + j * 8 + 4);
                    float4 t1 = *(const float4*)(tv + hh + j * 8 + 4);
                    v0.x = fmaxf(v0.x * s0.x + t0.x, 0.0f);
                    v0.y = fmaxf(v0.y * s0.y + t0.y, 0.0f);
                    v0.z = fmaxf(v0.z * s0.z + t0.z, 0.0f);
                    v0.w = fmaxf(v0.w * s0.w + t0.w, 0.0f);
                    v1.x = fmaxf(v1.x * s1.x + t1.x, 0.0f);
                    v1.y = fmaxf(v1.y * s1.y + t1.y, 0.0f);
                    v1.z = fmaxf(v1.z * s1.z + t1.z, 0.0f);
                    v1.w = fmaxf(v1.w * s1.w + t1.w, 0.0f);
                }
                uint4 H, L;
                H.x = pack_hilo(v0.x, v0.y, L.x);
                H.y = pack_hilo(v0.z, v0.w, L.y);
                H.z = pack_hilo(v1.x, v1.y, L.z);
                H.w = pack_hilo(v1.z, v1.w, L.w);
                const int off = (rr * ROWB + hh + j * 8) * 2;
                *(uint4*)(smem + SM_AHI + off) = H;
                *(uint4*)(smem + SM_ALO + off) = L;
            }
        }
        __syncthreads();          // conversion done; ASTG free, AHI/ALO ready

        // ---- prefetch next tile into ASTG (overlaps MMA) ----
        const int nxt = tile + gridDim.x;
        if (nxt < NTILES) {
            const float* src = In + ((long long)nxt * 128 + rr) * HID + hh;
#pragma unroll
            for (int i = 0; i < 16; i++) cp16(stg_dst + i * 16, src + i * 4);
        }
        CP_COMMIT();

        // ---- mainloop ----
        float acc[2][8][4];
#pragma unroll
        for (int mf = 0; mf < 2; mf++)
#pragma unroll
            for (int nf = 0; nf < 8; nf++)
#pragma unroll
                for (int q = 0; q < 4; q++) acc[mf][nf][q] = 0.0f;

#pragma unroll
        for (int k = 0; k < 8; k++) {
            uint32_t Bh[4][4], Bl[4][4];
#pragma unroll
            for (int nf2 = 0; nf2 < 4; nf2++) {
                const int n    = nw * 64 + nf2 * 16 + b_noff;
                const uint32_t ad = sb + SM_WHI + (uint32_t)((n * ROWB + k * 16 + b_koff) * 2);
                ldsm4(Bh[nf2], ad);
                ldsm4(Bl[nf2], ad + (SM_WLO - SM_WHI));
            }
            uint32_t Ah[2][4], Al[2][4];
#pragma unroll
            for (int mf = 0; mf < 2; mf++) {
                const int r2 = mw * 32 + mf * 16 + a_row;
                const uint32_t ad = sb + SM_AHI + (uint32_t)((r2 * ROWB + k * 16 + a_koff) * 2);
                ldsm4(Ah[mf], ad);
                ldsm4(Al[mf], ad + (SM_ALO - SM_AHI));
            }
#pragma unroll
            for (int mf = 0; mf < 2; mf++)
#pragma unroll
                for (int nf2 = 0; nf2 < 4; nf2++) {
                    mma_bf16(acc[mf][2 * nf2],     Ah[mf], Bh[nf2][0], Bh[nf2][1]);
                    mma_bf16(acc[mf][2 * nf2],     Al[mf], Bh[nf2][0], Bh[nf2][1]);
                    mma_bf16(acc[mf][2 * nf2],     Ah[mf], Bl[nf2][0], Bl[nf2][1]);
                    mma_bf16(acc[mf][2 * nf2 + 1], Ah[mf], Bh[nf2][2], Bh[nf2][3]);
                    mma_bf16(acc[mf][2 * nf2 + 1], Al[mf], Bh[nf2][2], Bh[nf2][3]);
                    mma_bf16(acc[mf][2 * nf2 + 1], Ah[mf], Bl[nf2][2], Bl[nf2][3]);
                }
        }

        // ---- epilogue (register -> gmem; no smem) ----
        const long long base = (long long)tile * 128;
#pragma unroll
        for (int mf = 0; mf < 2; mf++) {
            const long long r0 = base + mw * 32 + mf * 16 + (lane >> 2);
            const long long r1 = r0 + 8;
            float* o1a = out1 + r0 * HID;
            float* o1b = out1 + r1 * HID;
            const int cb = nw * 64 + (lane & 3) * 2;
#pragma unroll
            for (int nf = 0; nf < 8; nf++) {
                const int c = cb + nf * 8;
                *(float2*)(o1a + c) = make_float2(acc[mf][nf][0], acc[mf][nf][1]);
                *(float2*)(o1b + c) = make_float2(acc[mf][nf][2], acc[mf][nf][3]);
            }
        }

        CP_WAIT0();               // next tile staged
        __syncthreads();          // all lds of AHI/ALO done; safe to overwrite next iter
    }
}

// ---------- CSR pull-aggregation: out[d] = dinv_d^2*hw[d] + sum norm*hw[s] ----------
template <bool POOL>
__global__ void k_agg(const float* __restrict__ hw, float* __restrict__ outbuf,
                      const int* __restrict__ batch) {
    long long t = (long long)blockIdx.x * blockDim.x + threadIdx.x;
    const int node = (int)(t >> 5);
    if (node >= N_NODES) return;
    const int lane = threadIdx.x & 31;

    const float dd  = g_dinv[node];
    const float di2 = dd * dd;
    float4 acc = *(const float4*)(hw + (long long)node * HID + lane * 4);
    acc.x *= di2; acc.y *= di2; acc.z *= di2; acc.w *= di2;

    const int start = g_off[node];
    const int deg   = g_degi[node];
    int i = 0;
    for (; i + 3 < deg; i += 4) {
        const int s0 = g_csr[start + i];
        const int s1 = g_csr[start + i + 1];
        const int s2 = g_csr[start + i + 2];
        const int s3 = g_csr[start + i + 3];
        const float n0 = dd * g_dinv[s0];
        const float n1 = dd * g_dinv[s1];
        const float n2 = dd * g_dinv[s2];
        const float n3 = dd * g_dinv[s3];
        float4 v0 = *(const float4*)(hw + (long long)s0 * HID + lane * 4);
        float4 v1 = *(const float4*)(hw + (long long)s1 * HID + lane * 4);
        float4 v2 = *(const float4*)(hw + (long long)s2 * HID + lane * 4);
        float4 v3 = *(const float4*)(hw + (long long)s3 * HID + lane * 4);
        acc.x += n0 * v0.x + n1 * v1.x + n2 * v2.x + n3 * v3.x;
        acc.y += n0 * v0.y + n1 * v1.y + n2 * v2.y + n3 * v3.y;
        acc.z += n0 * v0.z + n1 * v1.z + n2 * v2.z + n3 * v3.z;
        acc.w += n0 * v0.w + n1 * v1.w + n2 * v2.w + n3 * v3.w;
    }
    for (; i < deg; i++) {
        const int s0 = g_csr[start + i];
        const float n0 = dd * g_dinv[s0];
        float4 v0 = *(const float4*)(hw + (long long)s0 * HID + lane * 4);
        acc.x += n0 * v0.x;
        acc.y += n0 * v0.y;
        acc.z += n0 * v0.z;
        acc.w += n0 * v0.w;
    }

    if (POOL) {
        float4 s4 = *(const float4*)(g_s + 2 * HID + lane * 4);
        float4 t4 = *(const float4*)(g_t + 2 * HID + lane * 4);
        float a = fmaxf(acc.x * s4.x + t4.x, 0.0f);
        float b = fmaxf(acc.y * s4.y + t4.y, 0.0f);
        float c = fmaxf(acc.z * s4.z + t4.z, 0.0f);
        float d = fmaxf(acc.w * s4.w + t4.w, 0.0f);
        red_add_v4(g_pool + (long long)batch[node] * HID + lane * 4, a, b, c, d);
    } else {
        *(float4*)(outbuf + (long long)node * HID + lane * 4) = acc;
    }
}

// final MLP head: 8 graphs per block (1 warp per graph)
__global__ void k_mlp(const float* __restrict__ Wc1, const float* __restrict__ bc1,
                      const float* __restrict__ Wc2, const float* __restrict__ bc2,
                      float* __restrict__ out) {
    __shared__ float W1s[128 * 64];
    __shared__ float w2s[64];
    __shared__ float b1s[64];
    __shared__ float msm[8][128];
    int tid = threadIdx.x;
    for (int i = tid; i < 128 * 64; i += 256) W1s[i] = Wc1[i];
    if (tid < 64) { w2s[tid] = Wc2[tid]; b1s[tid] = bc1[tid]; }
    __syncthreads();
    int w = tid >> 5, lane = tid & 31;
    int g = blockIdx.x * 8 + w;
    float inv = 1.0f / fmaxf(g_cnt[g], 1.0f);
    float4 v = *(const float4*)(g_pool + (long long)g * HID + lane * 4);
    *(float4*)(&msm[w][lane * 4]) = make_float4(v.x * inv, v.y * inv, v.z * inv, v.w * inv);
    __syncwarp();
    float h0 = b1s[lane], h1 = b1s[lane + 32];
#pragma unroll 8
    for (int i = 0; i < 128; i++) {
        float m = msm[w][i];
        h0 += m * W1s[i * 64 + lane];
        h1 += m * W1s[i * 64 + lane + 32];
    }
    h0 = fmaxf(h0, 0.0f);
    h1 = fmaxf(h1, 0.0f);
    float p = h0 * w2s[lane] + h1 * w2s[lane + 32];
#pragma unroll
    for (int off = 16; off > 0; off >>= 1) p += __shfl_down_sync(0xffffffffu, p, off);
    if (lane == 0) out[g] = p + bc2[0];
}

// ---------------- launch ----------------
extern "C" void kernel_launch(void* const* d_in, const int* in_sizes, int n_in,
                              void* d_out, int out_size) {
    const float* x     = (const float*)d_in[0];
    const int*   ei    = (const int*)d_in[1];
    const int*   batch = (const int*)d_in[2];
    const float* W1 = (const float*)d_in[3];
    const float* b1 = (const float*)d_in[4];
    const float* ga1 = (const float*)d_in[5];
    const float* be1 = (const float*)d_in[6];
    const float* rm1 = (const float*)d_in[7];
    const float* rv1 = (const float*)d_in[8];
    const float* W2 = (const float*)d_in[9];
    const float* b2 = (const float*)d_in[10];
    const float* ga2 = (const float*)d_in[11];
    const float* be2 = (const float*)d_in[12];
    const float* rm2 = (const float*)d_in[13];
    const float* rv2 = (const float*)d_in[14];
    const float* W3 = (const float*)d_in[15];
    const float* b3 = (const float*)d_in[16];
    const float* ga3 = (const float*)d_in[17];
    const float* be3 = (const float*)d_in[18];
    const float* rm3 = (const float*)d_in[19];
    const float* rv3 = (const float*)d_in[20];
    const float* Wc1 = (const float*)d_in[21];
    const float* bc1 = (const float*)d_in[22];
    const float* Wc2 = (const float*)d_in[23];
    const float* bc2 = (const float*)d_in[24];
    float* out = (float*)d_out;

    float *p_s = nullptr, *p_t = nullptr;
    cudaGetSymbolAddress((void**)&p_s, g_s);
    cudaGetSymbolAddress((void**)&p_t, g_t);
    float *p_h1 = nullptr, *p_hw = nullptr, *p_out = nullptr;
    cudaGetSymbolAddress((void**)&p_h1, g_h1);
    cudaGetSymbolAddress((void**)&p_hw, g_hw);
    cudaGetSymbolAddress((void**)&p_out, g_out);

    cudaFuncSetAttribute(k_gemm_mma<false>, cudaFuncAttributeMaxDynamicSharedMemorySize, SM_TOT);
    cudaFuncSetAttribute(k_gemm_mma<true>,  cudaFuncAttributeMaxDynamicSharedMemorySize, SM_TOT);

    k_zero<<<(N_GRAPHS * HID) / 256, 256>>>();
    k_bnprep<<<1, 128>>>(b1, ga1, be1, rm1, rv1, b2, ga2, be2, rm2, rv2,
                         b3, ga3, be3, rm3, rv3);
    k_deg<<<(N_EDGES + 255) / 256, 256>>>(ei);
    // CSR build
    k_scan1<<<NSCAN_B, 256>>>();
    k_scan2<<<1, 1024>>>();
    k_scan3<<<NSCAN_B, 256>>>();
    k_bin<<<(N_EDGES + 255) / 256, 256>>>(ei);

    k_node_prep<<<(N_NODES + 255) / 256, 256>>>(x, batch);
    k_scatter8<<<(N_EDGES + 255) / 256, 256>>>(ei);
    k_gemm1<<<N_NODES / 32, 128>>>(W1);

    const int agg_grid = (int)(((long long)N_NODES * 32 + 255) / 256);
    // layer 2: hw = h1 @ W2 ; g_out = A_norm * hw (pull)
    k_gemm_mma<false><<<148, 256, SM_TOT>>>(p_h1, W2, nullptr, nullptr, p_hw);
    k_agg<false><<<agg_grid, 256>>>(p_hw, p_out, batch);
    // layer 3: hw = act2(g_out) @ W3 ; pool += relu(bn3(A_norm * hw)) (pull, fused)
    k_gemm_mma<true><<<148, 256, SM_TOT>>>(p_out, W3, p_s + HID, p_t + HID, p_hw);
    k_agg<true><<<agg_grid, 256>>>(p_hw, nullptr, batch);

    k_mlp<<<N_GRAPHS / 8, 256>>>(Wc1, bc1, Wc2, bc2, out);
}

// round 13
// speedup vs baseline: 1.8854x; 1.0562x over previous
#include <cuda_runtime.h>
#include <cuda_fp16.h>
#include <cstdint>

#define N_NODES  1000000
#define N_EDGES  4000000
#define N_GRAPHS 32768
#define HID      128
#define BN_EPS   1e-5f

#define NTILES   7813                       // ceil(1e6/128)
#define N_PAD    (NTILES * 128)             // 1000064
#define NSCAN_B  977                        // ceil(1e6/1024)

// ---------------- scratch (device globals: no allocations allowed) ----------------
__device__ float g_dinv[N_NODES];          // rsqrt(deg+1)
__device__ int   g_degi[N_NODES];          // int in-degree (by dst, no self loop)
__device__ int   g_off [N_NODES];          // CSR offsets (exclusive scan of degi)
__device__ int   g_cur [N_NODES];          // binning cursors
__device__ int   g_csr [N_EDGES];          // src ids grouped by dst
__device__ int   g_bsum[1024];             // scan block sums
__device__ float g_xpad[N_NODES * 8];      // x padded to 8 cols
__device__ float g_agg0[N_NODES * 8];      // A @ x   (7 used cols)
__device__ float g_h1 [N_PAD * HID];       // h1 (activated)
__device__ float g_hw [N_PAD * HID];       // hW scratch (gather source)
__device__ float g_out[N_PAD * HID];       // aggregated layer-2 (raw)
__device__ float g_pool[N_GRAPHS * HID];   // pooled sums
__device__ float g_cnt [N_GRAPHS];         // nodes per graph
__device__ float g_s[3 * HID];             // folded BN scale  per layer
__device__ float g_t[3 * HID];             // folded BN shift (includes bias) per layer

// ---------------- helpers ----------------
__device__ __forceinline__ void red_add_v4(float* addr, float x, float y, float z, float w) {
    asm volatile("red.global.add.v4.f32 [%0], {%1,%2,%3,%4};"
                 :: "l"(addr), "f"(x), "f"(y), "f"(z), "f"(w) : "memory");
}
__device__ __forceinline__ uint32_t smem_u32(const void* p) {
    uint32_t a;
    asm("{ .reg .u64 t; cvta.to.shared.u64 t, %1; cvt.u32.u64 %0, t; }" : "=r"(a) : "l"(p));
    return a;
}
// fp32 pair -> fp16x2 hi (returned) + fp16x2 lo residual (out-param); elem a in low half
__device__ __forceinline__ uint32_t pack_hilo16(float a, float b, uint32_t& lo) {
    __half ah = __float2half_rn(a);
    __half bh = __float2half_rn(b);
    __half al = __float2half_rn(a - __half2float(ah));
    __half bl = __float2half_rn(b - __half2float(bh));
    lo = ((uint32_t)__half_as_ushort(bl) << 16) | __half_as_ushort(al);
    return ((uint32_t)__half_as_ushort(bh) << 16) | __half_as_ushort(ah);
}
// fp32 pair -> fp16x2 (hi only, for W)
__device__ __forceinline__ uint32_t pack16(float a, float b) {
    return ((uint32_t)__half_as_ushort(__float2half_rn(b)) << 16) |
           __half_as_ushort(__float2half_rn(a));
}
__device__ __forceinline__ void ldsm4(uint32_t* r, uint32_t addr) {
    asm volatile("ldmatrix.sync.aligned.m8n8.x4.shared.b16 {%0,%1,%2,%3}, [%4];"
                 : "=r"(r[0]), "=r"(r[1]), "=r"(r[2]), "=r"(r[3]) : "r"(addr));
}
__device__ __forceinline__ void mma_f16(float* d, const uint32_t* a, uint32_t b0, uint32_t b1) {
    asm volatile(
        "mma.sync.aligned.m16n8k16.row.col.f32.f16.f16.f32 "
        "{%0,%1,%2,%3}, {%4,%5,%6,%7}, {%8,%9}, {%0,%1,%2,%3};"
        : "+f"(d[0]), "+f"(d[1]), "+f"(d[2]), "+f"(d[3])
        : "r"(a[0]), "r"(a[1]), "r"(a[2]), "r"(a[3]), "r"(b0), "r"(b1));
}
__device__ __forceinline__ void cp16(uint32_t smem_dst, const void* gmem_src) {
    asm volatile("cp.async.cg.shared.global [%0], [%1], 16;"
                 :: "r"(smem_dst), "l"(gmem_src) : "memory");
}
#define CP_COMMIT() asm volatile("cp.async.commit_group;" ::: "memory")
#define CP_WAIT0()  asm volatile("cp.async.wait_group 0;" ::: "memory")

// padded fp16 tile layout: 128 rows x 136 halves (272 B/row; rows shift 4 banks -> LDSM conflict-free)
#define ROWB   136
#define TILE_B (128 * ROWB * 2)             // 34816 bytes
// fp32 staging tile: 128 rows x 132 floats (528 B/row -> <=2-way LDS conflicts)
#define SROWF  132
#define STG_B  (128 * SROWF * 4)            // 67584 bytes
#define SM_WHI  0
#define SM_AHI  (TILE_B)
#define SM_ALO  (2 * TILE_B)
#define SM_ASTG (3 * TILE_B)
#define SM_TOT  (3 * TILE_B + STG_B)        // 172032 bytes

// ---------------- init / prep ----------------
__global__ void k_zero() {
    int i = blockIdx.x * blockDim.x + threadIdx.x;         // grid covers N_GRAPHS*HID
    g_pool[i] = 0.0f;
    if (i < N_NODES)  { g_degi[i] = 0; g_cur[i] = 0; }
    if (i < N_GRAPHS) g_cnt[i]  = 0.0f;
}

__global__ void k_bnprep(const float* __restrict__ b1, const float* __restrict__ ga1,
                         const float* __restrict__ be1, const float* __restrict__ rm1,
                         const float* __restrict__ rv1,
                         const float* __restrict__ b2, const float* __restrict__ ga2,
                         const float* __restrict__ be2, const float* __restrict__ rm2,
                         const float* __restrict__ rv2,
                         const float* __restrict__ b3, const float* __restrict__ ga3,
                         const float* __restrict__ be3, const float* __restrict__ rm3,
                         const float* __restrict__ rv3) {
    int j = threadIdx.x;
    if (j >= HID) return;
    const float* B[3]  = {b1, b2, b3};
    const float* G[3]  = {ga1, ga2, ga3};
    const float* BE[3] = {be1, be2, be3};
    const float* RM[3] = {rm1, rm2, rm3};
    const float* RV[3] = {rv1, rv2, rv3};
    for (int l = 0; l < 3; l++) {
        float s = G[l][j] * rsqrtf(RV[l][j] + BN_EPS);
        g_s[l * HID + j] = s;
        g_t[l * HID + j] = (B[l][j] - RM[l][j]) * s + BE[l][j];
    }
}

__global__ void k_deg(const int* __restrict__ ei) {
    int e = blockIdx.x * blockDim.x + threadIdx.x;
    if (e >= N_EDGES) return;
    atomicAdd(&g_degi[ei[N_EDGES + e]], 1);
}

// ---- 3-kernel exclusive scan of g_degi -> g_off ----
__global__ void k_scan1() {
    __shared__ int sd[256];
    const int b = blockIdx.x, t = threadIdx.x;
    const int base = b * 1024 + t * 4;
    int v[4];
#pragma unroll
    for (int j = 0; j < 4; j++) v[j] = (base + j < N_NODES) ? g_degi[base + j] : 0;
    const int s = v[0] + v[1] + v[2] + v[3];
    sd[t] = s;
    __syncthreads();
    for (int off = 1; off < 256; off <<= 1) {
        int x = (t >= off) ? sd[t - off] : 0;
        __syncthreads();
        sd[t] += x;
        __syncthreads();
    }
    int run = sd[t] - s;                   // exclusive within block
#pragma unroll
    for (int j = 0; j < 4; j++) {
        if (base + j < N_NODES) g_off[base + j] = run;
        run += v[j];
    }
    if (t == 255) g_bsum[b] = sd[255];
}
__global__ void k_scan2() {
    __shared__ int sd[1024];
    const int t = threadIdx.x;
    const int v = (t < NSCAN_B) ? g_bsum[t] : 0;
    sd[t] = v;
    __syncthreads();
    for (int off = 1; off < 1024; off <<= 1) {
        int x = (t >= off) ? sd[t - off] : 0;
        __syncthreads();
        sd[t] += x;
        __syncthreads();
    }
    if (t < NSCAN_B) g_bsum[t] = sd[t] - v;   // exclusive
}
__global__ void k_scan3() {
    const int b = blockIdx.x, t = threadIdx.x;
    const int add = g_bsum[b];
    const int base = b * 1024 + t * 4;
#pragma unroll
    for (int j = 0; j < 4; j++)
        if (base + j < N_NODES) g_off[base + j] += add;
}

// bin edges by dst
__global__ void k_bin(const int* __restrict__ ei) {
    int e = blockIdx.x * blockDim.x + threadIdx.x;
    if (e >= N_EDGES) return;
    const int d = ei[N_EDGES + e];
    const int pos = g_off[d] + atomicAdd(&g_cur[d], 1);
    g_csr[pos] = ei[e];
}

__global__ void k_node_prep(const float* __restrict__ x, const int* __restrict__ batch) {
    int i = blockIdx.x * blockDim.x + threadIdx.x;
    if (i >= N_NODES) return;
    float di = rsqrtf((float)g_degi[i] + 1.0f);   // + self-loop
    g_dinv[i] = di;
    float di2 = di * di;
    const float* xr = x + (long long)i * 7;
    float xv[8];
#pragma unroll
    for (int j = 0; j < 7; j++) xv[j] = xr[j];
    xv[7] = 0.0f;
    float4* xp = (float4*)(g_xpad + i * 8);
    float4* ag = (float4*)(g_agg0 + i * 8);
    xp[0] = make_float4(xv[0], xv[1], xv[2], xv[3]);
    xp[1] = make_float4(xv[4], xv[5], xv[6], xv[7]);
    ag[0] = make_float4(di2 * xv[0], di2 * xv[1], di2 * xv[2], di2 * xv[3]);
    ag[1] = make_float4(di2 * xv[4], di2 * xv[5], di2 * xv[6], di2 * xv[7]);
    atomicAdd(&g_cnt[batch[i]], 1.0f);
}

// layer-1 edge scatter on 8-wide x (atomics fine at this width)
__global__ void k_scatter8(const int* __restrict__ ei) {
    int e = blockIdx.x * blockDim.x + threadIdx.x;
    if (e >= N_EDGES) return;
    int s = ei[e], d = ei[N_EDGES + e];
    float nrm = g_dinv[s] * g_dinv[d];
    const float4* sp = (const float4*)(g_xpad + s * 8);
    float4 a = sp[0], b = sp[1];
    red_add_v4(g_agg0 + d * 8,     nrm * a.x, nrm * a.y, nrm * a.z, nrm * a.w);
    red_add_v4(g_agg0 + d * 8 + 4, nrm * b.x, nrm * b.y, nrm * b.z, nrm * b.w);
}

// h1 = relu( (agg0 @ W1) * s1 + t1 )
__global__ void k_gemm1(const float* __restrict__ W1) {
    __shared__ float Wsm[7 * 128];
    __shared__ float rsm[32 * 8];
    int j = threadIdx.x;
#pragma unroll
    for (int k = 0; k < 7; k++) Wsm[k * 128 + j] = W1[k * 128 + j];
    float sj = g_s[j], tj = g_t[j];
    int base = blockIdx.x * 32;
    rsm[j]       = g_agg0[base * 8 + j];
    rsm[j + 128] = g_agg0[base * 8 + j + 128];
    __syncthreads();
#pragma unroll 4
    for (int n = 0; n < 32; n++) {
        float acc = 0.0f;
#pragma unroll
        for (int k = 0; k < 7; k++) acc += rsm[n * 8 + k] * Wsm[k * 128 + j];
        g_h1[(long long)(base + n) * HID + j] = fmaxf(acc * sj + tj, 0.0f);
    }
}

// ---------- HMMA GEMM: out = act(In) @ W ----------
// fp16 2-term split: D = Ah*Wh + Al*Wh  (A exact via hi+lo, W rounded to fp16).
// cp.async-pipelined A staging. Pad rows carry garbage; never consumed downstream.
template <bool ACT>
__global__ void __launch_bounds__(256, 1)
k_gemm_mma(const float* __restrict__ In, const float* __restrict__ Wg,
           const float* __restrict__ sv, const float* __restrict__ tv,
           float* __restrict__ out1) {
    extern __shared__ char smem[];
    const uint32_t sb = smem_u32(smem);
    const int tid  = threadIdx.x;
    const int wid  = tid >> 5, lane = tid & 31;
    const int mw   = wid >> 1;
    const int nw   = wid & 1;

    // ---- W transpose -> fp16 into padded SMEM (once per CTA) ----
    {
        const int n  = tid >> 1;
        const int kh = (tid & 1) * 64;
#pragma unroll
        for (int j = 0; j < 8; j++) {
            uint32_t hi[4];
#pragma unroll
            for (int q = 0; q < 4; q++)
                hi[q] = pack16(Wg[(kh + j * 8 + q * 2) * 128 + n],
                               Wg[(kh + j * 8 + q * 2 + 1) * 128 + n]);
            const int off = (n * ROWB + kh + j * 8) * 2;
            *(uint4*)(smem + SM_WHI + off) = make_uint4(hi[0], hi[1], hi[2], hi[3]);
        }
    }

    // staging assignment: thread -> row rr, half hh (64 floats = 256B)
    const int rr = tid >> 1;
    const int hh = (tid & 1) * 64;
    const uint32_t stg_dst = sb + SM_ASTG + (uint32_t)((rr * SROWF + hh) * 4);

    // prologue: cp.async tile(blockIdx.x)
    {
        const float* src = In + ((long long)blockIdx.x * 128 + rr) * HID + hh;
#pragma unroll
        for (int i = 0; i < 16; i++) cp16(stg_dst + i * 16, src + i * 4);
        CP_COMMIT();
    }
    CP_WAIT0();
    __syncthreads();

    const int a_row  = (lane & 15);
    const int a_koff = (lane >> 4) * 8;
    const int b_noff = (lane & 7) + ((lane >> 4) & 1) * 8;
    const int b_koff = ((lane >> 3) & 1) * 8;

    for (int tile = blockIdx.x; tile < NTILES; tile += gridDim.x) {
        // ---- convert staged fp32 -> (ACT) -> fp16 hi/lo (SMEM -> SMEM) ----
        {
            const float* ap = (const float*)(smem + SM_ASTG) + rr * SROWF + hh;
#pragma unroll
            for (int j = 0; j < 8; j++) {
                float4 v0 = *(const float4*)(ap + j * 8);
                float4 v1 = *(const float4*)(ap + j * 8 + 4);
                if (ACT) {
                    float4 s0 = *(const float4*)(sv + hh + j * 8);
                    float4 t0 = *(const float4*)(tv + hh + j * 8);
                    float4 s1 = *(const float4*)(sv + hh + j * 8 + 4);
                    float4 t1 = *(const float4*)(tv + hh + j * 8 + 4);
                    v0.x = fmaxf(v0.x * s0.x + t0.x, 0.0f);
                    v0.y = fmaxf(v0.y * s0.y + t0.y, 0.0f);
                    v0.z = fmaxf(v0.z * s0.z + t0.z, 0.0f);
                    v0.w = fmaxf(v0.w * s0.w + t0.w, 0.0f);
                    v1.x = fmaxf(v1.x * s1.x + t1.x, 0.0f);
                    v1.y = fmaxf(v1.y * s1.y + t1.y, 0.0f);
                    v1.z = fmaxf(v1.z * s1.z + t1.z, 0.0f);
                    v1.w = fmaxf(v1.w * s1.w + t1.w, 0.0f);
                }
                uint4 H, L;
                H.x = pack_hilo16(v0.x, v0.y, L.x);
                H.y = pack_hilo16(v0.z, v0.w, L.y);
                H.z = pack_hilo16(v1.x, v1.y, L.z);
                H.w = pack_hilo16(v1.z, v1.w, L.w);
                const int off = (rr * ROWB + hh + j * 8) * 2;
                *(uint4*)(smem + SM_AHI + off) = H;
                *(uint4*)(smem + SM_ALO + off) = L;
            }
        }
        __syncthreads();          // conversion done; ASTG free, AHI/ALO ready

        // ---- prefetch next tile into ASTG (overlaps MMA) ----
        const int nxt = tile + gridDim.x;
        if (nxt < NTILES) {
            const float* src = In + ((long long)nxt * 128 + rr) * HID + hh;
#pragma unroll
            for (int i = 0; i < 16; i++) cp16(stg_dst + i * 16, src + i * 4);
        }
        CP_COMMIT();

        // ---- mainloop ----
        float acc[2][8][4];
#pragma unroll
        for (int mf = 0; mf < 2; mf++)
#pragma unroll
            for (int nf = 0; nf < 8; nf++)
#pragma unroll
                for (int q = 0; q < 4; q++) acc[mf][nf][q] = 0.0f;

#pragma unroll
        for (int k = 0; k < 8; k++) {
            uint32_t Bh[4][4];
#pragma unroll
            for (int nf2 = 0; nf2 < 4; nf2++) {
                const int n    = nw * 64 + nf2 * 16 + b_noff;
                const uint32_t ad = sb + SM_WHI + (uint32_t)((n * ROWB + k * 16 + b_koff) * 2);
                ldsm4(Bh[nf2], ad);
            }
            uint32_t Ah[2][4], Al[2][4];
#pragma unroll
            for (int mf = 0; mf < 2; mf++) {
                const int r2 = mw * 32 + mf * 16 + a_row;
                const uint32_t ad = sb + SM_AHI + (uint32_t)((r2 * ROWB + k * 16 + a_koff) * 2);
                ldsm4(Ah[mf], ad);
                ldsm4(Al[mf], ad + (SM_ALO - SM_AHI));
            }
#pragma unroll
            for (int mf = 0; mf < 2; mf++)
#pragma unroll
                for (int nf2 = 0; nf2 < 4; nf2++) {
                    mma_f16(acc[mf][2 * nf2],     Ah[mf], Bh[nf2][0], Bh[nf2][1]);
                    mma_f16(acc[mf][2 * nf2],     Al[mf], Bh[nf2][0], Bh[nf2][1]);
                    mma_f16(acc[mf][2 * nf2 + 1], Ah[mf], Bh[nf2][2], Bh[nf2][3]);
                    mma_f16(acc[mf][2 * nf2 + 1], Al[mf], Bh[nf2][2], Bh[nf2][3]);
                }
        }

        // ---- epilogue (register -> gmem; no smem) ----
        const long long base = (long long)tile * 128;
#pragma unroll
        for (int mf = 0; mf < 2; mf++) {
            const long long r0 = base + mw * 32 + mf * 16 + (lane >> 2);
            const long long r1 = r0 + 8;
            float* o1a = out1 + r0 * HID;
            float* o1b = out1 + r1 * HID;
            const int cb = nw * 64 + (lane & 3) * 2;
#pragma unroll
            for (int nf = 0; nf < 8; nf++) {
                const int c = cb + nf * 8;
                *(float2*)(o1a + c) = make_float2(acc[mf][nf][0], acc[mf][nf][1]);
                *(float2*)(o1b + c) = make_float2(acc[mf][nf][2], acc[mf][nf][3]);
            }
        }

        CP_WAIT0();               // next tile staged
        __syncthreads();          // all lds of AHI/ALO done; safe to overwrite next iter
    }
}

// ---------- CSR pull-aggregation: out[d] = dinv_d^2*hw[d] + sum norm*hw[s] ----------
template <bool POOL>
__global__ void k_agg(const float* __restrict__ hw, float* __restrict__ outbuf,
                      const int* __restrict__ batch) {
    long long t = (long long)blockIdx.x * blockDim.x + threadIdx.x;
    const int node = (int)(t >> 5);
    if (node >= N_NODES) return;
    const int lane = threadIdx.x & 31;

    const float dd  = g_dinv[node];
    const float di2 = dd * dd;
    float4 acc = *(const float4*)(hw + (long long)node * HID + lane * 4);
    acc.x *= di2; acc.y *= di2; acc.z *= di2; acc.w *= di2;

    const int start = g_off[node];
    const int deg   = g_degi[node];
    int i = 0;
    for (; i + 3 < deg; i += 4) {
        const int s0 = g_csr[start + i];
        const int s1 = g_csr[start + i + 1];
        const int s2 = g_csr[start + i + 2];
        const int s3 = g_csr[start + i + 3];
        const float n0 = dd * g_dinv[s0];
        const float n1 = dd * g_dinv[s1];
        const float n2 = dd * g_dinv[s2];
        const float n3 = dd * g_dinv[s3];
        float4 v0 = *(const float4*)(hw + (long long)s0 * HID + lane * 4);
        float4 v1 = *(const float4*)(hw + (long long)s1 * HID + lane * 4);
        float4 v2 = *(const float4*)(hw + (long long)s2 * HID + lane * 4);
        float4 v3 = *(const float4*)(hw + (long long)s3 * HID + lane * 4);
        acc.x += n0 * v0.x + n1 * v1.x + n2 * v2.x + n3 * v3.x;
        acc.y += n0 * v0.y + n1 * v1.y + n2 * v2.y + n3 * v3.y;
        acc.z += n0 * v0.z + n1 * v1.z + n2 * v2.z + n3 * v3.z;
        acc.w += n0 * v0.w + n1 * v1.w + n2 * v2.w + n3 * v3.w;
    }
    for (; i < deg; i++) {
        const int s0 = g_csr[start + i];
        const float n0 = dd * g_dinv[s0];
        float4 v0 = *(const float4*)(hw + (long long)s0 * HID + lane * 4);
        acc.x += n0 * v0.x;
        acc.y += n0 * v0.y;
        acc.z += n0 * v0.z;
        acc.w += n0 * v0.w;
    }

    if (POOL) {
        float4 s4 = *(const float4*)(g_s + 2 * HID + lane * 4);
        float4 t4 = *(const float4*)(g_t + 2 * HID + lane * 4);
        float a = fmaxf(acc.x * s4.x + t4.x, 0.0f);
        float b = fmaxf(acc.y * s4.y + t4.y, 0.0f);
        float c = fmaxf(acc.z * s4.z + t4.z, 0.0f);
        float d = fmaxf(acc.w * s4.w + t4.w, 0.0f);
        red_add_v4(g_pool + (long long)batch[node] * HID + lane * 4, a, b, c, d);
    } else {
        *(float4*)(outbuf + (long long)node * HID + lane * 4) = acc;
    }
}

// final MLP head: 8 graphs per block (1 warp per graph)
__global__ void k_mlp(const float* __restrict__ Wc1, const float* __restrict__ bc1,
                      const float* __restrict__ Wc2, const float* __restrict__ bc2,
                      float* __restrict__ out) {
    __shared__ float W1s[128 * 64];
    __shared__ float w2s[64];
    __shared__ float b1s[64];
    __shared__ float msm[8][128];
    int tid = threadIdx.x;
    for (int i = tid; i < 128 * 64; i += 256) W1s[i] = Wc1[i];
    if (tid < 64) { w2s[tid] = Wc2[tid]; b1s[tid] = bc1[tid]; }
    __syncthreads();
    int w = tid >> 5, lane = tid & 31;
    int g = blockIdx.x * 8 + w;
    float inv = 1.0f / fmaxf(g_cnt[g], 1.0f);
    float4 v = *(const float4*)(g_pool + (long long)g * HID + lane * 4);
    *(float4*)(&msm[w][lane * 4]) = make_float4(v.x * inv, v.y * inv, v.z * inv, v.w * inv);
    __syncwarp();
    float h0 = b1s[lane], h1 = b1s[lane + 32];
#pragma unroll 8
    for (int i = 0; i < 128; i++) {
        float m = msm[w][i];
        h0 += m * W1s[i * 64 + lane];
        h1 += m * W1s[i * 64 + lane + 32];
    }
    h0 = fmaxf(h0, 0.0f);
    h1 = fmaxf(h1, 0.0f);
    float p = h0 * w2s[lane] + h1 * w2s[lane + 32];
#pragma unroll
    for (int off = 16; off > 0; off >>= 1) p += __shfl_down_sync(0xffffffffu, p, off);
    if (lane == 0) out[g] = p + bc2[0];
}

// ---------------- launch ----------------
extern "C" void kernel_launch(void* const* d_in, const int* in_sizes, int n_in,
                              void* d_out, int out_size) {
    const float* x     = (const float*)d_in[0];
    const int*   ei    = (const int*)d_in[1];
    const int*   batch = (const int*)d_in[2];
    const float* W1 = (const float*)d_in[3];
    const float* b1 = (const float*)d_in[4];
    const float* ga1 = (const float*)d_in[5];
    const float* be1 = (const float*)d_in[6];
    const float* rm1 = (const float*)d_in[7];
    const float* rv1 = (const float*)d_in[8];
    const float* W2 = (const float*)d_in[9];
    const float* b2 = (const float*)d_in[10];
    const float* ga2 = (const float*)d_in[11];
    const float* be2 = (const float*)d_in[12];
    const float* rm2 = (const float*)d_in[13];
    const float* rv2 = (const float*)d_in[14];
    const float* W3 = (const float*)d_in[15];
    const float* b3 = (const float*)d_in[16];
    const float* ga3 = (const float*)d_in[17];
    const float* be3 = (const float*)d_in[18];
    const float* rm3 = (const float*)d_in[19];
    const float* rv3 = (const float*)d_in[20];
    const float* Wc1 = (const float*)d_in[21];
    const float* bc1 = (const float*)d_in[22];
    const float* Wc2 = (const float*)d_in[23];
    const float* bc2 = (const float*)d_in[24];
    float* out = (float*)d_out;

    float *p_s = nullptr, *p_t = nullptr;
    cudaGetSymbolAddress((void**)&p_s, g_s);
    cudaGetSymbolAddress((void**)&p_t, g_t);
    float *p_h1 = nullptr, *p_hw = nullptr, *p_out = nullptr;
    cudaGetSymbolAddress((void**)&p_h1, g_h1);
    cudaGetSymbolAddress((void**)&p_hw, g_hw);
    cudaGetSymbolAddress((void**)&p_out, g_out);

    cudaFuncSetAttribute(k_gemm_mma<false>, cudaFuncAttributeMaxDynamicSharedMemorySize, SM_TOT);
    cudaFuncSetAttribute(k_gemm_mma<true>,  cudaFuncAttributeMaxDynamicSharedMemorySize, SM_TOT);

    k_zero<<<(N_GRAPHS * HID) / 256, 256>>>();
    k_bnprep<<<1, 128>>>(b1, ga1, be1, rm1, rv1, b2, ga2, be2, rm2, rv2,
                         b3, ga3, be3, rm3, rv3);
    k_deg<<<(N_EDGES + 255) / 256, 256>>>(ei);
    // CSR build
    k_scan1<<<NSCAN_B, 256>>>();
    k_scan2<<<1, 1024>>>();
    k_scan3<<<NSCAN_B, 256>>>();
    k_bin<<<(N_EDGES + 255) / 256, 256>>>(ei);

    k_node_prep<<<(N_NODES + 255) / 256, 256>>>(x, batch);
    k_scatter8<<<(N_EDGES + 255) / 256, 256>>>(ei);
    k_gemm1<<<N_NODES / 32, 128>>>(W1);

    const int agg_grid = (int)(((long long)N_NODES * 32 + 255) / 256);
    // layer 2: hw = h1 @ W2 ; g_out = A_norm * hw (pull)
    k_gemm_mma<false><<<148, 256, SM_TOT>>>(p_h1, W2, nullptr, nullptr, p_hw);
    k_agg<false><<<agg_grid, 256>>>(p_hw, p_out, batch);
    // layer 3: hw = act2(g_out) @ W3 ; pool += relu(bn3(A_norm * hw)) (pull, fused)
    k_gemm_mma<true><<<148, 256, SM_TOT>>>(p_out, W3, p_s + HID, p_t + HID, p_hw);
    k_agg<true><<<agg_grid, 256>>>(p_hw, nullptr, batch);

    k_mlp<<<N_GRAPHS / 8, 256>>>(Wc1, bc1, Wc2, bc2, out);
}

// round 14
// speedup vs baseline: 2.5536x; 1.3545x over previous
#include <cuda_runtime.h>
#include <cuda_fp16.h>
#include <cstdint>

#define N_NODES  1000000
#define N_EDGES  4000000
#define N_GRAPHS 32768
#define HID      128
#define BN_EPS   1e-5f

#define NTILES   7813                       // ceil(1e6/128)
#define N_PAD    (NTILES * 128)             // 1000064
#define NSCAN_B  977                        // ceil(1e6/1024)

// ---------------- scratch (device globals: no allocations allowed) ----------------
__device__ float  g_dinv[N_NODES];          // rsqrt(deg+1)
__device__ int    g_degi[N_NODES];          // int in-degree (by dst, no self loop)
__device__ int    g_off [N_NODES];          // CSR offsets (exclusive scan of degi)
__device__ int    g_cur [N_NODES];          // binning cursors
__device__ int    g_csr [N_EDGES];          // src ids grouped by dst
__device__ int    g_bsum[1024];             // scan block sums
__device__ float  g_xpad[N_NODES * 8];      // x padded to 8 cols
__device__ float  g_agg0[N_NODES * 8];      // A @ x   (7 used cols)
__device__ float  g_h1 [N_PAD * HID];       // h1 (activated)
__device__ __half g_hw [N_PAD * HID];       // hW scratch, fp16 (gather source)
__device__ float  g_out[N_PAD * HID];       // aggregated layer-2 (raw)
__device__ float  g_pool[N_GRAPHS * HID];   // pooled sums
__device__ float  g_cnt [N_GRAPHS];         // nodes per graph
__device__ float  g_s[3 * HID];             // folded BN scale  per layer
__device__ float  g_t[3 * HID];             // folded BN shift (includes bias) per layer

// ---------------- helpers ----------------
__device__ __forceinline__ void red_add_v4(float* addr, float x, float y, float z, float w) {
    asm volatile("red.global.add.v4.f32 [%0], {%1,%2,%3,%4};"
                 :: "l"(addr), "f"(x), "f"(y), "f"(z), "f"(w) : "memory");
}
__device__ __forceinline__ uint32_t smem_u32(const void* p) {
    uint32_t a;
    asm("{ .reg .u64 t; cvta.to.shared.u64 t, %1; cvt.u32.u64 %0, t; }" : "=r"(a) : "l"(p));
    return a;
}
// fp32 pair -> fp16x2 (elem a in low half)
__device__ __forceinline__ uint32_t pack16(float a, float b) {
    return ((uint32_t)__half_as_ushort(__float2half_rn(b)) << 16) |
           __half_as_ushort(__float2half_rn(a));
}
__device__ __forceinline__ void ldsm4(uint32_t* r, uint32_t addr) {
    asm volatile("ldmatrix.sync.aligned.m8n8.x4.shared.b16 {%0,%1,%2,%3}, [%4];"
                 : "=r"(r[0]), "=r"(r[1]), "=r"(r[2]), "=r"(r[3]) : "r"(addr));
}
__device__ __forceinline__ void mma_f16(float* d, const uint32_t* a, uint32_t b0, uint32_t b1) {
    asm volatile(
        "mma.sync.aligned.m16n8k16.row.col.f32.f16.f16.f32 "
        "{%0,%1,%2,%3}, {%4,%5,%6,%7}, {%8,%9}, {%0,%1,%2,%3};"
        : "+f"(d[0]), "+f"(d[1]), "+f"(d[2]), "+f"(d[3])
        : "r"(a[0]), "r"(a[1]), "r"(a[2]), "r"(a[3]), "r"(b0), "r"(b1));
}
__device__ __forceinline__ void cp16(uint32_t smem_dst, const void* gmem_src) {
    asm volatile("cp.async.cg.shared.global [%0], [%1], 16;"
                 :: "r"(smem_dst), "l"(gmem_src) : "memory");
}
#define CP_COMMIT() asm volatile("cp.async.commit_group;" ::: "memory")
#define CP_WAIT0()  asm volatile("cp.async.wait_group 0;" ::: "memory")

// padded fp16 tile layout: 128 rows x 136 halves (272 B/row; rows shift 4 banks -> LDSM conflict-free)
#define ROWB   136
#define TILE_B (128 * ROWB * 2)             // 34816 bytes
// fp32 staging tile: 128 rows x 132 floats (528 B/row -> <=2-way LDS conflicts)
#define SROWF  132
#define STG_B  (128 * SROWF * 4)            // 67584 bytes
#define SM_WHI  0
#define SM_AHI  (TILE_B)
#define SM_ASTG (2 * TILE_B)
#define SM_TOT  (2 * TILE_B + STG_B)        // 137216 bytes

// ---------------- init / prep ----------------
__global__ void k_zero() {
    int i = blockIdx.x * blockDim.x + threadIdx.x;         // grid covers N_GRAPHS*HID
    g_pool[i] = 0.0f;
    if (i < N_NODES)  { g_degi[i] = 0; g_cur[i] = 0; }
    if (i < N_GRAPHS) g_cnt[i]  = 0.0f;
}

__global__ void k_bnprep(const float* __restrict__ b1, const float* __restrict__ ga1,
                         const float* __restrict__ be1, const float* __restrict__ rm1,
                         const float* __restrict__ rv1,
                         const float* __restrict__ b2, const float* __restrict__ ga2,
                         const float* __restrict__ be2, const float* __restrict__ rm2,
                         const float* __restrict__ rv2,
                         const float* __restrict__ b3, const float* __restrict__ ga3,
                         const float* __restrict__ be3, const float* __restrict__ rm3,
                         const float* __restrict__ rv3) {
    int j = threadIdx.x;
    if (j >= HID) return;
    const float* B[3]  = {b1, b2, b3};
    const float* G[3]  = {ga1, ga2, ga3};
    const float* BE[3] = {be1, be2, be3};
    const float* RM[3] = {rm1, rm2, rm3};
    const float* RV[3] = {rv1, rv2, rv3};
    for (int l = 0; l < 3; l++) {
        float s = G[l][j] * rsqrtf(RV[l][j] + BN_EPS);
        g_s[l * HID + j] = s;
        g_t[l * HID + j] = (B[l][j] - RM[l][j]) * s + BE[l][j];
    }
}

__global__ void k_deg(const int* __restrict__ ei) {
    int e = blockIdx.x * blockDim.x + threadIdx.x;
    if (e >= N_EDGES) return;
    atomicAdd(&g_degi[ei[N_EDGES + e]], 1);
}

// ---- 3-kernel exclusive scan of g_degi -> g_off ----
__global__ void k_scan1() {
    __shared__ int sd[256];
    const int b = blockIdx.x, t = threadIdx.x;
    const int base = b * 1024 + t * 4;
    int v[4];
#pragma unroll
    for (int j = 0; j < 4; j++) v[j] = (base + j < N_NODES) ? g_degi[base + j] : 0;
    const int s = v[0] + v[1] + v[2] + v[3];
    sd[t] = s;
    __syncthreads();
    for (int off = 1; off < 256; off <<= 1) {
        int x = (t >= off) ? sd[t - off] : 0;
        __syncthreads();
        sd[t] += x;
        __syncthreads();
    }
    int run = sd[t] - s;                   // exclusive within block
#pragma unroll
    for (int j = 0; j < 4; j++) {
        if (base + j < N_NODES) g_off[base + j] = run;
        run += v[j];
    }
    if (t == 255) g_bsum[b] = sd[255];
}
__global__ void k_scan2() {
    __shared__ int sd[1024];
    const int t = threadIdx.x;
    const int v = (t < NSCAN_B) ? g_bsum[t] : 0;
    sd[t] = v;
    __syncthreads();
    for (int off = 1; off < 1024; off <<= 1) {
        int x = (t >= off) ? sd[t - off] : 0;
        __syncthreads();
        sd[t] += x;
        __syncthreads();
    }
    if (t < NSCAN_B) g_bsum[t] = sd[t] - v;   // exclusive
}
__global__ void k_scan3() {
    const int b = blockIdx.x, t = threadIdx.x;
    const int add = g_bsum[b];
    const int base = b * 1024 + t * 4;
#pragma unroll
    for (int j = 0; j < 4; j++)
        if (base + j < N_NODES) g_off[base + j] += add;
}

// bin edges by dst
__global__ void k_bin(const int* __restrict__ ei) {
    int e = blockIdx.x * blockDim.x + threadIdx.x;
    if (e >= N_EDGES) return;
    const int d = ei[N_EDGES + e];
    const int pos = g_off[d] + atomicAdd(&g_cur[d], 1);
    g_csr[pos] = ei[e];
}

__global__ void k_node_prep(const float* __restrict__ x, const int* __restrict__ batch) {
    int i = blockIdx.x * blockDim.x + threadIdx.x;
    if (i >= N_NODES) return;
    float di = rsqrtf((float)g_degi[i] + 1.0f);   // + self-loop
    g_dinv[i] = di;
    float di2 = di * di;
    const float* xr = x + (long long)i * 7;
    float xv[8];
#pragma unroll
    for (int j = 0; j < 7; j++) xv[j] = xr[j];
    xv[7] = 0.0f;
    float4* xp = (float4*)(g_xpad + i * 8);
    float4* ag = (float4*)(g_agg0 + i * 8);
    xp[0] = make_float4(xv[0], xv[1], xv[2], xv[3]);
    xp[1] = make_float4(xv[4], xv[5], xv[6], xv[7]);
    ag[0] = make_float4(di2 * xv[0], di2 * xv[1], di2 * xv[2], di2 * xv[3]);
    ag[1] = make_float4(di2 * xv[4], di2 * xv[5], di2 * xv[6], di2 * xv[7]);
    atomicAdd(&g_cnt[batch[i]], 1.0f);
}

// layer-1 edge scatter on 8-wide x (atomics fine at this width)
__global__ void k_scatter8(const int* __restrict__ ei) {
    int e = blockIdx.x * blockDim.x + threadIdx.x;
    if (e >= N_EDGES) return;
    int s = ei[e], d = ei[N_EDGES + e];
    float nrm = g_dinv[s] * g_dinv[d];
    const float4* sp = (const float4*)(g_xpad + s * 8);
    float4 a = sp[0], b = sp[1];
    red_add_v4(g_agg0 + d * 8,     nrm * a.x, nrm * a.y, nrm * a.z, nrm * a.w);
    red_add_v4(g_agg0 + d * 8 + 4, nrm * b.x, nrm * b.y, nrm * b.z, nrm * b.w);
}

// h1 = relu( (agg0 @ W1) * s1 + t1 )
__global__ void k_gemm1(const float* __restrict__ W1) {
    __shared__ float Wsm[7 * 128];
    __shared__ float rsm[32 * 8];
    int j = threadIdx.x;
#pragma unroll
    for (int k = 0; k < 7; k++) Wsm[k * 128 + j] = W1[k * 128 + j];
    float sj = g_s[j], tj = g_t[j];
    int base = blockIdx.x * 32;
    rsm[j]       = g_agg0[base * 8 + j];
    rsm[j + 128] = g_agg0[base * 8 + j + 128];
    __syncthreads();
#pragma unroll 4
    for (int n = 0; n < 32; n++) {
        float acc = 0.0f;
#pragma unroll
        for (int k = 0; k < 7; k++) acc += rsm[n * 8 + k] * Wsm[k * 128 + j];
        g_h1[(long long)(base + n) * HID + j] = fmaxf(acc * sj + tj, 0.0f);
    }
}

// ---------- HMMA GEMM: out = act(In) @ W  (pure fp16, fp32 accum; fp16 output) ----------
// cp.async-pipelined A staging. Pad rows carry garbage; never consumed downstream.
template <bool ACT>
__global__ void __launch_bounds__(256, 1)
k_gemm_mma(const float* __restrict__ In, const float* __restrict__ Wg,
           const float* __restrict__ sv, const float* __restrict__ tv,
           __half* __restrict__ out1) {
    extern __shared__ char smem[];
    const uint32_t sb = smem_u32(smem);
    const int tid  = threadIdx.x;
    const int wid  = tid >> 5, lane = tid & 31;
    const int mw   = wid >> 1;
    const int nw   = wid & 1;

    // ---- W transpose -> fp16 into padded SMEM (once per CTA) ----
    {
        const int n  = tid >> 1;
        const int kh = (tid & 1) * 64;
#pragma unroll
        for (int j = 0; j < 8; j++) {
            uint32_t hi[4];
#pragma unroll
            for (int q = 0; q < 4; q++)
                hi[q] = pack16(Wg[(kh + j * 8 + q * 2) * 128 + n],
                               Wg[(kh + j * 8 + q * 2 + 1) * 128 + n]);
            const int off = (n * ROWB + kh + j * 8) * 2;
            *(uint4*)(smem + SM_WHI + off) = make_uint4(hi[0], hi[1], hi[2], hi[3]);
        }
    }

    // staging assignment: thread -> row rr, half hh (64 floats = 256B)
    const int rr = tid >> 1;
    const int hh = (tid & 1) * 64;
    const uint32_t stg_dst = sb + SM_ASTG + (uint32_t)((rr * SROWF + hh) * 4);

    // prologue: cp.async tile(blockIdx.x)
    {
        const float* src = In + ((long long)blockIdx.x * 128 + rr) * HID + hh;
#pragma unroll
        for (int i = 0; i < 16; i++) cp16(stg_dst + i * 16, src + i * 4);
        CP_COMMIT();
    }
    CP_WAIT0();
    __syncthreads();

    const int a_row  = (lane & 15);
    const int a_koff = (lane >> 4) * 8;
    const int b_noff = (lane & 7) + ((lane >> 4) & 1) * 8;
    const int b_koff = ((lane >> 3) & 1) * 8;

    for (int tile = blockIdx.x; tile < NTILES; tile += gridDim.x) {
        // ---- convert staged fp32 -> (ACT) -> fp16 (SMEM -> SMEM) ----
        {
            const float* ap = (const float*)(smem + SM_ASTG) + rr * SROWF + hh;
#pragma unroll
            for (int j = 0; j < 8; j++) {
                float4 v0 = *(const float4*)(ap + j * 8);
                float4 v1 = *(const float4*)(ap + j * 8 + 4);
                if (ACT) {
                    float4 s0 = *(const float4*)(sv + hh + j * 8);
                    float4 t0 = *(const float4*)(tv + hh + j * 8);
                    float4 s1 = *(const float4*)(sv + hh + j * 8 + 4);
                    float4 t1 = *(const float4*)(tv + hh + j * 8 + 4);
                    v0.x = fmaxf(v0.x * s0.x + t0.x, 0.0f);
                    v0.y = fmaxf(v0.y * s0.y + t0.y, 0.0f);
                    v0.z = fmaxf(v0.z * s0.z + t0.z, 0.0f);
                    v0.w = fmaxf(v0.w * s0.w + t0.w, 0.0f);
                    v1.x = fmaxf(v1.x * s1.x + t1.x, 0.0f);
                    v1.y = fmaxf(v1.y * s1.y + t1.y, 0.0f);
                    v1.z = fmaxf(v1.z * s1.z + t1.z, 0.0f);
                    v1.w = fmaxf(v1.w * s1.w + t1.w, 0.0f);
                }
                uint4 H;
                H.x = pack16(v0.x, v0.y);
                H.y = pack16(v0.z, v0.w);
                H.z = pack16(v1.x, v1.y);
                H.w = pack16(v1.z, v1.w);
                *(uint4*)(smem + SM_AHI + (rr * ROWB + hh + j * 8) * 2) = H;
            }
        }
        __syncthreads();          // conversion done; ASTG free, AHI ready

        // ---- prefetch next tile into ASTG (overlaps MMA) ----
        const int nxt = tile + gridDim.x;
        if (nxt < NTILES) {
            const float* src = In + ((long long)nxt * 128 + rr) * HID + hh;
#pragma unroll
            for (int i = 0; i < 16; i++) cp16(stg_dst + i * 16, src + i * 4);
        }
        CP_COMMIT();

        // ---- mainloop ----
        float acc[2][8][4];
#pragma unroll
        for (int mf = 0; mf < 2; mf++)
#pragma unroll
            for (int nf = 0; nf < 8; nf++)
#pragma unroll
                for (int q = 0; q < 4; q++) acc[mf][nf][q] = 0.0f;

#pragma unroll
        for (int k = 0; k < 8; k++) {
            uint32_t Bh[4][4];
#pragma unroll
            for (int nf2 = 0; nf2 < 4; nf2++) {
                const int n    = nw * 64 + nf2 * 16 + b_noff;
                const uint32_t ad = sb + SM_WHI + (uint32_t)((n * ROWB + k * 16 + b_koff) * 2);
                ldsm4(Bh[nf2], ad);
            }
            uint32_t Ah[2][4];
#pragma unroll
            for (int mf = 0; mf < 2; mf++) {
                const int r2 = mw * 32 + mf * 16 + a_row;
                const uint32_t ad = sb + SM_AHI + (uint32_t)((r2 * ROWB + k * 16 + a_koff) * 2);
                ldsm4(Ah[mf], ad);
            }
#pragma unroll
            for (int mf = 0; mf < 2; mf++)
#pragma unroll
                for (int nf2 = 0; nf2 < 4; nf2++) {
                    mma_f16(acc[mf][2 * nf2],     Ah[mf], Bh[nf2][0], Bh[nf2][1]);
                    mma_f16(acc[mf][2 * nf2 + 1], Ah[mf], Bh[nf2][2], Bh[nf2][3]);
                }
        }

        // ---- epilogue: fp32 acc -> fp16 gmem ----
        const long long base = (long long)tile * 128;
#pragma unroll
        for (int mf = 0; mf < 2; mf++) {
            const long long r0 = base + mw * 32 + mf * 16 + (lane >> 2);
            const long long r1 = r0 + 8;
            __half* o1a = out1 + r0 * HID;
            __half* o1b = out1 + r1 * HID;
            const int cb = nw * 64 + (lane & 3) * 2;
#pragma unroll
            for (int nf = 0; nf < 8; nf++) {
                const int c = cb + nf * 8;
                *(__half2*)(o1a + c) = __floats2half2_rn(acc[mf][nf][0], acc[mf][nf][1]);
                *(__half2*)(o1b + c) = __floats2half2_rn(acc[mf][nf][2], acc[mf][nf][3]);
            }
        }

        CP_WAIT0();               // next tile staged
        __syncthreads();          // all lds of AHI done; safe to overwrite next iter
    }
}

// ---------- CSR pull-aggregation over fp16 hw: out[d] = dinv_d^2*hw[d] + sum norm*hw[s] ----------
__device__ __forceinline__ float4 ld_hw4(const __half* hw, long long row, int lane) {
    uint2 u = *(const uint2*)(hw + row * HID + lane * 4);
    __half2 a = *(__half2*)&u.x;
    __half2 b = *(__half2*)&u.y;
    float2 fa = __half22float2(a);
    float2 fb = __half22float2(b);
    return make_float4(fa.x, fa.y, fb.x, fb.y);
}

template <bool POOL>
__global__ void k_agg(const __half* __restrict__ hw, float* __restrict__ outbuf,
                      const int* __restrict__ batch) {
    long long t = (long long)blockIdx.x * blockDim.x + threadIdx.x;
    const int node = (int)(t >> 5);
    if (node >= N_NODES) return;
    const int lane = threadIdx.x & 31;

    const float dd  = g_dinv[node];
    const float di2 = dd * dd;
    float4 acc = ld_hw4(hw, node, lane);
    acc.x *= di2; acc.y *= di2; acc.z *= di2; acc.w *= di2;

    const int start = g_off[node];
    const int deg   = g_degi[node];
    int i = 0;
    for (; i + 3 < deg; i += 4) {
        const int s0 = g_csr[start + i];
        const int s1 = g_csr[start + i + 1];
        const int s2 = g_csr[start + i + 2];
        const int s3 = g_csr[start + i + 3];
        const float n0 = dd * g_dinv[s0];
        const float n1 = dd * g_dinv[s1];
        const float n2 = dd * g_dinv[s2];
        const float n3 = dd * g_dinv[s3];
        float4 v0 = ld_hw4(hw, s0, lane);
        float4 v1 = ld_hw4(hw, s1, lane);
        float4 v2 = ld_hw4(hw, s2, lane);
        float4 v3 = ld_hw4(hw, s3, lane);
        acc.x += n0 * v0.x + n1 * v1.x + n2 * v2.x + n3 * v3.x;
        acc.y += n0 * v0.y + n1 * v1.y + n2 * v2.y + n3 * v3.y;
        acc.z += n0 * v0.z + n1 * v1.z + n2 * v2.z + n3 * v3.z;
        acc.w += n0 * v0.w + n1 * v1.w + n2 * v2.w + n3 * v3.w;
    }
    for (; i < deg; i++) {
        const int s0 = g_csr[start + i];
        const float n0 = dd * g_dinv[s0];
        float4 v0 = ld_hw4(hw, s0, lane);
        acc.x += n0 * v0.x;
        acc.y += n0 * v0.y;
        acc.z += n0 * v0.z;
        acc.w += n0 * v0.w;
    }

    if (POOL) {
        float4 s4 = *(const float4*)(g_s + 2 * HID + lane * 4);
        float4 t4 = *(const float4*)(g_t + 2 * HID + lane * 4);
        float a = fmaxf(acc.x * s4.x + t4.x, 0.0f);
        float b = fmaxf(acc.y * s4.y + t4.y, 0.0f);
        float c = fmaxf(acc.z * s4.z + t4.z, 0.0f);
        float d = fmaxf(acc.w * s4.w + t4.w, 0.0f);
        red_add_v4(g_pool + (long long)batch[node] * HID + lane * 4, a, b, c, d);
    } else {
        *(float4*)(outbuf + (long long)node * HID + lane * 4) = acc;
    }
}

// final MLP head: 8 graphs per block (1 warp per graph)
__global__ void k_mlp(const float* __restrict__ Wc1, const float* __restrict__ bc1,
                      const float* __restrict__ Wc2, const float* __restrict__ bc2,
                      float* __restrict__ out) {
    __shared__ float W1s[128 * 64];
    __shared__ float w2s[64];
    __shared__ float b1s[64];
    __shared__ float msm[8][128];
    int tid = threadIdx.x;
    for (int i = tid; i < 128 * 64; i += 256) W1s[i] = Wc1[i];
    if (tid < 64) { w2s[tid] = Wc2[tid]; b1s[tid] = bc1[tid]; }
    __syncthreads();
    int w = tid >> 5, lane = tid & 31;
    int g = blockIdx.x * 8 + w;
    float inv = 1.0f / fmaxf(g_cnt[g], 1.0f);
    float4 v = *(const float4*)(g_pool + (long long)g * HID + lane * 4);
    *(float4*)(&msm[w][lane * 4]) = make_float4(v.x * inv, v.y * inv, v.z * inv, v.w * inv);
    __syncwarp();
    float h0 = b1s[lane], h1 = b1s[lane + 32];
#pragma unroll 8
    for (int i = 0; i < 128; i++) {
        float m = msm[w][i];
        h0 += m * W1s[i * 64 + lane];
        h1 += m * W1s[i * 64 + lane + 32];
    }
    h0 = fmaxf(h0, 0.0f);
    h1 = fmaxf(h1, 0.0f);
    float p = h0 * w2s[lane] + h1 * w2s[lane + 32];
#pragma unroll
    for (int off = 16; off > 0; off >>= 1) p += __shfl_down_sync(0xffffffffu, p, off);
    if (lane == 0) out[g] = p + bc2[0];
}

// ---------------- launch ----------------
extern "C" void kernel_launch(void* const* d_in, const int* in_sizes, int n_in,
                              void* d_out, int out_size) {
    const float* x     = (const float*)d_in[0];
    const int*   ei    = (const int*)d_in[1];
    const int*   batch = (const int*)d_in[2];
    const float* W1 = (const float*)d_in[3];
    const float* b1 = (const float*)d_in[4];
    const float* ga1 = (const float*)d_in[5];
    const float* be1 = (const float*)d_in[6];
    const float* rm1 = (const float*)d_in[7];
    const float* rv1 = (const float*)d_in[8];
    const float* W2 = (const float*)d_in[9];
    const float* b2 = (const float*)d_in[10];
    const float* ga2 = (const float*)d_in[11];
    const float* be2 = (const float*)d_in[12];
    const float* rm2 = (const float*)d_in[13];
    const float* rv2 = (const float*)d_in[14];
    const float* W3 = (const float*)d_in[15];
    const float* b3 = (const float*)d_in[16];
    const float* ga3 = (const float*)d_in[17];
    const float* be3 = (const float*)d_in[18];
    const float* rm3 = (const float*)d_in[19];
    const float* rv3 = (const float*)d_in[20];
    const float* Wc1 = (const float*)d_in[21];
    const float* bc1 = (const float*)d_in[22];
    const float* Wc2 = (const float*)d_in[23];
    const float* bc2 = (const float*)d_in[24];
    float* out = (float*)d_out;

    float *p_s = nullptr, *p_t = nullptr;
    cudaGetSymbolAddress((void**)&p_s, g_s);
    cudaGetSymbolAddress((void**)&p_t, g_t);
    float *p_h1 = nullptr, *p_out = nullptr;
    __half* p_hw = nullptr;
    cudaGetSymbolAddress((void**)&p_h1, g_h1);
    cudaGetSymbolAddress((void**)&p_hw, g_hw);
    cudaGetSymbolAddress((void**)&p_out, g_out);

    cudaFuncSetAttribute(k_gemm_mma<false>, cudaFuncAttributeMaxDynamicSharedMemorySize, SM_TOT);
    cudaFuncSetAttribute(k_gemm_mma<true>,  cudaFuncAttributeMaxDynamicSharedMemorySize, SM_TOT);

    k_zero<<<(N_GRAPHS * HID) / 256, 256>>>();
    k_bnprep<<<1, 128>>>(b1, ga1, be1, rm1, rv1, b2, ga2, be2, rm2, rv2,
                         b3, ga3, be3, rm3, rv3);
    k_deg<<<(N_EDGES + 255) / 256, 256>>>(ei);
    // CSR build
    k_scan1<<<NSCAN_B, 256>>>();
    k_scan2<<<1, 1024>>>();
    k_scan3<<<NSCAN_B, 256>>>();
    k_bin<<<(N_EDGES + 255) / 256, 256>>>(ei);

    k_node_prep<<<(N_NODES + 255) / 256, 256>>>(x, batch);
    k_scatter8<<<(N_EDGES + 255) / 256, 256>>>(ei);
    k_gemm1<<<N_NODES / 32, 128>>>(W1);

    const int agg_grid = (int)(((long long)N_NODES * 32 + 255) / 256);
    // layer 2: hw = h1 @ W2 (fp16) ; g_out = A_norm * hw (pull, fp32)
    k_gemm_mma<false><<<148, 256, SM_TOT>>>(p_h1, W2, nullptr, nullptr, p_hw);
    k_agg<false><<<agg_grid, 256>>>(p_hw, p_out, batch);
    // layer 3: hw = act2(g_out) @ W3 (fp16) ; pool += relu(bn3(A_norm * hw)) (pull, fused)
    k_gemm_mma<true><<<148, 256, SM_TOT>>>(p_out, W3, p_s + HID, p_t + HID, p_hw);
    k_agg<true><<<agg_grid, 256>>>(p_hw, nullptr, batch);

    k_mlp<<<N_GRAPHS / 8, 256>>>(Wc1, bc1, Wc2, bc2, out);
}

// round 15
// speedup vs baseline: 3.0293x; 1.1863x over previous
#include <cuda_runtime.h>
#include <cuda_fp16.h>
#include <cstdint>

#define N_NODES  1000000
#define N_EDGES  4000000
#define N_GRAPHS 32768
#define HID      128
#define BN_EPS   1e-5f

#define NTILES   7813                       // ceil(1e6/128)
#define N_PAD    (NTILES * 128)             // 1000064
#define NSCAN_B  977                        // ceil(1e6/1024)

// ---------------- scratch (device globals: no allocations allowed) ----------------
__device__ float  g_dinv[N_NODES];          // rsqrt(deg+1)
__device__ int    g_degi[N_NODES];          // int in-degree (by dst, no self loop)
__device__ int    g_off [N_NODES];          // CSR offsets (exclusive scan of degi)
__device__ int    g_cur [N_NODES];          // binning cursors
__device__ int    g_csr [N_EDGES];          // src ids grouped by dst
__device__ int    g_bsum[1024];             // scan block sums
__device__ float  g_xpad[N_NODES * 8];      // x padded to 8 cols
__device__ float  g_agg0[N_NODES * 8];      // A @ x   (7 used cols)
__device__ __half g_h1 [N_PAD * HID];       // h1 (activated), fp16
__device__ __half g_hw [N_PAD * HID];       // hW scratch, fp16 (gather source)
__device__ __half g_out[N_PAD * HID];       // act2(aggregated layer-2), fp16
__device__ float  g_pool[N_GRAPHS * HID];   // pooled sums
__device__ float  g_cnt [N_GRAPHS];         // nodes per graph
__device__ float  g_s[3 * HID];             // folded BN scale  per layer
__device__ float  g_t[3 * HID];             // folded BN shift (includes bias) per layer

// ---------------- helpers ----------------
__device__ __forceinline__ void red_add_v4(float* addr, float x, float y, float z, float w) {
    asm volatile("red.global.add.v4.f32 [%0], {%1,%2,%3,%4};"
                 :: "l"(addr), "f"(x), "f"(y), "f"(z), "f"(w) : "memory");
}
__device__ __forceinline__ uint32_t smem_u32(const void* p) {
    uint32_t a;
    asm("{ .reg .u64 t; cvta.to.shared.u64 t, %1; cvt.u32.u64 %0, t; }" : "=r"(a) : "l"(p));
    return a;
}
// fp32 pair -> fp16x2 (elem a in low half)
__device__ __forceinline__ uint32_t pack16(float a, float b) {
    return ((uint32_t)__half_as_ushort(__float2half_rn(b)) << 16) |
           __half_as_ushort(__float2half_rn(a));
}
__device__ __forceinline__ void ldsm4(uint32_t* r, uint32_t addr) {
    asm volatile("ldmatrix.sync.aligned.m8n8.x4.shared.b16 {%0,%1,%2,%3}, [%4];"
                 : "=r"(r[0]), "=r"(r[1]), "=r"(r[2]), "=r"(r[3]) : "r"(addr));
}
__device__ __forceinline__ void mma_f16(float* d, const uint32_t* a, uint32_t b0, uint32_t b1) {
    asm volatile(
        "mma.sync.aligned.m16n8k16.row.col.f32.f16.f16.f32 "
        "{%0,%1,%2,%3}, {%4,%5,%6,%7}, {%8,%9}, {%0,%1,%2,%3};"
        : "+f"(d[0]), "+f"(d[1]), "+f"(d[2]), "+f"(d[3])
        : "r"(a[0]), "r"(a[1]), "r"(a[2]), "r"(a[3]), "r"(b0), "r"(b1));
}
__device__ __forceinline__ void cp16(uint32_t smem_dst, const void* gmem_src) {
    asm volatile("cp.async.cg.shared.global [%0], [%1], 16;"
                 :: "r"(smem_dst), "l"(gmem_src) : "memory");
}
#define CP_COMMIT() asm volatile("cp.async.commit_group;" ::: "memory")
#define CP_WAIT0()  asm volatile("cp.async.wait_group 0;" ::: "memory")

// padded fp16 tile layout: 128 rows x 136 halves (272 B/row; rows shift 4 banks -> LDSM conflict-free)
#define ROWB   136
#define TILE_B (128 * ROWB * 2)             // 34816 bytes
#define SM_W   0
#define SM_A0  (TILE_B)
#define SM_A1  (2 * TILE_B)
#define SM_TOT (3 * TILE_B)                 // 104448 bytes

// ---------------- init / prep ----------------
__global__ void k_zero() {
    int i = blockIdx.x * blockDim.x + threadIdx.x;         // grid covers N_GRAPHS*HID
    g_pool[i] = 0.0f;
    if (i < N_NODES)  { g_degi[i] = 0; g_cur[i] = 0; }
    if (i < N_GRAPHS) g_cnt[i]  = 0.0f;
}

__global__ void k_bnprep(const float* __restrict__ b1, const float* __restrict__ ga1,
                         const float* __restrict__ be1, const float* __restrict__ rm1,
                         const float* __restrict__ rv1,
                         const float* __restrict__ b2, const float* __restrict__ ga2,
                         const float* __restrict__ be2, const float* __restrict__ rm2,
                         const float* __restrict__ rv2,
                         const float* __restrict__ b3, const float* __restrict__ ga3,
                         const float* __restrict__ be3, const float* __restrict__ rm3,
                         const float* __restrict__ rv3) {
    int j = threadIdx.x;
    if (j >= HID) return;
    const float* B[3]  = {b1, b2, b3};
    const float* G[3]  = {ga1, ga2, ga3};
    const float* BE[3] = {be1, be2, be3};
    const float* RM[3] = {rm1, rm2, rm3};
    const float* RV[3] = {rv1, rv2, rv3};
    for (int l = 0; l < 3; l++) {
        float s = G[l][j] * rsqrtf(RV[l][j] + BN_EPS);
        g_s[l * HID + j] = s;
        g_t[l * HID + j] = (B[l][j] - RM[l][j]) * s + BE[l][j];
    }
}

__global__ void k_deg(const int* __restrict__ ei) {
    int e = blockIdx.x * blockDim.x + threadIdx.x;
    if (e >= N_EDGES) return;
    atomicAdd(&g_degi[ei[N_EDGES + e]], 1);
}

// ---- 3-kernel exclusive scan of g_degi -> g_off ----
__global__ void k_scan1() {
    __shared__ int sd[256];
    const int b = blockIdx.x, t = threadIdx.x;
    const int base = b * 1024 + t * 4;
    int v[4];
#pragma unroll
    for (int j = 0; j < 4; j++) v[j] = (base + j < N_NODES) ? g_degi[base + j] : 0;
    const int s = v[0] + v[1] + v[2] + v[3];
    sd[t] = s;
    __syncthreads();
    for (int off = 1; off < 256; off <<= 1) {
        int x = (t >= off) ? sd[t - off] : 0;
        __syncthreads();
        sd[t] += x;
        __syncthreads();
    }
    int run = sd[t] - s;                   // exclusive within block
#pragma unroll
    for (int j = 0; j < 4; j++) {
        if (base + j < N_NODES) g_off[base + j] = run;
        run += v[j];
    }
    if (t == 255) g_bsum[b] = sd[255];
}
__global__ void k_scan2() {
    __shared__ int sd[1024];
    const int t = threadIdx.x;
    const int v = (t < NSCAN_B) ? g_bsum[t] : 0;
    sd[t] = v;
    __syncthreads();
    for (int off = 1; off < 1024; off <<= 1) {
        int x = (t >= off) ? sd[t - off] : 0;
        __syncthreads();
        sd[t] += x;
        __syncthreads();
    }
    if (t < NSCAN_B) g_bsum[t] = sd[t] - v;   // exclusive
}
__global__ void k_scan3() {
    const int b = blockIdx.x, t = threadIdx.x;
    const int add = g_bsum[b];
    const int base = b * 1024 + t * 4;
#pragma unroll
    for (int j = 0; j < 4; j++)
        if (base + j < N_NODES) g_off[base + j] += add;
}

// bin edges by dst
__global__ void k_bin(const int* __restrict__ ei) {
    int e = blockIdx.x * blockDim.x + threadIdx.x;
    if (e >= N_EDGES) return;
    const int d = ei[N_EDGES + e];
    const int pos = g_off[d] + atomicAdd(&g_cur[d], 1);
    g_csr[pos] = ei[e];
}

__global__ void k_node_prep(const float* __restrict__ x, const int* __restrict__ batch) {
    int i = blockIdx.x * blockDim.x + threadIdx.x;
    if (i >= N_NODES) return;
    float di = rsqrtf((float)g_degi[i] + 1.0f);   // + self-loop
    g_dinv[i] = di;
    const float* xr = x + (long long)i * 7;
    float xv[8];
#pragma unroll
    for (int j = 0; j < 7; j++) xv[j] = xr[j];
    xv[7] = 0.0f;
    float4* xp = (float4*)(g_xpad + i * 8);
    xp[0] = make_float4(xv[0], xv[1], xv[2], xv[3]);
    xp[1] = make_float4(xv[4], xv[5], xv[6], xv[7]);
    atomicAdd(&g_cnt[batch[i]], 1.0f);
}

// layer-1 CSR pull on 8-wide x: agg0[d] = dinv_d^2*x[d] + sum norm*x[s]; 8 lanes per node
__global__ void k_pull8() {
    long long t = (long long)blockIdx.x * blockDim.x + threadIdx.x;
    const int node = (int)(t >> 3);
    if (node >= N_NODES) return;
    const int sl = (int)(t & 7);
    const float dd = g_dinv[node];
    float acc = dd * dd * g_xpad[node * 8 + sl];
    const int start = g_off[node];
    const int deg   = g_degi[node];
    int i = 0;
    for (; i + 1 < deg; i += 2) {
        const int s0 = g_csr[start + i];
        const int s1 = g_csr[start + i + 1];
        acc += dd * g_dinv[s0] * g_xpad[s0 * 8 + sl]
             + dd * g_dinv[s1] * g_xpad[s1 * 8 + sl];
    }
    if (i < deg) {
        const int s0 = g_csr[start + i];
        acc += dd * g_dinv[s0] * g_xpad[s0 * 8 + sl];
    }
    g_agg0[node * 8 + sl] = acc;
}

// h1 = relu( (agg0 @ W1) * s1 + t1 )  -> fp16
__global__ void k_gemm1(const float* __restrict__ W1) {
    __shared__ float Wsm[7 * 128];
    __shared__ float rsm[32 * 8];
    int j = threadIdx.x;
#pragma unroll
    for (int k = 0; k < 7; k++) Wsm[k * 128 + j] = W1[k * 128 + j];
    float sj = g_s[j], tj = g_t[j];
    int base = blockIdx.x * 32;
    rsm[j]       = g_agg0[base * 8 + j];
    rsm[j + 128] = g_agg0[base * 8 + j + 128];
    __syncthreads();
#pragma unroll 4
    for (int n = 0; n < 32; n++) {
        float acc = 0.0f;
#pragma unroll
        for (int k = 0; k < 7; k++) acc += rsm[n * 8 + k] * Wsm[k * 128 + j];
        g_h1[(long long)(base + n) * HID + j] = __float2half_rn(fmaxf(acc * sj + tj, 0.0f));
    }
}

// ---------- HMMA GEMM: out = In(fp16, pre-activated) @ W  (fp32 accum; fp16 out) ----------
// cp.async stages fp16 rows DIRECTLY into the LDSM-padded tile (no conversion stage).
// Double-buffered. Pad rows carry garbage; never consumed downstream.
__global__ void __launch_bounds__(256, 1)
k_gemm_mma(const __half* __restrict__ In, const float* __restrict__ Wg,
           __half* __restrict__ out1) {
    extern __shared__ char smem[];
    const uint32_t sb = smem_u32(smem);
    const int tid  = threadIdx.x;
    const int wid  = tid >> 5, lane = tid & 31;
    const int mw   = wid >> 1;
    const int nw   = wid & 1;

    // ---- W transpose -> fp16 into padded SMEM (once per CTA) ----
    {
        const int n  = tid >> 1;
        const int kh = (tid & 1) * 64;
#pragma unroll
        for (int j = 0; j < 8; j++) {
            uint32_t hi[4];
#pragma unroll
            for (int q = 0; q < 4; q++)
                hi[q] = pack16(Wg[(kh + j * 8 + q * 2) * 128 + n],
                               Wg[(kh + j * 8 + q * 2 + 1) * 128 + n]);
            *(uint4*)(smem + SM_W + (n * ROWB + kh + j * 8) * 2) =
                make_uint4(hi[0], hi[1], hi[2], hi[3]);
        }
    }

    // A staging: thread -> row rr, 8 chunks of 16B (8 halves each)
    const int rr = tid >> 1;
    const int c0 = (tid & 1) * 8;           // chunk base (of 16 chunks per 256B row)
    const uint32_t dst_off = (uint32_t)(rr * ROWB * 2);

    // prologue: stage tile(blockIdx.x) into A0
    {
        const __half* src = In + ((long long)blockIdx.x * 128 + rr) * HID + c0 * 8;
#pragma unroll
        for (int i = 0; i < 8; i++)
            cp16(sb + SM_A0 + dst_off + (c0 + i) * 16, src + i * 8);
        CP_COMMIT();
    }
    CP_WAIT0();
    __syncthreads();

    const int a_row  = (lane & 15);
    const int a_koff = (lane >> 4) * 8;
    const int b_noff = (lane & 7) + ((lane >> 4) & 1) * 8;
    const int b_koff = ((lane >> 3) & 1) * 8;

    int cur = 0;
    for (int tile = blockIdx.x; tile < NTILES; tile += gridDim.x) {
        // ---- prefetch next tile into other buffer (overlaps MMA) ----
        const int nxt = tile + gridDim.x;
        const uint32_t abuf = sb + SM_A0 + (uint32_t)cur * TILE_B;
        const uint32_t obuf = sb + SM_A0 + (uint32_t)(cur ^ 1) * TILE_B;
        if (nxt < NTILES) {
            const __half* src = In + ((long long)nxt * 128 + rr) * HID + c0 * 8;
#pragma unroll
            for (int i = 0; i < 8; i++)
                cp16(obuf + dst_off + (c0 + i) * 16, src + i * 8);
        }
        CP_COMMIT();

        // ---- mainloop ----
        float acc[2][8][4];
#pragma unroll
        for (int mf = 0; mf < 2; mf++)
#pragma unroll
            for (int nf = 0; nf < 8; nf++)
#pragma unroll
                for (int q = 0; q < 4; q++) acc[mf][nf][q] = 0.0f;

#pragma unroll
        for (int k = 0; k < 8; k++) {
            uint32_t Bh[4][4];
#pragma unroll
            for (int nf2 = 0; nf2 < 4; nf2++) {
                const int n = nw * 64 + nf2 * 16 + b_noff;
                ldsm4(Bh[nf2], sb + SM_W + (uint32_t)((n * ROWB + k * 16 + b_koff) * 2));
            }
            uint32_t Ah[2][4];
#pragma unroll
            for (int mf = 0; mf < 2; mf++) {
                const int r2 = mw * 32 + mf * 16 + a_row;
                ldsm4(Ah[mf], abuf + (uint32_t)((r2 * ROWB + k * 16 + a_koff) * 2));
            }
#pragma unroll
            for (int mf = 0; mf < 2; mf++)
#pragma unroll
                for (int nf2 = 0; nf2 < 4; nf2++) {
                    mma_f16(acc[mf][2 * nf2],     Ah[mf], Bh[nf2][0], Bh[nf2][1]);
                    mma_f16(acc[mf][2 * nf2 + 1], Ah[mf], Bh[nf2][2], Bh[nf2][3]);
                }
        }

        // ---- epilogue: fp32 acc -> fp16 gmem ----
        const long long base = (long long)tile * 128;
#pragma unroll
        for (int mf = 0; mf < 2; mf++) {
            const long long r0 = base + mw * 32 + mf * 16 + (lane >> 2);
            const long long r1 = r0 + 8;
            __half* o1a = out1 + r0 * HID;
            __half* o1b = out1 + r1 * HID;
            const int cb = nw * 64 + (lane & 3) * 2;
#pragma unroll
            for (int nf = 0; nf < 8; nf++) {
                const int c = cb + nf * 8;
                *(__half2*)(o1a + c) = __floats2half2_rn(acc[mf][nf][0], acc[mf][nf][1]);
                *(__half2*)(o1b + c) = __floats2half2_rn(acc[mf][nf][2], acc[mf][nf][3]);
            }
        }

        CP_WAIT0();               // next tile staged
        __syncthreads();          // all ldsm of abuf done before reuse next iter
        cur ^= 1;
    }
}

// ---------- CSR pull-aggregation over fp16 hw ----------
// MODE 0: out[d] = act2( dinv^2*hw[d] + sum norm*hw[s] )  -> fp16 (layer-2, pre-activates for GEMM3)
// MODE 1: pool[batch[d]] += relu(bn3( dinv^2*hw[d] + sum norm*hw[s] ))  (layer-3, fused pool)
__device__ __forceinline__ float4 ld_hw4(const __half* hw, long long row, int lane) {
    uint2 u = *(const uint2*)(hw + row * HID + lane * 4);
    __half2 a = *(__half2*)&u.x;
    __half2 b = *(__half2*)&u.y;
    float2 fa = __half22float2(a);
    float2 fb = __half22float2(b);
    return make_float4(fa.x, fa.y, fb.x, fb.y);
}

template <int MODE>
__global__ void k_agg(const __half* __restrict__ hw, __half* __restrict__ outh,
                      const int* __restrict__ batch) {
    long long t = (long long)blockIdx.x * blockDim.x + threadIdx.x;
    const int node = (int)(t >> 5);
    if (node >= N_NODES) return;
    const int lane = threadIdx.x & 31;

    const float dd  = g_dinv[node];
    const float di2 = dd * dd;
    float4 acc = ld_hw4(hw, node, lane);
    acc.x *= di2; acc.y *= di2; acc.z *= di2; acc.w *= di2;

    const int start = g_off[node];
    const int deg   = g_degi[node];
    int i = 0;
    for (; i + 3 < deg; i += 4) {
        const int s0 = g_csr[start + i];
        const int s1 = g_csr[start + i + 1];
        const int s2 = g_csr[start + i + 2];
        const int s3 = g_csr[start + i + 3];
        const float n0 = dd * g_dinv[s0];
        const float n1 = dd * g_dinv[s1];
        const float n2 = dd * g_dinv[s2];
        const float n3 = dd * g_dinv[s3];
        float4 v0 = ld_hw4(hw, s0, lane);
        float4 v1 = ld_hw4(hw, s1, lane);
        float4 v2 = ld_hw4(hw, s2, lane);
        float4 v3 = ld_hw4(hw, s3, lane);
        acc.x += n0 * v0.x + n1 * v1.x + n2 * v2.x + n3 * v3.x;
        acc.y += n0 * v0.y + n1 * v1.y + n2 * v2.y + n3 * v3.y;
        acc.z += n0 * v0.z + n1 * v1.z + n2 * v2.z + n3 * v3.z;
        acc.w += n0 * v0.w + n1 * v1.w + n2 * v2.w + n3 * v3.w;
    }
    for (; i < deg; i++) {
        const int s0 = g_csr[start + i];
        const float n0 = dd * g_dinv[s0];
        float4 v0 = ld_hw4(hw, s0, lane);
        acc.x += n0 * v0.x;
        acc.y += n0 * v0.y;
        acc.z += n0 * v0.z;
        acc.w += n0 * v0.w;
    }

    const int lidx = (MODE == 0 ? 1 : 2) * HID + lane * 4;   // s/t of layer 2 or 3
    float4 s4 = *(const float4*)(g_s + lidx);
    float4 t4 = *(const float4*)(g_t + lidx);
    float a = fmaxf(acc.x * s4.x + t4.x, 0.0f);
    float b = fmaxf(acc.y * s4.y + t4.y, 0.0f);
    float c = fmaxf(acc.z * s4.z + t4.z, 0.0f);
    float d = fmaxf(acc.w * s4.w + t4.w, 0.0f);

    if (MODE == 0) {
        uint2 u;
        u.x = pack16(a, b);
        u.y = pack16(c, d);
        *(uint2*)(outh + (long long)node * HID + lane * 4) = u;
    } else {
        red_add_v4(g_pool + (long long)batch[node] * HID + lane * 4, a, b, c, d);
    }
}

// final MLP head: 8 graphs per block (1 warp per graph)
__global__ void k_mlp(const float* __restrict__ Wc1, const float* __restrict__ bc1,
                      const float* __restrict__ Wc2, const float* __restrict__ bc2,
                      float* __restrict__ out) {
    __shared__ float W1s[128 * 64];
    __shared__ float w2s[64];
    __shared__ float b1s[64];
    __shared__ float msm[8][128];
    int tid = threadIdx.x;
    for (int i = tid; i < 128 * 64; i += 256) W1s[i] = Wc1[i];
    if (tid < 64) { w2s[tid] = Wc2[tid]; b1s[tid] = bc1[tid]; }
    __syncthreads();
    int w = tid >> 5, lane = tid & 31;
    int g = blockIdx.x * 8 + w;
    float inv = 1.0f / fmaxf(g_cnt[g], 1.0f);
    float4 v = *(const float4*)(g_pool + (long long)g * HID + lane * 4);
    *(float4*)(&msm[w][lane * 4]) = make_float4(v.x * inv, v.y * inv, v.z * inv, v.w * inv);
    __syncwarp();
    float h0 = b1s[lane], h1 = b1s[lane + 32];
#pragma unroll 8
    for (int i = 0; i < 128; i++) {
        float m = msm[w][i];
        h0 += m * W1s[i * 64 + lane];
        h1 += m * W1s[i * 64 + lane + 32];
    }
    h0 = fmaxf(h0, 0.0f);
    h1 = fmaxf(h1, 0.0f);
    float p = h0 * w2s[lane] + h1 * w2s[lane + 32];
#pragma unroll
    for (int off = 16; off > 0; off >>= 1) p += __shfl_down_sync(0xffffffffu, p, off);
    if (lane == 0) out[g] = p + bc2[0];
}

// ---------------- launch ----------------
extern "C" void kernel_launch(void* const* d_in, const int* in_sizes, int n_in,
                              void* d_out, int out_size) {
    const float* x     = (const float*)d_in[0];
    const int*   ei    = (const int*)d_in[1];
    const int*   batch = (const int*)d_in[2];
    const float* W1 = (const float*)d_in[3];
    const float* b1 = (const float*)d_in[4];
    const float* ga1 = (const float*)d_in[5];
    const float* be1 = (const float*)d_in[6];
    const float* rm1 = (const float*)d_in[7];
    const float* rv1 = (const float*)d_in[8];
    const float* W2 = (const float*)d_in[9];
    const float* b2 = (const float*)d_in[10];
    const float* ga2 = (const float*)d_in[11];
    const float* be2 = (const float*)d_in[12];
    const float* rm2 = (const float*)d_in[13];
    const float* rv2 = (const float*)d_in[14];
    const float* W3 = (const float*)d_in[15];
    const float* b3 = (const float*)d_in[16];
    const float* ga3 = (const float*)d_in[17];
    const float* be3 = (const float*)d_in[18];
    const float* rm3 = (const float*)d_in[19];
    const float* rv3 = (const float*)d_in[20];
    const float* Wc1 = (const float*)d_in[21];
    const float* bc1 = (const float*)d_in[22];
    const float* Wc2 = (const float*)d_in[23];
    const float* bc2 = (const float*)d_in[24];
    float* out = (float*)d_out;

    __half *p_h1 = nullptr, *p_hw = nullptr, *p_out = nullptr;
    cudaGetSymbolAddress((void**)&p_h1, g_h1);
    cudaGetSymbolAddress((void**)&p_hw, g_hw);
    cudaGetSymbolAddress((void**)&p_out, g_out);

    cudaFuncSetAttribute(k_gemm_mma, cudaFuncAttributeMaxDynamicSharedMemorySize, SM_TOT);

    k_zero<<<(N_GRAPHS * HID) / 256, 256>>>();
    k_bnprep<<<1, 128>>>(b1, ga1, be1, rm1, rv1, b2, ga2, be2, rm2, rv2,
                         b3, ga3, be3, rm3, rv3);
    k_deg<<<(N_EDGES + 255) / 256, 256>>>(ei);
    // CSR build
    k_scan1<<<NSCAN_B, 256>>>();
    k_scan2<<<1, 1024>>>();
    k_scan3<<<NSCAN_B, 256>>>();
    k_bin<<<(N_EDGES + 255) / 256, 256>>>(ei);

    k_node_prep<<<(N_NODES + 255) / 256, 256>>>(x, batch);
    k_pull8<<<(int)(((long long)N_NODES * 8 + 255) / 256), 256>>>();
    k_gemm1<<<N_NODES / 32, 128>>>(W1);

    const int agg_grid = (int)(((long long)N_NODES * 32 + 255) / 256);
    // layer 2: hw = h1 @ W2 (fp16) ; g_out = act2(A_norm * hw) (pull, fp16)
    k_gemm_mma<<<148, 256, SM_TOT>>>(p_h1, W2, p_hw);
    k_agg<0><<<agg_grid, 256>>>(p_hw, p_out, batch);
    // layer 3: hw = g_out @ W3 (fp16) ; pool += relu(bn3(A_norm * hw)) (pull, fused)
    k_gemm_mma<<<148, 256, SM_TOT>>>(p_out, W3, p_hw);
    k_agg<1><<<agg_grid, 256>>>(p_hw, nullptr, batch);

    k_mlp<<<N_GRAPHS / 8, 256>>>(Wc1, bc1, Wc2, bc2, out);
}

// round 17
// speedup vs baseline: 3.0885x; 1.0195x over previous
#include <cuda_runtime.h>
#include <cuda_fp16.h>
#include <cstdint>

#define N_NODES  1000000
#define N_EDGES  4000000
#define N_GRAPHS 32768
#define HID      128
#define BN_EPS   1e-5f

#define NTILES   7813                       // ceil(1e6/128)
#define N_PAD    (NTILES * 128)             // 1000064
#define NSCAN_B  977                        // ceil(1e6/1024)

// ---------------- scratch (device globals: no allocations allowed) ----------------
__device__ float  g_dinv[N_NODES];          // rsqrt(deg+1)
__device__ int    g_degi[N_NODES];          // int in-degree (by dst, no self loop)
__device__ int    g_off [N_NODES];          // CSR offsets (exclusive scan of degi)
__device__ int    g_cur [N_NODES];          // binning cursors
__device__ int    g_csr [N_EDGES];          // src ids grouped by dst
__device__ int    g_bsum[1024];             // scan block sums
__device__ float  g_xpad[N_NODES * 8];      // x padded to 8 cols
__device__ float  g_agg0[N_NODES * 8];      // A @ x   (7 used cols)
__device__ __half g_h1 [N_PAD * HID];       // h1 (activated), fp16
__device__ __half g_hw [N_PAD * HID];       // hW scratch, fp16 (gather source)
__device__ __half g_out[N_PAD * HID];       // act2(aggregated layer-2), fp16
__device__ float  g_pool[N_GRAPHS * HID];   // pooled sums
__device__ float  g_cnt [N_GRAPHS];         // nodes per graph
__device__ float  g_s[3 * HID];             // folded BN scale  per layer
__device__ float  g_t[3 * HID];             // folded BN shift (includes bias) per layer

// ---------------- helpers ----------------
__device__ __forceinline__ void red_add_v4(float* addr, float x, float y, float z, float w) {
    asm volatile("red.global.add.v4.f32 [%0], {%1,%2,%3,%4};"
                 :: "l"(addr), "f"(x), "f"(y), "f"(z), "f"(w) : "memory");
}
__device__ __forceinline__ uint32_t smem_u32(const void* p) {
    uint32_t a;
    asm("{ .reg .u64 t; cvta.to.shared.u64 t, %1; cvt.u32.u64 %0, t; }" : "=r"(a) : "l"(p));
    return a;
}
// fp32 pair -> fp16x2 (elem a in low half)
__device__ __forceinline__ uint32_t pack16(float a, float b) {
    return ((uint32_t)__half_as_ushort(__float2half_rn(b)) << 16) |
           __half_as_ushort(__float2half_rn(a));
}
__device__ __forceinline__ void ldsm4(uint32_t* r, uint32_t addr) {
    asm volatile("ldmatrix.sync.aligned.m8n8.x4.shared.b16 {%0,%1,%2,%3}, [%4];"
                 : "=r"(r[0]), "=r"(r[1]), "=r"(r[2]), "=r"(r[3]) : "r"(addr));
}
__device__ __forceinline__ void mma_f16(float* d, const uint32_t* a, uint32_t b0, uint32_t b1) {
    asm volatile(
        "mma.sync.aligned.m16n8k16.row.col.f32.f16.f16.f32 "
        "{%0,%1,%2,%3}, {%4,%5,%6,%7}, {%8,%9}, {%0,%1,%2,%3};"
        : "+f"(d[0]), "+f"(d[1]), "+f"(d[2]), "+f"(d[3])
        : "r"(a[0]), "r"(a[1]), "r"(a[2]), "r"(a[3]), "r"(b0), "r"(b1));
}
__device__ __forceinline__ void cp16(uint32_t smem_dst, const void* gmem_src) {
    asm volatile("cp.async.cg.shared.global [%0], [%1], 16;"
                 :: "r"(smem_dst), "l"(gmem_src) : "memory");
}
#define CP_COMMIT() asm volatile("cp.async.commit_group;" ::: "memory")
#define CP_WAIT0()  asm volatile("cp.async.wait_group 0;" ::: "memory")

// padded fp16 tile layout: 128 rows x 136 halves (272 B/row; rows shift 4 banks -> LDSM conflict-free)
#define ROWB   136
#define TILE_B (128 * ROWB * 2)             // 34816 bytes
#define SM_W   0
#define SM_A0  (TILE_B)
#define SM_A1  (2 * TILE_B)
#define SM_TOT (3 * TILE_B)                 // 104448 bytes (2 CTAs/SM: 208896 <= 228KB)

// ---------------- init / prep ----------------
__global__ void k_zero() {
    int i = blockIdx.x * blockDim.x + threadIdx.x;         // grid covers N_GRAPHS*HID
    g_pool[i] = 0.0f;
    if (i < N_NODES)  { g_degi[i] = 0; g_cur[i] = 0; }
    if (i < N_GRAPHS) g_cnt[i]  = 0.0f;
}

__global__ void k_bnprep(const float* __restrict__ b1, const float* __restrict__ ga1,
                         const float* __restrict__ be1, const float* __restrict__ rm1,
                         const float* __restrict__ rv1,
                         const float* __restrict__ b2, const float* __restrict__ ga2,
                         const float* __restrict__ be2, const float* __restrict__ rm2,
                         const float* __restrict__ rv2,
                         const float* __restrict__ b3, const float* __restrict__ ga3,
                         const float* __restrict__ be3, const float* __restrict__ rm3,
                         const float* __restrict__ rv3) {
    int j = threadIdx.x;
    if (j >= HID) return;
    const float* B[3]  = {b1, b2, b3};
    const float* G[3]  = {ga1, ga2, ga3};
    const float* BE[3] = {be1, be2, be3};
    const float* RM[3] = {rm1, rm2, rm3};
    const float* RV[3] = {rv1, rv2, rv3};
    for (int l = 0; l < 3; l++) {
        float s = G[l][j] * rsqrtf(RV[l][j] + BN_EPS);
        g_s[l * HID + j] = s;
        g_t[l * HID + j] = (B[l][j] - RM[l][j]) * s + BE[l][j];
    }
}

__global__ void k_deg(const int* __restrict__ ei) {
    int e = blockIdx.x * blockDim.x + threadIdx.x;
    if (e >= N_EDGES) return;
    atomicAdd(&g_degi[ei[N_EDGES + e]], 1);
}

// ---- 3-kernel exclusive scan of g_degi -> g_off ----
__global__ void k_scan1() {
    __shared__ int sd[256];
    const int b = blockIdx.x, t = threadIdx.x;
    const int base = b * 1024 + t * 4;
    int v[4];
#pragma unroll
    for (int j = 0; j < 4; j++) v[j] = (base + j < N_NODES) ? g_degi[base + j] : 0;
    const int s = v[0] + v[1] + v[2] + v[3];
    sd[t] = s;
    __syncthreads();
    for (int off = 1; off < 256; off <<= 1) {
        int x = (t >= off) ? sd[t - off] : 0;
        __syncthreads();
        sd[t] += x;
        __syncthreads();
    }
    int run = sd[t] - s;                   // exclusive within block
#pragma unroll
    for (int j = 0; j < 4; j++) {
        if (base + j < N_NODES) g_off[base + j] = run;
        run += v[j];
    }
    if (t == 255) g_bsum[b] = sd[255];
}
__global__ void k_scan2() {
    __shared__ int sd[1024];
    const int t = threadIdx.x;
    const int v = (t < NSCAN_B) ? g_bsum[t] : 0;
    sd[t] = v;
    __syncthreads();
    for (int off = 1; off < 1024; off <<= 1) {
        int x = (t >= off) ? sd[t - off] : 0;
        __syncthreads();
        sd[t] += x;
        __syncthreads();
    }
    if (t < NSCAN_B) g_bsum[t] = sd[t] - v;   // exclusive
}
__global__ void k_scan3() {
    const int b = blockIdx.x, t = threadIdx.x;
    const int add = g_bsum[b];
    const int base = b * 1024 + t * 4;
#pragma unroll
    for (int j = 0; j < 4; j++)
        if (base + j < N_NODES) g_off[base + j] += add;
}

// bin edges by dst
__global__ void k_bin(const int* __restrict__ ei) {
    int e = blockIdx.x * blockDim.x + threadIdx.x;
    if (e >= N_EDGES) return;
    const int d = ei[N_EDGES + e];
    const int pos = g_off[d] + atomicAdd(&g_cur[d], 1);
    g_csr[pos] = ei[e];
}

__global__ void k_node_prep(const float* __restrict__ x, const int* __restrict__ batch) {
    int i = blockIdx.x * blockDim.x + threadIdx.x;
    if (i >= N_NODES) return;
    float di = rsqrtf((float)g_degi[i] + 1.0f);   // + self-loop
    g_dinv[i] = di;
    const float* xr = x + (long long)i * 7;
    float xv[8];
#pragma unroll
    for (int j = 0; j < 7; j++) xv[j] = xr[j];
    xv[7] = 0.0f;
    float4* xp = (float4*)(g_xpad + i * 8);
    xp[0] = make_float4(xv[0], xv[1], xv[2], xv[3]);
    xp[1] = make_float4(xv[4], xv[5], xv[6], xv[7]);
    atomicAdd(&g_cnt[batch[i]], 1.0f);
}

// layer-1 CSR pull on 8-wide x: agg0[d] = dinv_d^2*x[d] + sum norm*x[s]; 8 lanes per node
__global__ void k_pull8() {
    long long t = (long long)blockIdx.x * blockDim.x + threadIdx.x;
    const int node = (int)(t >> 3);
    if (node >= N_NODES) return;
    const int sl = (int)(t & 7);
    const float dd = g_dinv[node];
    float acc = dd * dd * g_xpad[node * 8 + sl];
    const int start = g_off[node];
    const int deg   = g_degi[node];
    int i = 0;
    for (; i + 1 < deg; i += 2) {
        const int s0 = g_csr[start + i];
        const int s1 = g_csr[start + i + 1];
        acc += dd * g_dinv[s0] * g_xpad[s0 * 8 + sl]
             + dd * g_dinv[s1] * g_xpad[s1 * 8 + sl];
    }
    if (i < deg) {
        const int s0 = g_csr[start + i];
        acc += dd * g_dinv[s0] * g_xpad[s0 * 8 + sl];
    }
    g_agg0[node * 8 + sl] = acc;
}

// h1 = relu( (agg0 @ W1) * s1 + t1 )  -> fp16
__global__ void k_gemm1(const float* __restrict__ W1) {
    __shared__ float Wsm[7 * 128];
    __shared__ float rsm[32 * 8];
    int j = threadIdx.x;
#pragma unroll
    for (int k = 0; k < 7; k++) Wsm[k * 128 + j] = W1[k * 128 + j];
    float sj = g_s[j], tj = g_t[j];
    int base = blockIdx.x * 32;
    rsm[j]       = g_agg0[base * 8 + j];
    rsm[j + 128] = g_agg0[base * 8 + j + 128];
    __syncthreads();
#pragma unroll 4
    for (int n = 0; n < 32; n++) {
        float acc = 0.0f;
#pragma unroll
        for (int k = 0; k < 7; k++) acc += rsm[n * 8 + k] * Wsm[k * 128 + j];
        g_h1[(long long)(base + n) * HID + j] = __float2half_rn(fmaxf(acc * sj + tj, 0.0f));
    }
}

// ---------- HMMA GEMM: out = In(fp16, pre-activated) @ W  (fp32 accum; fp16 out) ----------
// cp.async stages fp16 rows DIRECTLY into the LDSM-padded tile; double-buffered.
// 2 CTAs/SM: co-resident CTA's MMA overlaps this CTA's epilogue/staging waits.
__global__ void __launch_bounds__(256, 2)
k_gemm_mma(const __half* __restrict__ In, const float* __restrict__ Wg,
           __half* __restrict__ out1) {
    extern __shared__ char smem[];
    const uint32_t sb = smem_u32(smem);
    const int tid  = threadIdx.x;
    const int wid  = tid >> 5, lane = tid & 31;
    const int mw   = wid >> 1;
    const int nw   = wid & 1;

    // ---- W transpose -> fp16 into padded SMEM (once per CTA) ----
    {
        const int n  = tid >> 1;
        const int kh = (tid & 1) * 64;
#pragma unroll
        for (int j = 0; j < 8; j++) {
            uint32_t hi[4];
#pragma unroll
            for (int q = 0; q < 4; q++)
                hi[q] = pack16(Wg[(kh + j * 8 + q * 2) * 128 + n],
                               Wg[(kh + j * 8 + q * 2 + 1) * 128 + n]);
            *(uint4*)(smem + SM_W + (n * ROWB + kh + j * 8) * 2) =
                make_uint4(hi[0], hi[1], hi[2], hi[3]);
        }
    }

    // A staging: thread -> row rr, 8 chunks of 16B (8 halves each)
    const int rr = tid >> 1;
    const int c0 = (tid & 1) * 8;           // chunk base (of 16 chunks per 256B row)
    const uint32_t dst_off = (uint32_t)(rr * ROWB * 2);

    // prologue: stage tile(blockIdx.x) into A0
    {
        const __half* src = In + ((long long)blockIdx.x * 128 + rr) * HID + c0 * 8;
#pragma unroll
        for (int i = 0; i < 8; i++)
            cp16(sb + SM_A0 + dst_off + (c0 + i) * 16, src + i * 8);
        CP_COMMIT();
    }
    CP_WAIT0();
    __syncthreads();

    const int a_row  = (lane & 15);
    const int a_koff = (lane >> 4) * 8;
    const int b_noff = (lane & 7) + ((lane >> 4) & 1) * 8;
    const int b_koff = ((lane >> 3) & 1) * 8;

    int cur = 0;
    for (int tile = blockIdx.x; tile < NTILES; tile += gridDim.x) {
        // ---- prefetch next tile into other buffer (overlaps MMA) ----
        const int nxt = tile + gridDim.x;
        const uint32_t abuf = sb + SM_A0 + (uint32_t)cur * TILE_B;
        const uint32_t obuf = sb + SM_A0 + (uint32_t)(cur ^ 1) * TILE_B;
        if (nxt < NTILES) {
            const __half* src = In + ((long long)nxt * 128 + rr) * HID + c0 * 8;
#pragma unroll
            for (int i = 0; i < 8; i++)
                cp16(obuf + dst_off + (c0 + i) * 16, src + i * 8);
        }
        CP_COMMIT();

        // ---- mainloop ----
        float acc[2][8][4];
#pragma unroll
        for (int mf = 0; mf < 2; mf++)
#pragma unroll
            for (int nf = 0; nf < 8; nf++)
#pragma unroll
                for (int q = 0; q < 4; q++) acc[mf][nf][q] = 0.0f;

#pragma unroll
        for (int k = 0; k < 8; k++) {
            uint32_t Bh[4][4];
#pragma unroll
            for (int nf2 = 0; nf2 < 4; nf2++) {
                const int n = nw * 64 + nf2 * 16 + b_noff;
                ldsm4(Bh[nf2], sb + SM_W + (uint32_t)((n * ROWB + k * 16 + b_koff) * 2));
            }
            uint32_t Ah[2][4];
#pragma unroll
            for (int mf = 0; mf < 2; mf++) {
                const int r2 = mw * 32 + mf * 16 + a_row;
                ldsm4(Ah[mf], abuf + (uint32_t)((r2 * ROWB + k * 16 + a_koff) * 2));
            }
#pragma unroll
            for (int mf = 0; mf < 2; mf++)
#pragma unroll
                for (int nf2 = 0; nf2 < 4; nf2++) {
                    mma_f16(acc[mf][2 * nf2],     Ah[mf], Bh[nf2][0], Bh[nf2][1]);
                    mma_f16(acc[mf][2 * nf2 + 1], Ah[mf], Bh[nf2][2], Bh[nf2][3]);
                }
        }

        // ---- epilogue: fp32 acc -> fp16 gmem ----
        const long long base = (long long)tile * 128;
#pragma unroll
        for (int mf = 0; mf < 2; mf++) {
            const long long r0 = base + mw * 32 + mf * 16 + (lane >> 2);
            const long long r1 = r0 + 8;
            __half* o1a = out1 + r0 * HID;
            __half* o1b = out1 + r1 * HID;
            const int cb = nw * 64 + (lane & 3) * 2;
#pragma unroll
            for (int nf = 0; nf < 8; nf++) {
                const int c = cb + nf * 8;
                *(__half2*)(o1a + c) = __floats2half2_rn(acc[mf][nf][0], acc[mf][nf][1]);
                *(__half2*)(o1b + c) = __floats2half2_rn(acc[mf][nf][2], acc[mf][nf][3]);
            }
        }

        CP_WAIT0();               // next tile staged
        __syncthreads();          // all ldsm of abuf done before reuse next iter
        cur ^= 1;
    }
}

// ---------- CSR pull-aggregation over fp16 hw ----------
// MODE 0: out[d] = act2( dinv^2*hw[d] + sum norm*hw[s] )  -> fp16 (layer-2, pre-activates for GEMM3)
// MODE 1: pool[batch[d]] += relu(bn3( dinv^2*hw[d] + sum norm*hw[s] ))  (layer-3, fused pool)
__device__ __forceinline__ float4 ld_hw4(const __half* hw, long long row, int lane) {
    uint2 u = *(const uint2*)(hw + row * HID + lane * 4);
    __half2 a = *(__half2*)&u.x;
    __half2 b = *(__half2*)&u.y;
    float2 fa = __half22float2(a);
    float2 fb = __half22float2(b);
    return make_float4(fa.x, fa.y, fb.x, fb.y);
}

template <int MODE>
__global__ void k_agg(const __half* __restrict__ hw, __half* __restrict__ outh,
                      const int* __restrict__ batch) {
    long long t = (long long)blockIdx.x * blockDim.x + threadIdx.x;
    const int node = (int)(t >> 5);
    if (node >= N_NODES) return;
    const int lane = threadIdx.x & 31;

    const float dd  = g_dinv[node];
    const float di2 = dd * dd;
    float4 acc = ld_hw4(hw, node, lane);
    acc.x *= di2; acc.y *= di2; acc.z *= di2; acc.w *= di2;

    const int start = g_off[node];
    const int deg   = g_degi[node];
    int i = 0;
    for (; i + 3 < deg; i += 4) {
        const int s0 = g_csr[start + i];
        const int s1 = g_csr[start + i + 1];
        const int s2 = g_csr[start + i + 2];
        const int s3 = g_csr[start + i + 3];
        const float n0 = dd * g_dinv[s0];
        const float n1 = dd * g_dinv[s1];
        const float n2 = dd * g_dinv[s2];
        const float n3 = dd * g_dinv[s3];
        float4 v0 = ld_hw4(hw, s0, lane);
        float4 v1 = ld_hw4(hw, s1, lane);
        float4 v2 = ld_hw4(hw, s2, lane);
        float4 v3 = ld_hw4(hw, s3, lane);
        acc.x += n0 * v0.x + n1 * v1.x + n2 * v2.x + n3 * v3.x;
        acc.y += n0 * v0.y + n1 * v1.y + n2 * v2.y + n3 * v3.y;
        acc.z += n0 * v0.z + n1 * v1.z + n2 * v2.z + n3 * v3.z;
        acc.w += n0 * v0.w + n1 * v1.w + n2 * v2.w + n3 * v3.w;
    }
    for (; i < deg; i++) {
        const int s0 = g_csr[start + i];
        const float n0 = dd * g_dinv[s0];
        float4 v0 = ld_hw4(hw, s0, lane);
        acc.x += n0 * v0.x;
        acc.y += n0 * v0.y;
        acc.z += n0 * v0.z;
        acc.w += n0 * v0.w;
    }

    const int lidx = (MODE == 0 ? 1 : 2) * HID + lane * 4;   // s/t of layer 2 or 3
    float4 s4 = *(const float4*)(g_s + lidx);
    float4 t4 = *(const float4*)(g_t + lidx);
    float a = fmaxf(acc.x * s4.x + t4.x, 0.0f);
    float b = fmaxf(acc.y * s4.y + t4.y, 0.0f);
    float c = fmaxf(acc.z * s4.z + t4.z, 0.0f);
    float d = fmaxf(acc.w * s4.w + t4.w, 0.0f);

    if (MODE == 0) {
        uint2 u;
        u.x = pack16(a, b);
        u.y = pack16(c, d);
        *(uint2*)(outh + (long long)node * HID + lane * 4) = u;
    } else {
        red_add_v4(g_pool + (long long)batch[node] * HID + lane * 4, a, b, c, d);
    }
}

// final MLP head: 8 graphs per block (1 warp per graph)
__global__ void k_mlp(const float* __restrict__ Wc1, const float* __restrict__ bc1,
                      const float* __restrict__ Wc2, const float* __restrict__ bc2,
                      float* __restrict__ out) {
    __shared__ float W1s[128 * 64];
    __shared__ float w2s[64];
    __shared__ float b1s[64];
    __shared__ float msm[8][128];
    int tid = threadIdx.x;
    for (int i = tid; i < 128 * 64; i += 256) W1s[i] = Wc1[i];
    if (tid < 64) { w2s[tid] = Wc2[tid]; b1s[tid] = bc1[tid]; }
    __syncthreads();
    int w = tid >> 5, lane = tid & 31;
    int g = blockIdx.x * 8 + w;
    float inv = 1.0f / fmaxf(g_cnt[g], 1.0f);
    float4 v = *(const float4*)(g_pool + (long long)g * HID + lane * 4);
    *(float4*)(&msm[w][lane * 4]) = make_float4(v.x * inv, v.y * inv, v.z * inv, v.w * inv);
    __syncwarp();
    float h0 = b1s[lane], h1 = b1s[lane + 32];
#pragma unroll 8
    for (int i = 0; i < 128; i++) {
        float m = msm[w][i];
        h0 += m * W1s[i * 64 + lane];
        h1 += m * W1s[i * 64 + lane + 32];
    }
    h0 = fmaxf(h0, 0.0f);
    h1 = fmaxf(h1, 0.0f);
    float p = h0 * w2s[lane] + h1 * w2s[lane + 32];
#pragma unroll
    for (int off = 16; off > 0; off >>= 1) p += __shfl_down_sync(0xffffffffu, p, off);
    if (lane == 0) out[g] = p + bc2[0];
}

// ---------------- launch ----------------
extern "C" void kernel_launch(void* const* d_in, const int* in_sizes, int n_in,
                              void* d_out, int out_size) {
    const float* x     = (const float*)d_in[0];
    const int*   ei    = (const int*)d_in[1];
    const int*   batch = (const int*)d_in[2];
    const float* W1 = (const float*)d_in[3];
    const float* b1 = (const float*)d_in[4];
    const float* ga1 = (const float*)d_in[5];
    const float* be1 = (const float*)d_in[6];
    const float* rm1 = (const float*)d_in[7];
    const float* rv1 = (const float*)d_in[8];
    const float* W2 = (const float*)d_in[9];
    const float* b2 = (const float*)d_in[10];
    const float* ga2 = (const float*)d_in[11];
    const float* be2 = (const float*)d_in[12];
    const float* rm2 = (const float*)d_in[13];
    const float* rv2 = (const float*)d_in[14];
    const float* W3 = (const float*)d_in[15];
    const float* b3 = (const float*)d_in[16];
    const float* ga3 = (const float*)d_in[17];
    const float* be3 = (const float*)d_in[18];
    const float* rm3 = (const float*)d_in[19];
    const float* rv3 = (const float*)d_in[20];
    const float* Wc1 = (const float*)d_in[21];
    const float* bc1 = (const float*)d_in[22];
    const float* Wc2 = (const float*)d_in[23];
    const float* bc2 = (const float*)d_in[24];
    float* out = (float*)d_out;

    __half *p_h1 = nullptr, *p_hw = nullptr, *p_out = nullptr;
    cudaGetSymbolAddress((void**)&p_h1, g_h1);
    cudaGetSymbolAddress((void**)&p_hw, g_hw);
    cudaGetSymbolAddress((void**)&p_out, g_out);

    cudaFuncSetAttribute(k_gemm_mma, cudaFuncAttributeMaxDynamicSharedMemorySize, SM_TOT);

    k_zero<<<(N_GRAPHS * HID) / 256, 256>>>();
    k_bnprep<<<1, 128>>>(b1, ga1, be1, rm1, rv1, b2, ga2, be2, rm2, rv2,
                         b3, ga3, be3, rm3, rv3);
    k_deg<<<(N_EDGES + 255) / 256, 256>>>(ei);
    // CSR build
    k_scan1<<<NSCAN_B, 256>>>();
    k_scan2<<<1, 1024>>>();
    k_scan3<<<NSCAN_B, 256>>>();
    k_bin<<<(N_EDGES + 255) / 256, 256>>>(ei);

    k_node_prep<<<(N_NODES + 255) / 256, 256>>>(x, batch);
    k_pull8<<<(int)(((long long)N_NODES * 8 + 255) / 256), 256>>>();
    k_gemm1<<<N_NODES / 32, 128>>>(W1);

    const int agg_grid = (int)(((long long)N_NODES * 32 + 255) / 256);
    // layer 2: hw = h1 @ W2 (fp16) ; g_out = act2(A_norm * hw) (pull, fp16)
    k_gemm_mma<<<296, 256, SM_TOT>>>(p_h1, W2, p_hw);
    k_agg<0><<<agg_grid, 256>>>(p_hw, p_out, batch);
    // layer 3: hw = g_out @ W3 (fp16) ; pool += relu(bn3(A_norm * hw)) (pull, fused)
    k_gemm_mma<<<296, 256, SM_TOT>>>(p_out, W3, p_hw);
    k_agg<1><<<agg_grid, 256>>>(p_hw, nullptr, batch);

    k_mlp<<<N_GRAPHS / 8, 256>>>(Wc1, bc1, Wc2, bc2, out);
}